// round 1
// baseline (speedup 1.0000x reference)
#include <cuda_runtime.h>

#define BATCH 8
#define TSEQ 1024
#define DMOD 1024
#define NH 8
#define DH 128
#define SCALE 0.08838834764831845f

#define SQ 68    // padded stride for transposed Q/K score tiles and S
#define SV 132   // padded stride for V tile

// Scratch for Q, K, V projections (device globals: allocation-free).
__device__ float g_Q[BATCH * TSEQ * DMOD];
__device__ float g_K[BATCH * TSEQ * DMOD];
__device__ float g_V[BATCH * TSEQ * DMOD];

typedef unsigned long long u64;

__device__ __forceinline__ u64 ffma2(u64 a, u64 b, u64 c) {
    u64 d;
    asm("fma.rn.f32x2 %0, %1, %2, %3;" : "=l"(d) : "l"(a), "l"(b), "l"(c));
    return d;
}
__device__ __forceinline__ u64 pack2(float x, float y) {
    u64 r;
    asm("mov.b64 %0, {%1, %2};" : "=l"(r) : "f"(x), "f"(y));
    return r;
}

// ---------------------------------------------------------------------------
// C[8192,1024] = A[8192,1024] @ W[1024,1024]^T   (both K-contiguous, "NT")
// 128x128 block tile, BK=16, 256 threads, 8x8 thread tile.
// Inner product uses fma.rn.f32x2 (FFMA2) over column PAIRS; columns are
// interleaved as {2*tx + 32*p} so the LDS.64 b-fragment reads are
// bank-conflict-free across the half-warp.
// ---------------------------------------------------------------------------
__global__ __launch_bounds__(256, 2) void qkv_gemm(const float* __restrict__ A,
                                                   const float* __restrict__ W,
                                                   float* __restrict__ C) {
    __shared__ __align__(16) float As[16][132];  // transposed: As[k][m]
    __shared__ __align__(16) float Bs[16][132];  // transposed: Bs[k][n]

    const int tid = threadIdx.x;
    const int tx = tid & 15, ty = tid >> 4;
    const int bm = blockIdx.y << 7, bn = blockIdx.x << 7;
    const int lr = tid >> 2, lk = tid & 3;

    u64 acc[8][4];
#pragma unroll
    for (int i = 0; i < 8; i++)
#pragma unroll
        for (int p = 0; p < 4; p++) acc[i][p] = 0ull;

    for (int kt = 0; kt < 1024; kt += 16) {
#pragma unroll
        for (int rr = 0; rr < 2; rr++) {
            int am = lr + (rr << 6);
            float4 va = *(const float4*)&A[(size_t)(bm + am) * DMOD + kt + (lk << 2)];
            As[(lk << 2) + 0][am] = va.x;
            As[(lk << 2) + 1][am] = va.y;
            As[(lk << 2) + 2][am] = va.z;
            As[(lk << 2) + 3][am] = va.w;
            float4 vb = *(const float4*)&W[(size_t)(bn + am) * DMOD + kt + (lk << 2)];
            Bs[(lk << 2) + 0][am] = vb.x;
            Bs[(lk << 2) + 1][am] = vb.y;
            Bs[(lk << 2) + 2][am] = vb.z;
            Bs[(lk << 2) + 3][am] = vb.w;
        }
        __syncthreads();
#pragma unroll
        for (int k = 0; k < 16; k++) {
            float4 a0 = *(const float4*)&As[k][ty << 3];
            float4 a1 = *(const float4*)&As[k][(ty << 3) + 4];
            u64 bfr[4];
#pragma unroll
            for (int p = 0; p < 4; p++)
                bfr[p] = *(const u64*)&Bs[k][(tx << 1) + (p << 5)];
            float av[8] = {a0.x, a0.y, a0.z, a0.w, a1.x, a1.y, a1.z, a1.w};
#pragma unroll
            for (int i = 0; i < 8; i++) {
                u64 ad = pack2(av[i], av[i]);
#pragma unroll
                for (int p = 0; p < 4; p++)
                    acc[i][p] = ffma2(ad, bfr[p], acc[i][p]);
            }
        }
        __syncthreads();
    }
#pragma unroll
    for (int i = 0; i < 8; i++) {
        size_t row = (size_t)(bm + (ty << 3) + i);
#pragma unroll
        for (int p = 0; p < 4; p++)
            *(u64*)&C[row * DMOD + bn + (tx << 1) + (p << 5)] = acc[i][p];
    }
}

// ---------------------------------------------------------------------------
// Flash attention over (qt, h, b). 64-row query tiles, 64-row key tiles.
// Q/K stored transposed in smem ([k][row], pad 68) -> broadcast a-frag +
// conflict-free b-frag in the score GEMM. Online softmax with 4 lanes/row.
// Masked key tiles (kt < qt) skipped except for the last q-tile (row 1023
// attends everything via the uniform -10000 shift).
// ---------------------------------------------------------------------------
__global__ __launch_bounds__(256, 1) void attn_kernel(const float* __restrict__ mask,
                                                      float* __restrict__ out) {
    extern __shared__ __align__(16) float sm[];
    float* Qts  = sm;               // [128][SQ] transposed
    float* Kts  = Qts + 128 * SQ;   // [128][SQ] transposed
    float* Vs   = Kts + 128 * SQ;   // [64][SV]  natural
    float* Ss   = Vs + 64 * SV;     // [64][SQ]  scores / probs
    float* rowm = Ss + 64 * SQ;     // [64]
    float* rowl = rowm + 64;        // [64]
    float* rowa = rowl + 64;        // [64]

    const int tid = threadIdx.x;
    const int tx = tid & 15, ty = tid >> 4;
    const int qt = blockIdx.x, h = blockIdx.y, b = blockIdx.z;

    const float* Qg = g_Q + (size_t)b * TSEQ * DMOD + (size_t)h * DH;
    const float* Kg = g_K + (size_t)b * TSEQ * DMOD + (size_t)h * DH;
    const float* Vg = g_V + (size_t)b * TSEQ * DMOD + (size_t)h * DH;

    const int lr = tid >> 2, lk = tid & 3;

    // Load Q tile transposed: Qts[k][r] = Q[qt*64+r][k]
#pragma unroll
    for (int kk = 0; kk < 8; kk++) {
        int k0 = (lk << 2) + (kk << 4);
        float4 v = *(const float4*)&Qg[(size_t)(qt * 64 + lr) * DMOD + k0];
        Qts[(k0 + 0) * SQ + lr] = v.x;
        Qts[(k0 + 1) * SQ + lr] = v.y;
        Qts[(k0 + 2) * SQ + lr] = v.z;
        Qts[(k0 + 3) * SQ + lr] = v.w;
    }
    if (tid < 64) { rowm[tid] = -1e30f; rowl[tid] = 0.f; }

    float o[4][8];
#pragma unroll
    for (int i = 0; i < 4; i++)
#pragma unroll
        for (int j = 0; j < 8; j++) o[i][j] = 0.f;

    const int kt0 = (qt == 15) ? 0 : qt;
    const int c4 = tid & 31, vr0 = tid >> 5;

    for (int kt = kt0; kt < 16; kt++) {
        __syncthreads();  // previous iteration's consumers done with Kts/Vs/Ss
        // Load K tile transposed
#pragma unroll
        for (int kk = 0; kk < 8; kk++) {
            int k0 = (lk << 2) + (kk << 4);
            float4 v = *(const float4*)&Kg[(size_t)(kt * 64 + lr) * DMOD + k0];
            Kts[(k0 + 0) * SQ + lr] = v.x;
            Kts[(k0 + 1) * SQ + lr] = v.y;
            Kts[(k0 + 2) * SQ + lr] = v.z;
            Kts[(k0 + 3) * SQ + lr] = v.w;
        }
        // Load V tile natural layout
#pragma unroll
        for (int rr = 0; rr < 8; rr++) {
            int vr = vr0 + (rr << 3);
            float4 v = *(const float4*)&Vg[(size_t)(kt * 64 + vr) * DMOD + (c4 << 2)];
            *(float4*)&Vs[vr * SV + (c4 << 2)] = v;
        }
        __syncthreads();

        // Scores: S[64,64] = Q . K^T  (4x4 per thread)
        float sacc[4][4];
#pragma unroll
        for (int i = 0; i < 4; i++)
#pragma unroll
            for (int j = 0; j < 4; j++) sacc[i][j] = 0.f;

#pragma unroll 8
        for (int k = 0; k < 128; k++) {
            float4 a  = *(const float4*)&Qts[k * SQ + (ty << 2)];
            float4 bb = *(const float4*)&Kts[k * SQ + (tx << 2)];
            float aa[4] = {a.x, a.y, a.z, a.w};
            float bv[4] = {bb.x, bb.y, bb.z, bb.w};
#pragma unroll
            for (int i = 0; i < 4; i++)
#pragma unroll
                for (int j = 0; j < 4; j++) sacc[i][j] += aa[i] * bv[j];
        }

        const int qbase = qt * 64 + (ty << 2);
        const int kbase = kt * 64 + (tx << 2);
#pragma unroll
        for (int i = 0; i < 4; i++) {
            float4 w;
            w.x = sacc[i][0] * SCALE + ((kbase + 0 <= qbase + i) ? -10000.f : 0.f);
            w.y = sacc[i][1] * SCALE + ((kbase + 1 <= qbase + i) ? -10000.f : 0.f);
            w.z = sacc[i][2] * SCALE + ((kbase + 2 <= qbase + i) ? -10000.f : 0.f);
            w.w = sacc[i][3] * SCALE + ((kbase + 3 <= qbase + i) ? -10000.f : 0.f);
            *(float4*)&Ss[((ty << 2) + i) * SQ + (tx << 2)] = w;
        }
        __syncthreads();

        // Online softmax: 4 lanes per row, 16 columns each
        {
            const int row = tid >> 2, q = tid & 3;
            float* srow = &Ss[row * SQ + (q << 4)];
            float4 v0 = *(float4*)&srow[0];
            float4 v1 = *(float4*)&srow[4];
            float4 v2 = *(float4*)&srow[8];
            float4 v3 = *(float4*)&srow[12];
            float mloc = fmaxf(
                fmaxf(fmaxf(fmaxf(v0.x, v0.y), fmaxf(v0.z, v0.w)),
                      fmaxf(fmaxf(v1.x, v1.y), fmaxf(v1.z, v1.w))),
                fmaxf(fmaxf(fmaxf(v2.x, v2.y), fmaxf(v2.z, v2.w)),
                      fmaxf(fmaxf(v3.x, v3.y), fmaxf(v3.z, v3.w))));
            mloc = fmaxf(mloc, __shfl_xor_sync(0xffffffffu, mloc, 1));
            mloc = fmaxf(mloc, __shfl_xor_sync(0xffffffffu, mloc, 2));
            float mold  = rowm[row];
            float mnew  = fmaxf(mold, mloc);
            float alpha = __expf(mold - mnew);
            v0.x = __expf(v0.x - mnew); v0.y = __expf(v0.y - mnew);
            v0.z = __expf(v0.z - mnew); v0.w = __expf(v0.w - mnew);
            v1.x = __expf(v1.x - mnew); v1.y = __expf(v1.y - mnew);
            v1.z = __expf(v1.z - mnew); v1.w = __expf(v1.w - mnew);
            v2.x = __expf(v2.x - mnew); v2.y = __expf(v2.y - mnew);
            v2.z = __expf(v2.z - mnew); v2.w = __expf(v2.w - mnew);
            v3.x = __expf(v3.x - mnew); v3.y = __expf(v3.y - mnew);
            v3.z = __expf(v3.z - mnew); v3.w = __expf(v3.w - mnew);
            *(float4*)&srow[0]  = v0;
            *(float4*)&srow[4]  = v1;
            *(float4*)&srow[8]  = v2;
            *(float4*)&srow[12] = v3;
            float ssum = (v0.x + v0.y + v0.z + v0.w) + (v1.x + v1.y + v1.z + v1.w) +
                         (v2.x + v2.y + v2.z + v2.w) + (v3.x + v3.y + v3.z + v3.w);
            ssum += __shfl_xor_sync(0xffffffffu, ssum, 1);
            ssum += __shfl_xor_sync(0xffffffffu, ssum, 2);
            if (q == 0) {
                rowl[row] = rowl[row] * alpha + ssum;
                rowm[row] = mnew;
                rowa[row] = alpha;
            }
        }
        __syncthreads();

        // Rescale O and accumulate P @ V  (4 rows x 8 cols per thread)
        float al[4];
#pragma unroll
        for (int i = 0; i < 4; i++) al[i] = rowa[(ty << 2) + i];
#pragma unroll
        for (int i = 0; i < 4; i++)
#pragma unroll
            for (int j = 0; j < 8; j++) o[i][j] *= al[i];

#pragma unroll 4
        for (int k = 0; k < 64; k++) {
            float av[4];
            av[0] = Ss[((ty << 2) + 0) * SQ + k];
            av[1] = Ss[((ty << 2) + 1) * SQ + k];
            av[2] = Ss[((ty << 2) + 2) * SQ + k];
            av[3] = Ss[((ty << 2) + 3) * SQ + k];
            float4 b0 = *(const float4*)&Vs[k * SV + (tx << 3)];
            float4 b1 = *(const float4*)&Vs[k * SV + (tx << 3) + 4];
            float bv[8] = {b0.x, b0.y, b0.z, b0.w, b1.x, b1.y, b1.z, b1.w};
#pragma unroll
            for (int i = 0; i < 4; i++)
#pragma unroll
                for (int j = 0; j < 8; j++) o[i][j] += av[i] * bv[j];
        }
    }

    __syncthreads();
#pragma unroll
    for (int i = 0; i < 4; i++) {
        int row = (ty << 2) + i;
        float scl = (1.f / rowl[row]) * mask[(size_t)b * TSEQ + qt * 64 + row];
        float4 w0, w1;
        w0.x = o[i][0] * scl; w0.y = o[i][1] * scl;
        w0.z = o[i][2] * scl; w0.w = o[i][3] * scl;
        w1.x = o[i][4] * scl; w1.y = o[i][5] * scl;
        w1.z = o[i][6] * scl; w1.w = o[i][7] * scl;
        size_t base = ((size_t)(b * TSEQ + qt * 64 + row)) * DMOD + h * DH + (tx << 3);
        *(float4*)&out[base]     = w0;
        *(float4*)&out[base + 4] = w1;
    }
}

extern "C" void kernel_launch(void* const* d_in, const int* in_sizes, int n_in,
                              void* d_out, int out_size) {
    const float* x    = (const float*)d_in[0];
    const float* mask = (const float*)d_in[1];
    const float* Wq   = (const float*)d_in[2];
    const float* Wk   = (const float*)d_in[3];
    const float* Wv   = (const float*)d_in[4];
    float* out = (float*)d_out;

    float *q, *k, *v;
    cudaGetSymbolAddress((void**)&q, g_Q);
    cudaGetSymbolAddress((void**)&k, g_K);
    cudaGetSymbolAddress((void**)&v, g_V);

    dim3 ggrid(DMOD / 128, (BATCH * TSEQ) / 128);
    qkv_gemm<<<ggrid, 256>>>(x, Wq, q);
    qkv_gemm<<<ggrid, 256>>>(x, Wk, k);
    qkv_gemm<<<ggrid, 256>>>(x, Wv, v);

    int smem = (128 * SQ * 2 + 64 * SV + 64 * SQ + 192) * (int)sizeof(float);
    cudaFuncSetAttribute(attn_kernel, cudaFuncAttributeMaxDynamicSharedMemorySize, smem);
    dim3 agrid(TSEQ / 64, NH, BATCH);
    attn_kernel<<<agrid, 256, smem>>>(mask, out);
}

// round 3
// speedup vs baseline: 1.4000x; 1.4000x over previous
#include <cuda_runtime.h>
#include <cuda_bf16.h>
#include <cstdint>

#define BATCH 8
#define TSEQ 1024
#define DMOD 1024
#define NH 8
#define DH 128
#define SCALE 0.08838834764831845f

#define SQ 68
#define SV 132

// Scratch (device globals: allocation-free).
__device__ float g_Q[BATCH * TSEQ * DMOD];
__device__ float g_K[BATCH * TSEQ * DMOD];
__device__ float g_V[BATCH * TSEQ * DMOD];
__device__ __nv_bfloat16 g_Xh[BATCH * TSEQ * DMOD];
__device__ __nv_bfloat16 g_Xl[BATCH * TSEQ * DMOD];
__device__ __nv_bfloat16 g_Wh[DMOD * DMOD];
__device__ __nv_bfloat16 g_Wl[DMOD * DMOD];

// ===========================================================================
// Split fp32 -> (bf16 hi, bf16 lo) arrays. lo = bf16(x - float(hi)).
// ===========================================================================
__global__ __launch_bounds__(256) void split_bf16(const float4* __restrict__ src,
                                                  uint2* __restrict__ hi,
                                                  uint2* __restrict__ lo) {
    int i = blockIdx.x * 256 + threadIdx.x;
    float4 v = src[i];
    __nv_bfloat16 h0 = __float2bfloat16(v.x), h1 = __float2bfloat16(v.y);
    __nv_bfloat16 h2 = __float2bfloat16(v.z), h3 = __float2bfloat16(v.w);
    float r0 = v.x - __bfloat162float(h0);
    float r1 = v.y - __bfloat162float(h1);
    float r2 = v.z - __bfloat162float(h2);
    float r3 = v.w - __bfloat162float(h3);
    __nv_bfloat16 l0 = __float2bfloat16(r0), l1 = __float2bfloat16(r1);
    __nv_bfloat16 l2 = __float2bfloat16(r2), l3 = __float2bfloat16(r3);
    uint2 H, L;
    H.x = (uint32_t)__bfloat16_as_ushort(h0) | ((uint32_t)__bfloat16_as_ushort(h1) << 16);
    H.y = (uint32_t)__bfloat16_as_ushort(h2) | ((uint32_t)__bfloat16_as_ushort(h3) << 16);
    L.x = (uint32_t)__bfloat16_as_ushort(l0) | ((uint32_t)__bfloat16_as_ushort(l1) << 16);
    L.y = (uint32_t)__bfloat16_as_ushort(l2) | ((uint32_t)__bfloat16_as_ushort(l3) << 16);
    hi[i] = H;
    lo[i] = L;
}

// ===========================================================================
// Tensor-core GEMM: C[8192,1024] = A[8192,1024] @ W[1024,1024]^T
// mma.sync.m16n8k16 bf16, split-precision (Ah*Bh + Ah*Bl + Al*Bh).
// 128x128 block, BK=32, 8 warps (64x32 warptile), 2-stage cp.async pipeline.
// smem tiles: 128 rows x 32 bf16, padded to 40 bf16 (80B rows, conflict-free).
// ===========================================================================
#define TILE_B 10240                     // one 128x40 bf16 tile
#define STAGE_B (4 * TILE_B)             // Ah, Al, Bh, Bl
#define GEMM_SMEM (2 * STAGE_B)          // 81920 bytes

__device__ __forceinline__ uint32_t smem_u32(const void* p) {
    uint32_t a;
    asm("{ .reg .u64 t; cvta.to.shared.u64 t, %1; cvt.u32.u64 %0, t; }"
        : "=r"(a) : "l"(p));
    return a;
}
__device__ __forceinline__ void cp16(uint32_t dst, const void* src) {
    asm volatile("cp.async.cg.shared.global [%0], [%1], 16;"
                 :: "r"(dst), "l"(src) : "memory");
}
#define CP_COMMIT() asm volatile("cp.async.commit_group;" ::: "memory")
#define CP_WAIT(n)  asm volatile("cp.async.wait_group %0;" :: "n"(n) : "memory")

#define MMA_BF16(c, a, b) \
    asm volatile("mma.sync.aligned.m16n8k16.row.col.f32.bf16.bf16.f32 " \
                 "{%0,%1,%2,%3}, {%4,%5,%6,%7}, {%8,%9}, {%0,%1,%2,%3};" \
                 : "+f"((c)[0]), "+f"((c)[1]), "+f"((c)[2]), "+f"((c)[3]) \
                 : "r"((a)[0]), "r"((a)[1]), "r"((a)[2]), "r"((a)[3]), \
                   "r"((b)[0]), "r"((b)[1]))

__global__ __launch_bounds__(256, 1) void gemm_bf16_tc(const __nv_bfloat16* __restrict__ Ah,
                                                       const __nv_bfloat16* __restrict__ Al,
                                                       const __nv_bfloat16* __restrict__ Bh,
                                                       const __nv_bfloat16* __restrict__ Bl,
                                                       float* __restrict__ C) {
    extern __shared__ char smc[];
    const uint32_t sb = smem_u32(smc);

    const int tid = threadIdx.x;
    const int lane = tid & 31, wid = tid >> 5;
    const int bm = blockIdx.y << 7, bn = blockIdx.x << 7;
    const int wm = (wid & 1) * 64, wn = (wid >> 1) * 32;
    const int fm = lane >> 2;            // 0..7
    const int fkb = (lane & 3) * 4;      // byte offset of k-pair

    float acc[4][4][4];
#pragma unroll
    for (int i = 0; i < 4; i++)
#pragma unroll
        for (int j = 0; j < 4; j++)
#pragma unroll
            for (int q = 0; q < 4; q++) acc[i][j][q] = 0.f;

    // chunk mapping for cp.async: 512 chunks (128 rows x 4 x 16B) per tile
    const int c0row = tid >> 2, c0k = (tid & 3) * 16;            // chunk tid
    const int c1row = (tid + 256) >> 2, c1k = c0k;               // chunk tid+256

#define ISSUE_STAGE(kt, p) do {                                               \
    uint32_t s0 = sb + (p) * STAGE_B;                                         \
    size_t a0 = (size_t)(bm + c0row) * 1024 + (size_t)(kt) * 32 + (c0k >> 1); \
    size_t a1 = (size_t)(bm + c1row) * 1024 + (size_t)(kt) * 32 + (c0k >> 1); \
    size_t b0 = (size_t)(bn + c0row) * 1024 + (size_t)(kt) * 32 + (c0k >> 1); \
    size_t b1 = (size_t)(bn + c1row) * 1024 + (size_t)(kt) * 32 + (c0k >> 1); \
    uint32_t d0 = (uint32_t)(c0row * 80 + c0k);                               \
    uint32_t d1 = (uint32_t)(c1row * 80 + c1k);                               \
    cp16(s0 + d0,              Ah + a0);  cp16(s0 + d1,              Ah + a1);\
    cp16(s0 + TILE_B + d0,     Al + a0);  cp16(s0 + TILE_B + d1,     Al + a1);\
    cp16(s0 + 2 * TILE_B + d0, Bh + b0);  cp16(s0 + 2 * TILE_B + d1, Bh + b1);\
    cp16(s0 + 3 * TILE_B + d0, Bl + b0);  cp16(s0 + 3 * TILE_B + d1, Bl + b1);\
    CP_COMMIT();                                                              \
} while (0)

    ISSUE_STAGE(0, 0);

    for (int kt = 0; kt < 32; kt++) {
        const int p = kt & 1;
        if (kt < 31) {
            ISSUE_STAGE(kt + 1, p ^ 1);
            CP_WAIT(1);
        } else {
            CP_WAIT(0);
        }
        __syncthreads();

        const char* st = smc + p * STAGE_B;
#pragma unroll
        for (int k16o = 0; k16o < 64; k16o += 32) {
            uint32_t ah[4][4], al[4][4], bh[4][2], bl[4][2];
#pragma unroll
            for (int nt = 0; nt < 4; nt++) {
                int boff = (wn + nt * 8 + fm) * 80 + k16o + fkb;
                bh[nt][0] = *(const uint32_t*)(st + 2 * TILE_B + boff);
                bh[nt][1] = *(const uint32_t*)(st + 2 * TILE_B + boff + 16);
                bl[nt][0] = *(const uint32_t*)(st + 3 * TILE_B + boff);
                bl[nt][1] = *(const uint32_t*)(st + 3 * TILE_B + boff + 16);
            }
#pragma unroll
            for (int mt = 0; mt < 4; mt++) {
                int aoff = (wm + mt * 16 + fm) * 80 + k16o + fkb;
                ah[mt][0] = *(const uint32_t*)(st + aoff);
                ah[mt][1] = *(const uint32_t*)(st + aoff + 640);
                ah[mt][2] = *(const uint32_t*)(st + aoff + 16);
                ah[mt][3] = *(const uint32_t*)(st + aoff + 656);
                al[mt][0] = *(const uint32_t*)(st + TILE_B + aoff);
                al[mt][1] = *(const uint32_t*)(st + TILE_B + aoff + 640);
                al[mt][2] = *(const uint32_t*)(st + TILE_B + aoff + 16);
                al[mt][3] = *(const uint32_t*)(st + TILE_B + aoff + 656);
            }
            // hh pass (16 independent mma), then hl, then lh — long dep distance
#pragma unroll
            for (int mt = 0; mt < 4; mt++)
#pragma unroll
                for (int nt = 0; nt < 4; nt++) MMA_BF16(acc[mt][nt], ah[mt], bh[nt]);
#pragma unroll
            for (int mt = 0; mt < 4; mt++)
#pragma unroll
                for (int nt = 0; nt < 4; nt++) MMA_BF16(acc[mt][nt], ah[mt], bl[nt]);
#pragma unroll
            for (int mt = 0; mt < 4; mt++)
#pragma unroll
                for (int nt = 0; nt < 4; nt++) MMA_BF16(acc[mt][nt], al[mt], bh[nt]);
        }
        __syncthreads();
    }

    // Epilogue: direct fp32 stores
#pragma unroll
    for (int mt = 0; mt < 4; mt++) {
        int m0 = bm + wm + mt * 16 + fm;
#pragma unroll
        for (int nt = 0; nt < 4; nt++) {
            int n0 = bn + wn + nt * 8 + (fkb >> 1);
            float2 v0 = {acc[mt][nt][0], acc[mt][nt][1]};
            float2 v1 = {acc[mt][nt][2], acc[mt][nt][3]};
            *(float2*)&C[(size_t)m0 * 1024 + n0] = v0;
            *(float2*)&C[(size_t)(m0 + 8) * 1024 + n0] = v1;
        }
    }
}

// ===========================================================================
// Flash attention (unchanged — verified at 742us / rel_err 7e-7)
// ===========================================================================
__global__ __launch_bounds__(256, 1) void attn_kernel(const float* __restrict__ mask,
                                                      float* __restrict__ out) {
    extern __shared__ __align__(16) float sm[];
    float* Qts  = sm;
    float* Kts  = Qts + 128 * SQ;
    float* Vs   = Kts + 128 * SQ;
    float* Ss   = Vs + 64 * SV;
    float* rowm = Ss + 64 * SQ;
    float* rowl = rowm + 64;
    float* rowa = rowl + 64;

    const int tid = threadIdx.x;
    const int tx = tid & 15, ty = tid >> 4;
    const int qt = blockIdx.x, h = blockIdx.y, b = blockIdx.z;

    const float* Qg = g_Q + (size_t)b * TSEQ * DMOD + (size_t)h * DH;
    const float* Kg = g_K + (size_t)b * TSEQ * DMOD + (size_t)h * DH;
    const float* Vg = g_V + (size_t)b * TSEQ * DMOD + (size_t)h * DH;

    const int lr = tid >> 2, lk = tid & 3;

#pragma unroll
    for (int kk = 0; kk < 8; kk++) {
        int k0 = (lk << 2) + (kk << 4);
        float4 v = *(const float4*)&Qg[(size_t)(qt * 64 + lr) * DMOD + k0];
        Qts[(k0 + 0) * SQ + lr] = v.x;
        Qts[(k0 + 1) * SQ + lr] = v.y;
        Qts[(k0 + 2) * SQ + lr] = v.z;
        Qts[(k0 + 3) * SQ + lr] = v.w;
    }
    if (tid < 64) { rowm[tid] = -1e30f; rowl[tid] = 0.f; }

    float o[4][8];
#pragma unroll
    for (int i = 0; i < 4; i++)
#pragma unroll
        for (int j = 0; j < 8; j++) o[i][j] = 0.f;

    const int kt0 = (qt == 15) ? 0 : qt;
    const int c4 = tid & 31, vr0 = tid >> 5;

    for (int kt = kt0; kt < 16; kt++) {
        __syncthreads();
#pragma unroll
        for (int kk = 0; kk < 8; kk++) {
            int k0 = (lk << 2) + (kk << 4);
            float4 v = *(const float4*)&Kg[(size_t)(kt * 64 + lr) * DMOD + k0];
            Kts[(k0 + 0) * SQ + lr] = v.x;
            Kts[(k0 + 1) * SQ + lr] = v.y;
            Kts[(k0 + 2) * SQ + lr] = v.z;
            Kts[(k0 + 3) * SQ + lr] = v.w;
        }
#pragma unroll
        for (int rr = 0; rr < 8; rr++) {
            int vr = vr0 + (rr << 3);
            float4 v = *(const float4*)&Vg[(size_t)(kt * 64 + vr) * DMOD + (c4 << 2)];
            *(float4*)&Vs[vr * SV + (c4 << 2)] = v;
        }
        __syncthreads();

        float sacc[4][4];
#pragma unroll
        for (int i = 0; i < 4; i++)
#pragma unroll
            for (int j = 0; j < 4; j++) sacc[i][j] = 0.f;

#pragma unroll 8
        for (int k = 0; k < 128; k++) {
            float4 a  = *(const float4*)&Qts[k * SQ + (ty << 2)];
            float4 bb = *(const float4*)&Kts[k * SQ + (tx << 2)];
            float aa[4] = {a.x, a.y, a.z, a.w};
            float bv[4] = {bb.x, bb.y, bb.z, bb.w};
#pragma unroll
            for (int i = 0; i < 4; i++)
#pragma unroll
                for (int j = 0; j < 4; j++) sacc[i][j] += aa[i] * bv[j];
        }

        const int qbase = qt * 64 + (ty << 2);
        const int kbase = kt * 64 + (tx << 2);
#pragma unroll
        for (int i = 0; i < 4; i++) {
            float4 w;
            w.x = sacc[i][0] * SCALE + ((kbase + 0 <= qbase + i) ? -10000.f : 0.f);
            w.y = sacc[i][1] * SCALE + ((kbase + 1 <= qbase + i) ? -10000.f : 0.f);
            w.z = sacc[i][2] * SCALE + ((kbase + 2 <= qbase + i) ? -10000.f : 0.f);
            w.w = sacc[i][3] * SCALE + ((kbase + 3 <= qbase + i) ? -10000.f : 0.f);
            *(float4*)&Ss[((ty << 2) + i) * SQ + (tx << 2)] = w;
        }
        __syncthreads();

        {
            const int row = tid >> 2, q = tid & 3;
            float* srow = &Ss[row * SQ + (q << 4)];
            float4 v0 = *(float4*)&srow[0];
            float4 v1 = *(float4*)&srow[4];
            float4 v2 = *(float4*)&srow[8];
            float4 v3 = *(float4*)&srow[12];
            float mloc = fmaxf(
                fmaxf(fmaxf(fmaxf(v0.x, v0.y), fmaxf(v0.z, v0.w)),
                      fmaxf(fmaxf(v1.x, v1.y), fmaxf(v1.z, v1.w))),
                fmaxf(fmaxf(fmaxf(v2.x, v2.y), fmaxf(v2.z, v2.w)),
                      fmaxf(fmaxf(v3.x, v3.y), fmaxf(v3.z, v3.w))));
            mloc = fmaxf(mloc, __shfl_xor_sync(0xffffffffu, mloc, 1));
            mloc = fmaxf(mloc, __shfl_xor_sync(0xffffffffu, mloc, 2));
            float mold  = rowm[row];
            float mnew  = fmaxf(mold, mloc);
            float alpha = __expf(mold - mnew);
            v0.x = __expf(v0.x - mnew); v0.y = __expf(v0.y - mnew);
            v0.z = __expf(v0.z - mnew); v0.w = __expf(v0.w - mnew);
            v1.x = __expf(v1.x - mnew); v1.y = __expf(v1.y - mnew);
            v1.z = __expf(v1.z - mnew); v1.w = __expf(v1.w - mnew);
            v2.x = __expf(v2.x - mnew); v2.y = __expf(v2.y - mnew);
            v2.z = __expf(v2.z - mnew); v2.w = __expf(v2.w - mnew);
            v3.x = __expf(v3.x - mnew); v3.y = __expf(v3.y - mnew);
            v3.z = __expf(v3.z - mnew); v3.w = __expf(v3.w - mnew);
            *(float4*)&srow[0]  = v0;
            *(float4*)&srow[4]  = v1;
            *(float4*)&srow[8]  = v2;
            *(float4*)&srow[12] = v3;
            float ssum = (v0.x + v0.y + v0.z + v0.w) + (v1.x + v1.y + v1.z + v1.w) +
                         (v2.x + v2.y + v2.z + v2.w) + (v3.x + v3.y + v3.z + v3.w);
            ssum += __shfl_xor_sync(0xffffffffu, ssum, 1);
            ssum += __shfl_xor_sync(0xffffffffu, ssum, 2);
            if (q == 0) {
                rowl[row] = rowl[row] * alpha + ssum;
                rowm[row] = mnew;
                rowa[row] = alpha;
            }
        }
        __syncthreads();

        float al[4];
#pragma unroll
        for (int i = 0; i < 4; i++) al[i] = rowa[(ty << 2) + i];
#pragma unroll
        for (int i = 0; i < 4; i++)
#pragma unroll
            for (int j = 0; j < 8; j++) o[i][j] *= al[i];

#pragma unroll 4
        for (int k = 0; k < 64; k++) {
            float av[4];
            av[0] = Ss[((ty << 2) + 0) * SQ + k];
            av[1] = Ss[((ty << 2) + 1) * SQ + k];
            av[2] = Ss[((ty << 2) + 2) * SQ + k];
            av[3] = Ss[((ty << 2) + 3) * SQ + k];
            float4 b0 = *(const float4*)&Vs[k * SV + (tx << 3)];
            float4 b1 = *(const float4*)&Vs[k * SV + (tx << 3) + 4];
            float bv[8] = {b0.x, b0.y, b0.z, b0.w, b1.x, b1.y, b1.z, b1.w};
#pragma unroll
            for (int i = 0; i < 4; i++)
#pragma unroll
                for (int j = 0; j < 8; j++) o[i][j] += av[i] * bv[j];
        }
    }

    __syncthreads();
#pragma unroll
    for (int i = 0; i < 4; i++) {
        int row = (ty << 2) + i;
        float scl = (1.f / rowl[row]) * mask[(size_t)b * TSEQ + qt * 64 + row];
        float4 w0, w1;
        w0.x = o[i][0] * scl; w0.y = o[i][1] * scl;
        w0.z = o[i][2] * scl; w0.w = o[i][3] * scl;
        w1.x = o[i][4] * scl; w1.y = o[i][5] * scl;
        w1.z = o[i][6] * scl; w1.w = o[i][7] * scl;
        size_t base = ((size_t)(b * TSEQ + qt * 64 + row)) * DMOD + h * DH + (tx << 3);
        *(float4*)&out[base]     = w0;
        *(float4*)&out[base + 4] = w1;
    }
}

extern "C" void kernel_launch(void* const* d_in, const int* in_sizes, int n_in,
                              void* d_out, int out_size) {
    const float* x    = (const float*)d_in[0];
    const float* mask = (const float*)d_in[1];
    const float* Wq   = (const float*)d_in[2];
    const float* Wk   = (const float*)d_in[3];
    const float* Wv   = (const float*)d_in[4];
    float* out = (float*)d_out;

    float *q, *k, *v;
    __nv_bfloat16 *xh, *xl, *wh, *wl;
    cudaGetSymbolAddress((void**)&q, g_Q);
    cudaGetSymbolAddress((void**)&k, g_K);
    cudaGetSymbolAddress((void**)&v, g_V);
    cudaGetSymbolAddress((void**)&xh, g_Xh);
    cudaGetSymbolAddress((void**)&xl, g_Xl);
    cudaGetSymbolAddress((void**)&wh, g_Wh);
    cudaGetSymbolAddress((void**)&wl, g_Wl);

    cudaFuncSetAttribute(gemm_bf16_tc, cudaFuncAttributeMaxDynamicSharedMemorySize,
                         GEMM_SMEM);

    const int xn4 = BATCH * TSEQ * DMOD / 4;   // 2097152
    const int wn4 = DMOD * DMOD / 4;           // 262144
    split_bf16<<<xn4 / 256, 256>>>((const float4*)x, (uint2*)xh, (uint2*)xl);

    dim3 ggrid(DMOD / 128, (BATCH * TSEQ) / 128);

    split_bf16<<<wn4 / 256, 256>>>((const float4*)Wq, (uint2*)wh, (uint2*)wl);
    gemm_bf16_tc<<<ggrid, 256, GEMM_SMEM>>>(xh, xl, wh, wl, q);

    split_bf16<<<wn4 / 256, 256>>>((const float4*)Wk, (uint2*)wh, (uint2*)wl);
    gemm_bf16_tc<<<ggrid, 256, GEMM_SMEM>>>(xh, xl, wh, wl, k);

    split_bf16<<<wn4 / 256, 256>>>((const float4*)Wv, (uint2*)wh, (uint2*)wl);
    gemm_bf16_tc<<<ggrid, 256, GEMM_SMEM>>>(xh, xl, wh, wl, v);

    int smem = (128 * SQ * 2 + 64 * SV + 64 * SQ + 192) * (int)sizeof(float);
    cudaFuncSetAttribute(attn_kernel, cudaFuncAttributeMaxDynamicSharedMemorySize, smem);
    dim3 agrid(TSEQ / 64, NH, BATCH);
    attn_kernel<<<agrid, 256, smem>>>(mask, out);
}

// round 4
// speedup vs baseline: 2.1438x; 1.5313x over previous
#include <cuda_runtime.h>
#include <cuda_bf16.h>
#include <cstdint>

#define BATCH 8
#define TSEQ 1024
#define DMOD 1024
#define NH 8
#define DH 128
#define SCALE 0.08838834764831845f

// Scratch (device globals: allocation-free).
__device__ __nv_bfloat16 g_Xh[BATCH * TSEQ * DMOD];
__device__ __nv_bfloat16 g_Xl[BATCH * TSEQ * DMOD];
__device__ __nv_bfloat16 g_Wh[DMOD * DMOD];
__device__ __nv_bfloat16 g_Wl[DMOD * DMOD];
__device__ __nv_bfloat16 g_Qh[BATCH * TSEQ * DMOD];
__device__ __nv_bfloat16 g_Ql[BATCH * TSEQ * DMOD];
__device__ __nv_bfloat16 g_Kh[BATCH * TSEQ * DMOD];
__device__ __nv_bfloat16 g_Kl[BATCH * TSEQ * DMOD];
__device__ __nv_bfloat16 g_Vh[BATCH * TSEQ * DMOD];
__device__ __nv_bfloat16 g_Vl[BATCH * TSEQ * DMOD];

__device__ __forceinline__ uint32_t smem_u32(const void* p) {
    uint32_t a;
    asm("{ .reg .u64 t; cvta.to.shared.u64 t, %1; cvt.u32.u64 %0, t; }"
        : "=r"(a) : "l"(p));
    return a;
}
__device__ __forceinline__ void cp16(uint32_t dst, const void* src) {
    asm volatile("cp.async.cg.shared.global [%0], [%1], 16;"
                 :: "r"(dst), "l"(src) : "memory");
}
#define CP_COMMIT() asm volatile("cp.async.commit_group;" ::: "memory")
#define CP_WAIT(n)  asm volatile("cp.async.wait_group %0;" :: "n"(n) : "memory")

#define MMA_B2(c, a, b0_, b1_) \
    asm volatile("mma.sync.aligned.m16n8k16.row.col.f32.bf16.bf16.f32 " \
                 "{%0,%1,%2,%3}, {%4,%5,%6,%7}, {%8,%9}, {%0,%1,%2,%3};" \
                 : "+f"((c)[0]), "+f"((c)[1]), "+f"((c)[2]), "+f"((c)[3]) \
                 : "r"((a)[0]), "r"((a)[1]), "r"((a)[2]), "r"((a)[3]), \
                   "r"(b0_), "r"(b1_))

#define LDMX4(r, addr) \
    asm volatile("ldmatrix.sync.aligned.m8n8.x4.shared.b16 {%0,%1,%2,%3}, [%4];" \
                 : "=r"((r)[0]), "=r"((r)[1]), "=r"((r)[2]), "=r"((r)[3]) : "r"(addr))
#define LDMX4T(r, addr) \
    asm volatile("ldmatrix.sync.aligned.m8n8.x4.trans.shared.b16 {%0,%1,%2,%3}, [%4];" \
                 : "=r"((r)[0]), "=r"((r)[1]), "=r"((r)[2]), "=r"((r)[3]) : "r"(addr))

__device__ __forceinline__ uint32_t packbf(float x, float y) {
    __nv_bfloat16 hx = __float2bfloat16(x), hy = __float2bfloat16(y);
    return (uint32_t)__bfloat16_as_ushort(hx) |
           ((uint32_t)__bfloat16_as_ushort(hy) << 16);
}

// ===========================================================================
// Split fp32 -> (bf16 hi, bf16 lo)
// ===========================================================================
__global__ __launch_bounds__(256) void split_bf16(const float4* __restrict__ src,
                                                  uint2* __restrict__ hi,
                                                  uint2* __restrict__ lo) {
    int i = blockIdx.x * 256 + threadIdx.x;
    float4 v = src[i];
    __nv_bfloat16 h0 = __float2bfloat16(v.x), h1 = __float2bfloat16(v.y);
    __nv_bfloat16 h2 = __float2bfloat16(v.z), h3 = __float2bfloat16(v.w);
    uint2 H, L;
    H.x = (uint32_t)__bfloat16_as_ushort(h0) | ((uint32_t)__bfloat16_as_ushort(h1) << 16);
    H.y = (uint32_t)__bfloat16_as_ushort(h2) | ((uint32_t)__bfloat16_as_ushort(h3) << 16);
    L.x = packbf(v.x - __bfloat162float(h0), v.y - __bfloat162float(h1));
    L.y = packbf(v.z - __bfloat162float(h2), v.w - __bfloat162float(h3));
    hi[i] = H;
    lo[i] = L;
}

// ===========================================================================
// GEMM: Ch/Cl (bf16 hi/lo) [8192,1024] = A @ W^T via mma.sync bf16, 3-product
// split. 128x128 block, BK=32, 8 warps, 2-stage cp.async.
// ===========================================================================
#define TILE_B 10240
#define STAGE_B (4 * TILE_B)
#define GEMM_SMEM (2 * STAGE_B)

__global__ __launch_bounds__(256, 1) void gemm_bf16_tc(const __nv_bfloat16* __restrict__ Ah,
                                                       const __nv_bfloat16* __restrict__ Al,
                                                       const __nv_bfloat16* __restrict__ Bh,
                                                       const __nv_bfloat16* __restrict__ Bl,
                                                       __nv_bfloat16* __restrict__ Ch,
                                                       __nv_bfloat16* __restrict__ Cl) {
    extern __shared__ char smc[];
    const uint32_t sb = smem_u32(smc);

    const int tid = threadIdx.x;
    const int lane = tid & 31, wid = tid >> 5;
    const int bm = blockIdx.y << 7, bn = blockIdx.x << 7;
    const int wm = (wid & 1) * 64, wn = (wid >> 1) * 32;
    const int fm = lane >> 2;
    const int fkb = (lane & 3) * 4;

    float acc[4][4][4];
#pragma unroll
    for (int i = 0; i < 4; i++)
#pragma unroll
        for (int j = 0; j < 4; j++)
#pragma unroll
            for (int q = 0; q < 4; q++) acc[i][j][q] = 0.f;

    const int c0row = tid >> 2, c0k = (tid & 3) * 16;
    const int c1row = (tid + 256) >> 2, c1k = c0k;

#define ISSUE_STAGE(kt, p) do {                                               \
    uint32_t s0 = sb + (p) * STAGE_B;                                         \
    size_t a0 = (size_t)(bm + c0row) * 1024 + (size_t)(kt) * 32 + (c0k >> 1); \
    size_t a1 = (size_t)(bm + c1row) * 1024 + (size_t)(kt) * 32 + (c0k >> 1); \
    size_t b0 = (size_t)(bn + c0row) * 1024 + (size_t)(kt) * 32 + (c0k >> 1); \
    size_t b1 = (size_t)(bn + c1row) * 1024 + (size_t)(kt) * 32 + (c0k >> 1); \
    uint32_t d0 = (uint32_t)(c0row * 80 + c0k);                               \
    uint32_t d1 = (uint32_t)(c1row * 80 + c1k);                               \
    cp16(s0 + d0,              Ah + a0);  cp16(s0 + d1,              Ah + a1);\
    cp16(s0 + TILE_B + d0,     Al + a0);  cp16(s0 + TILE_B + d1,     Al + a1);\
    cp16(s0 + 2 * TILE_B + d0, Bh + b0);  cp16(s0 + 2 * TILE_B + d1, Bh + b1);\
    cp16(s0 + 3 * TILE_B + d0, Bl + b0);  cp16(s0 + 3 * TILE_B + d1, Bl + b1);\
    CP_COMMIT();                                                              \
} while (0)

    ISSUE_STAGE(0, 0);

    for (int kt = 0; kt < 32; kt++) {
        const int p = kt & 1;
        if (kt < 31) {
            ISSUE_STAGE(kt + 1, p ^ 1);
            CP_WAIT(1);
        } else {
            CP_WAIT(0);
        }
        __syncthreads();

        const char* st = smc + p * STAGE_B;
#pragma unroll
        for (int k16o = 0; k16o < 64; k16o += 32) {
            uint32_t ah[4][4], al[4][4], bh[4][2], bl[4][2];
#pragma unroll
            for (int nt = 0; nt < 4; nt++) {
                int boff = (wn + nt * 8 + fm) * 80 + k16o + fkb;
                bh[nt][0] = *(const uint32_t*)(st + 2 * TILE_B + boff);
                bh[nt][1] = *(const uint32_t*)(st + 2 * TILE_B + boff + 16);
                bl[nt][0] = *(const uint32_t*)(st + 3 * TILE_B + boff);
                bl[nt][1] = *(const uint32_t*)(st + 3 * TILE_B + boff + 16);
            }
#pragma unroll
            for (int mt = 0; mt < 4; mt++) {
                int aoff = (wm + mt * 16 + fm) * 80 + k16o + fkb;
                ah[mt][0] = *(const uint32_t*)(st + aoff);
                ah[mt][1] = *(const uint32_t*)(st + aoff + 640);
                ah[mt][2] = *(const uint32_t*)(st + aoff + 16);
                ah[mt][3] = *(const uint32_t*)(st + aoff + 656);
                al[mt][0] = *(const uint32_t*)(st + TILE_B + aoff);
                al[mt][1] = *(const uint32_t*)(st + TILE_B + aoff + 640);
                al[mt][2] = *(const uint32_t*)(st + TILE_B + aoff + 16);
                al[mt][3] = *(const uint32_t*)(st + TILE_B + aoff + 656);
            }
#pragma unroll
            for (int mt = 0; mt < 4; mt++)
#pragma unroll
                for (int nt = 0; nt < 4; nt++)
                    MMA_B2(acc[mt][nt], ah[mt], bh[nt][0], bh[nt][1]);
#pragma unroll
            for (int mt = 0; mt < 4; mt++)
#pragma unroll
                for (int nt = 0; nt < 4; nt++)
                    MMA_B2(acc[mt][nt], ah[mt], bl[nt][0], bl[nt][1]);
#pragma unroll
            for (int mt = 0; mt < 4; mt++)
#pragma unroll
                for (int nt = 0; nt < 4; nt++)
                    MMA_B2(acc[mt][nt], al[mt], bh[nt][0], bh[nt][1]);
        }
        __syncthreads();
    }

    // Epilogue: split fp32 acc -> bf16 hi/lo pairs, store packed
#pragma unroll
    for (int mt = 0; mt < 4; mt++) {
        size_t m0 = (size_t)(bm + wm + mt * 16 + fm);
#pragma unroll
        for (int nt = 0; nt < 4; nt++) {
            size_t n0 = (size_t)(bn + wn + nt * 8 + (fkb >> 1));
            float c0 = acc[mt][nt][0], c1 = acc[mt][nt][1];
            float c2 = acc[mt][nt][2], c3 = acc[mt][nt][3];
            __nv_bfloat16 h0 = __float2bfloat16(c0), h1 = __float2bfloat16(c1);
            __nv_bfloat16 h2 = __float2bfloat16(c2), h3 = __float2bfloat16(c3);
            uint32_t ph01 = (uint32_t)__bfloat16_as_ushort(h0) |
                            ((uint32_t)__bfloat16_as_ushort(h1) << 16);
            uint32_t ph23 = (uint32_t)__bfloat16_as_ushort(h2) |
                            ((uint32_t)__bfloat16_as_ushort(h3) << 16);
            uint32_t pl01 = packbf(c0 - __bfloat162float(h0), c1 - __bfloat162float(h1));
            uint32_t pl23 = packbf(c2 - __bfloat162float(h2), c3 - __bfloat162float(h3));
            *(uint32_t*)((char*)Ch + (m0 * 1024 + n0) * 2) = ph01;
            *(uint32_t*)((char*)Cl + (m0 * 1024 + n0) * 2) = pl01;
            *(uint32_t*)((char*)Ch + ((m0 + 8) * 1024 + n0) * 2) = ph23;
            *(uint32_t*)((char*)Cl + ((m0 + 8) * 1024 + n0) * 2) = pl23;
        }
    }
}

// ===========================================================================
// Tensor-core flash attention. 64 q-rows x 64 k-cols tiles, d=128.
// S = QK^T and O = PV via mma.sync bf16 with 3-product split precision.
// ldmatrix fragments; double-buffered cp.async K/V.
// ===========================================================================
// smem offsets (bytes)
#define A_QH 0
#define A_QL 17408
#define A_KB 34816          // 2 stages x (KH 17408 + KL 17408)
#define A_VB 104448         // 2 stages x (VH + VL)
#define A_SS 174080         // S fp32 [64][68]
#define A_PH 191488         // P hi bf16 [64][72]
#define A_PL 200704
#define A_RM 209920
#define A_RL 210176
#define A_RA 210432
#define ATTN_SMEM 210688
#define KV_STRIDE 34816

__global__ __launch_bounds__(256, 1) void attn_tc(const float* __restrict__ mask,
                                                  float* __restrict__ out) {
    extern __shared__ char smc[];
    const uint32_t sb = smem_u32(smc);

    const int tid = threadIdx.x;
    const int lane = tid & 31, wid = tid >> 5;
    const int qt = blockIdx.x, h = blockIdx.y, b = blockIdx.z;
    const int wm = (wid & 3) * 16;        // S and PV row tile
    const int wnS = (wid >> 2) * 32;      // S col tile
    const int wnV = (wid >> 2) * 64;      // O col tile
    const int fm = lane >> 2;

    const size_t bh_off = (size_t)b * TSEQ * DMOD + (size_t)h * DH;
    const __nv_bfloat16* Qh = g_Qh + bh_off;
    const __nv_bfloat16* Ql = g_Ql + bh_off;
    const __nv_bfloat16* Kh = g_Kh + bh_off;
    const __nv_bfloat16* Kl = g_Kl + bh_off;
    const __nv_bfloat16* Vh = g_Vh + bh_off;
    const __nv_bfloat16* Vl = g_Vl + bh_off;

    const int kt0 = (qt == 15) ? 0 : qt;

    // --- Q tile load (64 rows x 128, rows stride 272B in smem) ---
    for (int c = tid; c < 1024; c += 256) {
        int r = c >> 4, o = c & 15;
        uint32_t d = (uint32_t)(r * 272 + o * 16);
        size_t g = (size_t)(qt * 64 + r) * DMOD + o * 8;
        cp16(sb + A_QH + d, Qh + g);
        cp16(sb + A_QL + d, Ql + g);
    }

#define ISSUE_KV(kt_, s_) do {                                           \
    uint32_t kst = sb + A_KB + (uint32_t)(s_) * KV_STRIDE;               \
    uint32_t vst = sb + A_VB + (uint32_t)(s_) * KV_STRIDE;               \
    size_t roff = (size_t)(kt_) * 64 * DMOD;                             \
    for (int c = tid; c < 1024; c += 256) {                              \
        int r = c >> 4, o = c & 15;                                      \
        uint32_t d = (uint32_t)(r * 272 + o * 16);                       \
        size_t g = roff + (size_t)r * DMOD + o * 8;                      \
        cp16(kst + d,         Kh + g);                                   \
        cp16(kst + 17408 + d, Kl + g);                                   \
        cp16(vst + d,         Vh + g);                                   \
        cp16(vst + 17408 + d, Vl + g);                                   \
    }                                                                    \
} while (0)

    ISSUE_KV(kt0, 0);
    CP_COMMIT();                 // group: Q + KV(kt0)
    ISSUE_KV(kt0 + 1, 1);
    CP_COMMIT();                 // group: KV(kt0+1)

    float* rowm = (float*)(smc + A_RM);
    float* rowl = (float*)(smc + A_RL);
    float* rowa = (float*)(smc + A_RA);
    if (tid < 64) { rowm[tid] = -1e30f; rowl[tid] = 0.f; }

    float acc_o[8][4];
#pragma unroll
    for (int j = 0; j < 8; j++)
#pragma unroll
        for (int q = 0; q < 4; q++) acc_o[j][q] = 0.f;

    const int grp = lane >> 3, li = lane & 7;

    for (int kt = kt0; kt < 16; kt++) {
        const int p = (kt - kt0) & 1;
        if (kt == 15) { CP_WAIT(0); } else { CP_WAIT(1); }
        __syncthreads();

        const uint32_t kst = sb + A_KB + (uint32_t)p * KV_STRIDE;
        const uint32_t vst = sb + A_VB + (uint32_t)p * KV_STRIDE;

        // ---- S = Q K^T (3-product split) ----
        float sacc[4][4];
#pragma unroll
        for (int j = 0; j < 4; j++)
#pragma unroll
            for (int q = 0; q < 4; q++) sacc[j][q] = 0.f;

#pragma unroll
        for (int ks = 0; ks < 8; ks++) {
            uint32_t ah[4], al[4];
            {
                uint32_t arow = (uint32_t)(wm + ((grp & 1) << 3) + li);
                uint32_t akb = (uint32_t)(ks * 32 + ((grp >> 1) << 4));
                LDMX4(ah, sb + A_QH + arow * 272 + akb);
                LDMX4(al, sb + A_QL + arow * 272 + akb);
            }
            uint32_t bh[2][4], bl[2][4];
#pragma unroll
            for (int j2 = 0; j2 < 2; j2++) {
                uint32_t nrow = (uint32_t)(wnS + j2 * 16 + ((grp >> 1) << 3) + li);
                uint32_t kb = (uint32_t)(ks * 32 + ((grp & 1) << 4));
                LDMX4(bh[j2], kst + nrow * 272 + kb);
                LDMX4(bl[j2], kst + 17408 + nrow * 272 + kb);
            }
#pragma unroll
            for (int j = 0; j < 4; j++)
                MMA_B2(sacc[j], ah, bh[j >> 1][(j & 1) * 2], bh[j >> 1][(j & 1) * 2 + 1]);
#pragma unroll
            for (int j = 0; j < 4; j++)
                MMA_B2(sacc[j], ah, bl[j >> 1][(j & 1) * 2], bl[j >> 1][(j & 1) * 2 + 1]);
#pragma unroll
            for (int j = 0; j < 4; j++)
                MMA_B2(sacc[j], al, bh[j >> 1][(j & 1) * 2], bh[j >> 1][(j & 1) * 2 + 1]);
        }

        // scale + mask-adder, write S to smem
        {
            const int r0 = wm + fm;
            const int qg0 = qt * 64 + r0, qg1 = qg0 + 8;
#pragma unroll
            for (int j = 0; j < 4; j++) {
                int col = wnS + 8 * j + 2 * (lane & 3);
                int kg = kt * 64 + col;
                float2 v01, v23;
                v01.x = sacc[j][0] * SCALE + ((kg     <= qg0) ? -10000.f : 0.f);
                v01.y = sacc[j][1] * SCALE + ((kg + 1 <= qg0) ? -10000.f : 0.f);
                v23.x = sacc[j][2] * SCALE + ((kg     <= qg1) ? -10000.f : 0.f);
                v23.y = sacc[j][3] * SCALE + ((kg + 1 <= qg1) ? -10000.f : 0.f);
                *(float2*)(smc + A_SS + (size_t)r0 * 272 + col * 4) = v01;
                *(float2*)(smc + A_SS + (size_t)(r0 + 8) * 272 + col * 4) = v23;
            }
        }
        __syncthreads();

        // ---- online softmax + P -> bf16 hi/lo ----
        {
            const int row = tid >> 2, q = tid & 3;
            float* srow = (float*)(smc + A_SS + (size_t)row * 272) + (q << 4);
            float4 v0 = *(float4*)&srow[0];
            float4 v1 = *(float4*)&srow[4];
            float4 v2 = *(float4*)&srow[8];
            float4 v3 = *(float4*)&srow[12];
            float mloc = fmaxf(
                fmaxf(fmaxf(fmaxf(v0.x, v0.y), fmaxf(v0.z, v0.w)),
                      fmaxf(fmaxf(v1.x, v1.y), fmaxf(v1.z, v1.w))),
                fmaxf(fmaxf(fmaxf(v2.x, v2.y), fmaxf(v2.z, v2.w)),
                      fmaxf(fmaxf(v3.x, v3.y), fmaxf(v3.z, v3.w))));
            mloc = fmaxf(mloc, __shfl_xor_sync(0xffffffffu, mloc, 1));
            mloc = fmaxf(mloc, __shfl_xor_sync(0xffffffffu, mloc, 2));
            float mold = rowm[row];
            float mnew = fmaxf(mold, mloc);
            float alpha = __expf(mold - mnew);
            v0.x = __expf(v0.x - mnew); v0.y = __expf(v0.y - mnew);
            v0.z = __expf(v0.z - mnew); v0.w = __expf(v0.w - mnew);
            v1.x = __expf(v1.x - mnew); v1.y = __expf(v1.y - mnew);
            v1.z = __expf(v1.z - mnew); v1.w = __expf(v1.w - mnew);
            v2.x = __expf(v2.x - mnew); v2.y = __expf(v2.y - mnew);
            v2.z = __expf(v2.z - mnew); v2.w = __expf(v2.w - mnew);
            v3.x = __expf(v3.x - mnew); v3.y = __expf(v3.y - mnew);
            v3.z = __expf(v3.z - mnew); v3.w = __expf(v3.w - mnew);

            uint32_t* phr = (uint32_t*)(smc + A_PH + (size_t)row * 144) + (q << 3);
            uint32_t* plr = (uint32_t*)(smc + A_PL + (size_t)row * 144) + (q << 3);
            const float4 vv[4] = {v0, v1, v2, v3};
#pragma unroll
            for (int u = 0; u < 4; u++) {
                float a0 = vv[u].x, a1 = vv[u].y, a2 = vv[u].z, a3 = vv[u].w;
                __nv_bfloat16 h0 = __float2bfloat16(a0), h1 = __float2bfloat16(a1);
                __nv_bfloat16 h2 = __float2bfloat16(a2), h3 = __float2bfloat16(a3);
                phr[2 * u]     = (uint32_t)__bfloat16_as_ushort(h0) |
                                 ((uint32_t)__bfloat16_as_ushort(h1) << 16);
                phr[2 * u + 1] = (uint32_t)__bfloat16_as_ushort(h2) |
                                 ((uint32_t)__bfloat16_as_ushort(h3) << 16);
                plr[2 * u]     = packbf(a0 - __bfloat162float(h0), a1 - __bfloat162float(h1));
                plr[2 * u + 1] = packbf(a2 - __bfloat162float(h2), a3 - __bfloat162float(h3));
            }

            float ssum = (v0.x + v0.y + v0.z + v0.w) + (v1.x + v1.y + v1.z + v1.w) +
                         (v2.x + v2.y + v2.z + v2.w) + (v3.x + v3.y + v3.z + v3.w);
            ssum += __shfl_xor_sync(0xffffffffu, ssum, 1);
            ssum += __shfl_xor_sync(0xffffffffu, ssum, 2);
            if (q == 0) {
                rowl[row] = rowl[row] * alpha + ssum;
                rowm[row] = mnew;
                rowa[row] = alpha;
            }
        }
        __syncthreads();

        // ---- O = O*alpha + P V (3-product split) ----
        {
            float al0 = rowa[wm + fm], al1 = rowa[wm + fm + 8];
#pragma unroll
            for (int j = 0; j < 8; j++) {
                acc_o[j][0] *= al0; acc_o[j][1] *= al0;
                acc_o[j][2] *= al1; acc_o[j][3] *= al1;
            }
#pragma unroll
            for (int ks = 0; ks < 4; ks++) {
                uint32_t ph[4], pl[4];
                {
                    uint32_t arow = (uint32_t)(wm + ((grp & 1) << 3) + li);
                    uint32_t akb = (uint32_t)(ks * 32 + ((grp >> 1) << 4));
                    LDMX4(ph, sb + A_PH + arow * 144 + akb);
                    LDMX4(pl, sb + A_PL + arow * 144 + akb);
                }
#pragma unroll
                for (int j2 = 0; j2 < 4; j2++) {
                    uint32_t bvh[4], bvl[4];
                    uint32_t krow = (uint32_t)(ks * 16 + ((grp & 1) << 3) + li);
                    uint32_t nb = (uint32_t)((wnV + 16 * j2 + ((grp >> 1) << 3)) * 2);
                    LDMX4T(bvh, vst + krow * 272 + nb);
                    LDMX4T(bvl, vst + 17408 + krow * 272 + nb);
#pragma unroll
                    for (int jj = 0; jj < 2; jj++) {
                        int j = 2 * j2 + jj;
                        MMA_B2(acc_o[j], ph, bvh[jj * 2], bvh[jj * 2 + 1]);
                        MMA_B2(acc_o[j], ph, bvl[jj * 2], bvl[jj * 2 + 1]);
                        MMA_B2(acc_o[j], pl, bvh[jj * 2], bvh[jj * 2 + 1]);
                    }
                }
            }
        }
        __syncthreads();  // all warps done with stage p before refill

        if (kt + 2 <= 15) {
            ISSUE_KV(kt + 2, p);
            CP_COMMIT();
        }
    }

    // ---- epilogue ----
    {
        const int r0 = wm + fm;
        const int grow0 = b * TSEQ + qt * 64 + r0;
        float scl0 = (1.f / rowl[r0]) * mask[(size_t)b * TSEQ + qt * 64 + r0];
        float scl1 = (1.f / rowl[r0 + 8]) * mask[(size_t)b * TSEQ + qt * 64 + r0 + 8];
#pragma unroll
        for (int j = 0; j < 8; j++) {
            int col = h * DH + wnV + j * 8 + 2 * (lane & 3);
            float2 w0 = {acc_o[j][0] * scl0, acc_o[j][1] * scl0};
            float2 w1 = {acc_o[j][2] * scl1, acc_o[j][3] * scl1};
            *(float2*)&out[(size_t)grow0 * DMOD + col] = w0;
            *(float2*)&out[(size_t)(grow0 + 8) * DMOD + col] = w1;
        }
    }
}

extern "C" void kernel_launch(void* const* d_in, const int* in_sizes, int n_in,
                              void* d_out, int out_size) {
    const float* x    = (const float*)d_in[0];
    const float* mask = (const float*)d_in[1];
    const float* Wq   = (const float*)d_in[2];
    const float* Wk   = (const float*)d_in[3];
    const float* Wv   = (const float*)d_in[4];
    float* out = (float*)d_out;

    __nv_bfloat16 *xh, *xl, *wh, *wl, *qh, *ql, *kh, *kl, *vh, *vl;
    cudaGetSymbolAddress((void**)&xh, g_Xh);
    cudaGetSymbolAddress((void**)&xl, g_Xl);
    cudaGetSymbolAddress((void**)&wh, g_Wh);
    cudaGetSymbolAddress((void**)&wl, g_Wl);
    cudaGetSymbolAddress((void**)&qh, g_Qh);
    cudaGetSymbolAddress((void**)&ql, g_Ql);
    cudaGetSymbolAddress((void**)&kh, g_Kh);
    cudaGetSymbolAddress((void**)&kl, g_Kl);
    cudaGetSymbolAddress((void**)&vh, g_Vh);
    cudaGetSymbolAddress((void**)&vl, g_Vl);

    cudaFuncSetAttribute(gemm_bf16_tc, cudaFuncAttributeMaxDynamicSharedMemorySize,
                         GEMM_SMEM);
    cudaFuncSetAttribute(attn_tc, cudaFuncAttributeMaxDynamicSharedMemorySize,
                         ATTN_SMEM);

    const int xn4 = BATCH * TSEQ * DMOD / 4;
    const int wn4 = DMOD * DMOD / 4;
    split_bf16<<<xn4 / 256, 256>>>((const float4*)x, (uint2*)xh, (uint2*)xl);

    dim3 ggrid(DMOD / 128, (BATCH * TSEQ) / 128);

    split_bf16<<<wn4 / 256, 256>>>((const float4*)Wq, (uint2*)wh, (uint2*)wl);
    gemm_bf16_tc<<<ggrid, 256, GEMM_SMEM>>>(xh, xl, wh, wl, qh, ql);

    split_bf16<<<wn4 / 256, 256>>>((const float4*)Wk, (uint2*)wh, (uint2*)wl);
    gemm_bf16_tc<<<ggrid, 256, GEMM_SMEM>>>(xh, xl, wh, wl, kh, kl);

    split_bf16<<<wn4 / 256, 256>>>((const float4*)Wv, (uint2*)wh, (uint2*)wl);
    gemm_bf16_tc<<<ggrid, 256, GEMM_SMEM>>>(xh, xl, wh, wl, vh, vl);

    dim3 agrid(TSEQ / 64, NH, BATCH);
    attn_tc<<<agrid, 256, ATTN_SMEM>>>(mask, out);
}

// round 5
// speedup vs baseline: 2.3366x; 1.0899x over previous
#include <cuda_runtime.h>
#include <cuda_bf16.h>
#include <cstdint>

#define BATCH 8
#define TSEQ 1024
#define DMOD 1024
#define NH 8
#define DH 128
#define SCALE 0.08838834764831845f

// Scratch (device globals: allocation-free).
__device__ __nv_bfloat16 g_Xh[BATCH * TSEQ * DMOD];
__device__ __nv_bfloat16 g_Xl[BATCH * TSEQ * DMOD];
__device__ __nv_bfloat16 g_Wh[3 * DMOD * DMOD];
__device__ __nv_bfloat16 g_Wl[3 * DMOD * DMOD];
__device__ __nv_bfloat16 g_Qh[BATCH * TSEQ * DMOD];
__device__ __nv_bfloat16 g_Ql[BATCH * TSEQ * DMOD];
__device__ __nv_bfloat16 g_Kh[BATCH * TSEQ * DMOD];
__device__ __nv_bfloat16 g_Kl[BATCH * TSEQ * DMOD];
__device__ __nv_bfloat16 g_Vh[BATCH * TSEQ * DMOD];
__device__ __nv_bfloat16 g_Vl[BATCH * TSEQ * DMOD];

__device__ __forceinline__ uint32_t smem_u32(const void* p) {
    uint32_t a;
    asm("{ .reg .u64 t; cvta.to.shared.u64 t, %1; cvt.u32.u64 %0, t; }"
        : "=r"(a) : "l"(p));
    return a;
}
__device__ __forceinline__ void cp16(uint32_t dst, const void* src) {
    asm volatile("cp.async.cg.shared.global [%0], [%1], 16;"
                 :: "r"(dst), "l"(src) : "memory");
}
#define CP_COMMIT() asm volatile("cp.async.commit_group;" ::: "memory")
#define CP_WAIT(n)  asm volatile("cp.async.wait_group %0;" :: "n"(n) : "memory")

#define MMA_B2(c, a, b0_, b1_) \
    asm volatile("mma.sync.aligned.m16n8k16.row.col.f32.bf16.bf16.f32 " \
                 "{%0,%1,%2,%3}, {%4,%5,%6,%7}, {%8,%9}, {%0,%1,%2,%3};" \
                 : "+f"((c)[0]), "+f"((c)[1]), "+f"((c)[2]), "+f"((c)[3]) \
                 : "r"((a)[0]), "r"((a)[1]), "r"((a)[2]), "r"((a)[3]), \
                   "r"(b0_), "r"(b1_))

#define LDMX4(r, addr) \
    asm volatile("ldmatrix.sync.aligned.m8n8.x4.shared.b16 {%0,%1,%2,%3}, [%4];" \
                 : "=r"((r)[0]), "=r"((r)[1]), "=r"((r)[2]), "=r"((r)[3]) : "r"(addr))
#define LDMX4T(r, addr) \
    asm volatile("ldmatrix.sync.aligned.m8n8.x4.trans.shared.b16 {%0,%1,%2,%3}, [%4];" \
                 : "=r"((r)[0]), "=r"((r)[1]), "=r"((r)[2]), "=r"((r)[3]) : "r"(addr))

__device__ __forceinline__ uint32_t packbf(float x, float y) {
    __nv_bfloat16 hx = __float2bfloat16(x), hy = __float2bfloat16(y);
    return (uint32_t)__bfloat16_as_ushort(hx) |
           ((uint32_t)__bfloat16_as_ushort(hy) << 16);
}

// ===========================================================================
// Split fp32 -> (bf16 hi, bf16 lo)
// ===========================================================================
__global__ __launch_bounds__(256) void split_bf16(const float4* __restrict__ src,
                                                  uint2* __restrict__ hi,
                                                  uint2* __restrict__ lo) {
    int i = blockIdx.x * 256 + threadIdx.x;
    float4 v = src[i];
    __nv_bfloat16 h0 = __float2bfloat16(v.x), h1 = __float2bfloat16(v.y);
    __nv_bfloat16 h2 = __float2bfloat16(v.z), h3 = __float2bfloat16(v.w);
    uint2 H, L;
    H.x = (uint32_t)__bfloat16_as_ushort(h0) | ((uint32_t)__bfloat16_as_ushort(h1) << 16);
    H.y = (uint32_t)__bfloat16_as_ushort(h2) | ((uint32_t)__bfloat16_as_ushort(h3) << 16);
    L.x = packbf(v.x - __bfloat162float(h0), v.y - __bfloat162float(h1));
    L.y = packbf(v.z - __bfloat162float(h2), v.w - __bfloat162float(h3));
    hi[i] = H;
    lo[i] = L;
}

// ===========================================================================
// Fused QKV GEMM: [8192,3072] = A[8192,1024] @ Wqkv[3072,1024]^T
// mma.sync bf16, 3-product split. 128x128 block, BK=32, 8 warps,
// 2-stage cp.async, ldmatrix.x4 fragment loads (conflict-free on 80B stride).
// ===========================================================================
#define TILE_B 10240
#define STAGE_B (4 * TILE_B)
#define GEMM_SMEM (2 * STAGE_B)

__global__ __launch_bounds__(256, 1) void gemm_qkv_fused(
    const __nv_bfloat16* __restrict__ Ah, const __nv_bfloat16* __restrict__ Al,
    const __nv_bfloat16* __restrict__ Wh, const __nv_bfloat16* __restrict__ Wl,
    __nv_bfloat16* __restrict__ qh, __nv_bfloat16* __restrict__ ql,
    __nv_bfloat16* __restrict__ kh, __nv_bfloat16* __restrict__ kl,
    __nv_bfloat16* __restrict__ vh, __nv_bfloat16* __restrict__ vl) {
    extern __shared__ char smc[];
    const uint32_t sb = smem_u32(smc);

    const int tid = threadIdx.x;
    const int lane = tid & 31, wid = tid >> 5;
    const int bm = blockIdx.y << 7;
    const int bnG = blockIdx.x << 7;          // 0..2944 over fused N=3072
    const int wm = (wid & 1) * 64, wn = (wid >> 1) * 32;
    const int fm = lane >> 2;
    const int fkb = (lane & 3) * 4;
    const int grp = lane >> 3, li = lane & 7;

    float acc[4][4][4];
#pragma unroll
    for (int i = 0; i < 4; i++)
#pragma unroll
        for (int j = 0; j < 4; j++)
#pragma unroll
            for (int q = 0; q < 4; q++) acc[i][j][q] = 0.f;

    const int c0row = tid >> 2, c0k = (tid & 3) * 16;
    const int c1row = (tid + 256) >> 2, c1k = c0k;

#define ISSUE_STAGE(kt, p) do {                                                \
    uint32_t s0 = sb + (p) * STAGE_B;                                          \
    size_t a0 = (size_t)(bm + c0row) * 1024 + (size_t)(kt) * 32 + (c0k >> 1);  \
    size_t a1 = (size_t)(bm + c1row) * 1024 + (size_t)(kt) * 32 + (c0k >> 1);  \
    size_t b0 = (size_t)(bnG + c0row) * 1024 + (size_t)(kt) * 32 + (c0k >> 1); \
    size_t b1 = (size_t)(bnG + c1row) * 1024 + (size_t)(kt) * 32 + (c0k >> 1); \
    uint32_t d0 = (uint32_t)(c0row * 80 + c0k);                                \
    uint32_t d1 = (uint32_t)(c1row * 80 + c1k);                                \
    cp16(s0 + d0,              Ah + a0);  cp16(s0 + d1,              Ah + a1); \
    cp16(s0 + TILE_B + d0,     Al + a0);  cp16(s0 + TILE_B + d1,     Al + a1); \
    cp16(s0 + 2 * TILE_B + d0, Wh + b0);  cp16(s0 + 2 * TILE_B + d1, Wh + b1); \
    cp16(s0 + 3 * TILE_B + d0, Wl + b0);  cp16(s0 + 3 * TILE_B + d1, Wl + b1); \
    CP_COMMIT();                                                               \
} while (0)

    ISSUE_STAGE(0, 0);

    for (int kt = 0; kt < 32; kt++) {
        const int p = kt & 1;
        if (kt < 31) {
            ISSUE_STAGE(kt + 1, p ^ 1);
            CP_WAIT(1);
        } else {
            CP_WAIT(0);
        }
        __syncthreads();

        const uint32_t st = sb + p * STAGE_B;
#pragma unroll
        for (int k16o = 0; k16o < 64; k16o += 32) {
            uint32_t ah[4][4], al[4][4], bh[2][4], bl[2][4];
            const uint32_t akb = (uint32_t)(k16o + ((grp >> 1) << 4));
            const uint32_t bkb = (uint32_t)(k16o + ((grp & 1) << 4));
#pragma unroll
            for (int np = 0; np < 2; np++) {
                uint32_t nrow = (uint32_t)(wn + np * 16 + ((grp >> 1) << 3) + li);
                LDMX4(bh[np], st + 2 * TILE_B + nrow * 80 + bkb);
                LDMX4(bl[np], st + 3 * TILE_B + nrow * 80 + bkb);
            }
#pragma unroll
            for (int mt = 0; mt < 4; mt++) {
                uint32_t arow = (uint32_t)(wm + mt * 16 + ((grp & 1) << 3) + li);
                LDMX4(ah[mt], st + arow * 80 + akb);
                LDMX4(al[mt], st + TILE_B + arow * 80 + akb);
            }
#pragma unroll
            for (int mt = 0; mt < 4; mt++)
#pragma unroll
                for (int nt = 0; nt < 4; nt++)
                    MMA_B2(acc[mt][nt], ah[mt], bh[nt >> 1][(nt & 1) * 2],
                           bh[nt >> 1][(nt & 1) * 2 + 1]);
#pragma unroll
            for (int mt = 0; mt < 4; mt++)
#pragma unroll
                for (int nt = 0; nt < 4; nt++)
                    MMA_B2(acc[mt][nt], ah[mt], bl[nt >> 1][(nt & 1) * 2],
                           bl[nt >> 1][(nt & 1) * 2 + 1]);
#pragma unroll
            for (int mt = 0; mt < 4; mt++)
#pragma unroll
                for (int nt = 0; nt < 4; nt++)
                    MMA_B2(acc[mt][nt], al[mt], bh[nt >> 1][(nt & 1) * 2],
                           bh[nt >> 1][(nt & 1) * 2 + 1]);
        }
        __syncthreads();
    }

    // Epilogue: select output array by N-segment, split acc -> bf16 hi/lo
    const int which = bnG >> 10;
    const int nloc = bnG & 1023;
    __nv_bfloat16* Ch = (which == 0) ? qh : (which == 1) ? kh : vh;
    __nv_bfloat16* Cl = (which == 0) ? ql : (which == 1) ? kl : vl;

#pragma unroll
    for (int mt = 0; mt < 4; mt++) {
        size_t m0 = (size_t)(bm + wm + mt * 16 + fm);
#pragma unroll
        for (int nt = 0; nt < 4; nt++) {
            size_t n0 = (size_t)(nloc + wn + nt * 8 + (fkb >> 1));
            float c0 = acc[mt][nt][0], c1 = acc[mt][nt][1];
            float c2 = acc[mt][nt][2], c3 = acc[mt][nt][3];
            __nv_bfloat16 h0 = __float2bfloat16(c0), h1 = __float2bfloat16(c1);
            __nv_bfloat16 h2 = __float2bfloat16(c2), h3 = __float2bfloat16(c3);
            uint32_t ph01 = (uint32_t)__bfloat16_as_ushort(h0) |
                            ((uint32_t)__bfloat16_as_ushort(h1) << 16);
            uint32_t ph23 = (uint32_t)__bfloat16_as_ushort(h2) |
                            ((uint32_t)__bfloat16_as_ushort(h3) << 16);
            uint32_t pl01 = packbf(c0 - __bfloat162float(h0), c1 - __bfloat162float(h1));
            uint32_t pl23 = packbf(c2 - __bfloat162float(h2), c3 - __bfloat162float(h3));
            *(uint32_t*)((char*)Ch + (m0 * 1024 + n0) * 2) = ph01;
            *(uint32_t*)((char*)Cl + (m0 * 1024 + n0) * 2) = pl01;
            *(uint32_t*)((char*)Ch + ((m0 + 8) * 1024 + n0) * 2) = ph23;
            *(uint32_t*)((char*)Cl + ((m0 + 8) * 1024 + n0) * 2) = pl23;
        }
    }
}

// ===========================================================================
// Tensor-core flash attention (unchanged from Round 4 — verified).
// ===========================================================================
#define A_QH 0
#define A_QL 17408
#define A_KB 34816
#define A_VB 104448
#define A_SS 174080
#define A_PH 191488
#define A_PL 200704
#define A_RM 209920
#define A_RL 210176
#define A_RA 210432
#define ATTN_SMEM 210688
#define KV_STRIDE 34816

__global__ __launch_bounds__(256, 1) void attn_tc(const float* __restrict__ mask,
                                                  float* __restrict__ out) {
    extern __shared__ char smc[];
    const uint32_t sb = smem_u32(smc);

    const int tid = threadIdx.x;
    const int lane = tid & 31, wid = tid >> 5;
    const int qt = blockIdx.x, h = blockIdx.y, b = blockIdx.z;
    const int wm = (wid & 3) * 16;
    const int wnS = (wid >> 2) * 32;
    const int wnV = (wid >> 2) * 64;
    const int fm = lane >> 2;

    const size_t bh_off = (size_t)b * TSEQ * DMOD + (size_t)h * DH;
    const __nv_bfloat16* Qh = g_Qh + bh_off;
    const __nv_bfloat16* Ql = g_Ql + bh_off;
    const __nv_bfloat16* Kh = g_Kh + bh_off;
    const __nv_bfloat16* Kl = g_Kl + bh_off;
    const __nv_bfloat16* Vh = g_Vh + bh_off;
    const __nv_bfloat16* Vl = g_Vl + bh_off;

    const int kt0 = (qt == 15) ? 0 : qt;

    for (int c = tid; c < 1024; c += 256) {
        int r = c >> 4, o = c & 15;
        uint32_t d = (uint32_t)(r * 272 + o * 16);
        size_t g = (size_t)(qt * 64 + r) * DMOD + o * 8;
        cp16(sb + A_QH + d, Qh + g);
        cp16(sb + A_QL + d, Ql + g);
    }

#define ISSUE_KV(kt_, s_) do {                                           \
    uint32_t kst = sb + A_KB + (uint32_t)(s_) * KV_STRIDE;               \
    uint32_t vst = sb + A_VB + (uint32_t)(s_) * KV_STRIDE;               \
    size_t roff = (size_t)(kt_) * 64 * DMOD;                             \
    for (int c = tid; c < 1024; c += 256) {                              \
        int r = c >> 4, o = c & 15;                                      \
        uint32_t d = (uint32_t)(r * 272 + o * 16);                       \
        size_t g = roff + (size_t)r * DMOD + o * 8;                      \
        cp16(kst + d,         Kh + g);                                   \
        cp16(kst + 17408 + d, Kl + g);                                   \
        cp16(vst + d,         Vh + g);                                   \
        cp16(vst + 17408 + d, Vl + g);                                   \
    }                                                                    \
} while (0)

    ISSUE_KV(kt0, 0);
    CP_COMMIT();
    ISSUE_KV(kt0 + 1, 1);
    CP_COMMIT();

    float* rowm = (float*)(smc + A_RM);
    float* rowl = (float*)(smc + A_RL);
    float* rowa = (float*)(smc + A_RA);
    if (tid < 64) { rowm[tid] = -1e30f; rowl[tid] = 0.f; }

    float acc_o[8][4];
#pragma unroll
    for (int j = 0; j < 8; j++)
#pragma unroll
        for (int q = 0; q < 4; q++) acc_o[j][q] = 0.f;

    const int grp = lane >> 3, li = lane & 7;

    for (int kt = kt0; kt < 16; kt++) {
        const int p = (kt - kt0) & 1;
        if (kt == 15) { CP_WAIT(0); } else { CP_WAIT(1); }
        __syncthreads();

        const uint32_t kst = sb + A_KB + (uint32_t)p * KV_STRIDE;
        const uint32_t vst = sb + A_VB + (uint32_t)p * KV_STRIDE;

        float sacc[4][4];
#pragma unroll
        for (int j = 0; j < 4; j++)
#pragma unroll
            for (int q = 0; q < 4; q++) sacc[j][q] = 0.f;

#pragma unroll
        for (int ks = 0; ks < 8; ks++) {
            uint32_t ah[4], al[4];
            {
                uint32_t arow = (uint32_t)(wm + ((grp & 1) << 3) + li);
                uint32_t akb = (uint32_t)(ks * 32 + ((grp >> 1) << 4));
                LDMX4(ah, sb + A_QH + arow * 272 + akb);
                LDMX4(al, sb + A_QL + arow * 272 + akb);
            }
            uint32_t bh[2][4], bl[2][4];
#pragma unroll
            for (int j2 = 0; j2 < 2; j2++) {
                uint32_t nrow = (uint32_t)(wnS + j2 * 16 + ((grp >> 1) << 3) + li);
                uint32_t kb = (uint32_t)(ks * 32 + ((grp & 1) << 4));
                LDMX4(bh[j2], kst + nrow * 272 + kb);
                LDMX4(bl[j2], kst + 17408 + nrow * 272 + kb);
            }
#pragma unroll
            for (int j = 0; j < 4; j++)
                MMA_B2(sacc[j], ah, bh[j >> 1][(j & 1) * 2], bh[j >> 1][(j & 1) * 2 + 1]);
#pragma unroll
            for (int j = 0; j < 4; j++)
                MMA_B2(sacc[j], ah, bl[j >> 1][(j & 1) * 2], bl[j >> 1][(j & 1) * 2 + 1]);
#pragma unroll
            for (int j = 0; j < 4; j++)
                MMA_B2(sacc[j], al, bh[j >> 1][(j & 1) * 2], bh[j >> 1][(j & 1) * 2 + 1]);
        }

        {
            const int r0 = wm + fm;
            const int qg0 = qt * 64 + r0, qg1 = qg0 + 8;
#pragma unroll
            for (int j = 0; j < 4; j++) {
                int col = wnS + 8 * j + 2 * (lane & 3);
                int kg = kt * 64 + col;
                float2 v01, v23;
                v01.x = sacc[j][0] * SCALE + ((kg     <= qg0) ? -10000.f : 0.f);
                v01.y = sacc[j][1] * SCALE + ((kg + 1 <= qg0) ? -10000.f : 0.f);
                v23.x = sacc[j][2] * SCALE + ((kg     <= qg1) ? -10000.f : 0.f);
                v23.y = sacc[j][3] * SCALE + ((kg + 1 <= qg1) ? -10000.f : 0.f);
                *(float2*)(smc + A_SS + (size_t)r0 * 272 + col * 4) = v01;
                *(float2*)(smc + A_SS + (size_t)(r0 + 8) * 272 + col * 4) = v23;
            }
        }
        __syncthreads();

        {
            const int row = tid >> 2, q = tid & 3;
            float* srow = (float*)(smc + A_SS + (size_t)row * 272) + (q << 4);
            float4 v0 = *(float4*)&srow[0];
            float4 v1 = *(float4*)&srow[4];
            float4 v2 = *(float4*)&srow[8];
            float4 v3 = *(float4*)&srow[12];
            float mloc = fmaxf(
                fmaxf(fmaxf(fmaxf(v0.x, v0.y), fmaxf(v0.z, v0.w)),
                      fmaxf(fmaxf(v1.x, v1.y), fmaxf(v1.z, v1.w))),
                fmaxf(fmaxf(fmaxf(v2.x, v2.y), fmaxf(v2.z, v2.w)),
                      fmaxf(fmaxf(v3.x, v3.y), fmaxf(v3.z, v3.w))));
            mloc = fmaxf(mloc, __shfl_xor_sync(0xffffffffu, mloc, 1));
            mloc = fmaxf(mloc, __shfl_xor_sync(0xffffffffu, mloc, 2));
            float mold = rowm[row];
            float mnew = fmaxf(mold, mloc);
            float alpha = __expf(mold - mnew);
            v0.x = __expf(v0.x - mnew); v0.y = __expf(v0.y - mnew);
            v0.z = __expf(v0.z - mnew); v0.w = __expf(v0.w - mnew);
            v1.x = __expf(v1.x - mnew); v1.y = __expf(v1.y - mnew);
            v1.z = __expf(v1.z - mnew); v1.w = __expf(v1.w - mnew);
            v2.x = __expf(v2.x - mnew); v2.y = __expf(v2.y - mnew);
            v2.z = __expf(v2.z - mnew); v2.w = __expf(v2.w - mnew);
            v3.x = __expf(v3.x - mnew); v3.y = __expf(v3.y - mnew);
            v3.z = __expf(v3.z - mnew); v3.w = __expf(v3.w - mnew);

            uint32_t* phr = (uint32_t*)(smc + A_PH + (size_t)row * 144) + (q << 3);
            uint32_t* plr = (uint32_t*)(smc + A_PL + (size_t)row * 144) + (q << 3);
            const float4 vv[4] = {v0, v1, v2, v3};
#pragma unroll
            for (int u = 0; u < 4; u++) {
                float a0 = vv[u].x, a1 = vv[u].y, a2 = vv[u].z, a3 = vv[u].w;
                __nv_bfloat16 h0 = __float2bfloat16(a0), h1 = __float2bfloat16(a1);
                __nv_bfloat16 h2 = __float2bfloat16(a2), h3 = __float2bfloat16(a3);
                phr[2 * u]     = (uint32_t)__bfloat16_as_ushort(h0) |
                                 ((uint32_t)__bfloat16_as_ushort(h1) << 16);
                phr[2 * u + 1] = (uint32_t)__bfloat16_as_ushort(h2) |
                                 ((uint32_t)__bfloat16_as_ushort(h3) << 16);
                plr[2 * u]     = packbf(a0 - __bfloat162float(h0), a1 - __bfloat162float(h1));
                plr[2 * u + 1] = packbf(a2 - __bfloat162float(h2), a3 - __bfloat162float(h3));
            }

            float ssum = (v0.x + v0.y + v0.z + v0.w) + (v1.x + v1.y + v1.z + v1.w) +
                         (v2.x + v2.y + v2.z + v2.w) + (v3.x + v3.y + v3.z + v3.w);
            ssum += __shfl_xor_sync(0xffffffffu, ssum, 1);
            ssum += __shfl_xor_sync(0xffffffffu, ssum, 2);
            if (q == 0) {
                rowl[row] = rowl[row] * alpha + ssum;
                rowm[row] = mnew;
                rowa[row] = alpha;
            }
        }
        __syncthreads();

        {
            float al0 = rowa[wm + fm], al1 = rowa[wm + fm + 8];
#pragma unroll
            for (int j = 0; j < 8; j++) {
                acc_o[j][0] *= al0; acc_o[j][1] *= al0;
                acc_o[j][2] *= al1; acc_o[j][3] *= al1;
            }
#pragma unroll
            for (int ks = 0; ks < 4; ks++) {
                uint32_t ph[4], pl[4];
                {
                    uint32_t arow = (uint32_t)(wm + ((grp & 1) << 3) + li);
                    uint32_t akb = (uint32_t)(ks * 32 + ((grp >> 1) << 4));
                    LDMX4(ph, sb + A_PH + arow * 144 + akb);
                    LDMX4(pl, sb + A_PL + arow * 144 + akb);
                }
#pragma unroll
                for (int j2 = 0; j2 < 4; j2++) {
                    uint32_t bvh[4], bvl[4];
                    uint32_t krow = (uint32_t)(ks * 16 + ((grp & 1) << 3) + li);
                    uint32_t nb = (uint32_t)((wnV + 16 * j2 + ((grp >> 1) << 3)) * 2);
                    LDMX4T(bvh, vst + krow * 272 + nb);
                    LDMX4T(bvl, vst + 17408 + krow * 272 + nb);
#pragma unroll
                    for (int jj = 0; jj < 2; jj++) {
                        int j = 2 * j2 + jj;
                        MMA_B2(acc_o[j], ph, bvh[jj * 2], bvh[jj * 2 + 1]);
                        MMA_B2(acc_o[j], ph, bvl[jj * 2], bvl[jj * 2 + 1]);
                        MMA_B2(acc_o[j], pl, bvh[jj * 2], bvh[jj * 2 + 1]);
                    }
                }
            }
        }
        __syncthreads();

        if (kt + 2 <= 15) {
            ISSUE_KV(kt + 2, p);
            CP_COMMIT();
        }
    }

    {
        const int r0 = wm + fm;
        const int grow0 = b * TSEQ + qt * 64 + r0;
        float scl0 = (1.f / rowl[r0]) * mask[(size_t)b * TSEQ + qt * 64 + r0];
        float scl1 = (1.f / rowl[r0 + 8]) * mask[(size_t)b * TSEQ + qt * 64 + r0 + 8];
#pragma unroll
        for (int j = 0; j < 8; j++) {
            int col = h * DH + wnV + j * 8 + 2 * (lane & 3);
            float2 w0 = {acc_o[j][0] * scl0, acc_o[j][1] * scl0};
            float2 w1 = {acc_o[j][2] * scl1, acc_o[j][3] * scl1};
            *(float2*)&out[(size_t)grow0 * DMOD + col] = w0;
            *(float2*)&out[(size_t)(grow0 + 8) * DMOD + col] = w1;
        }
    }
}

extern "C" void kernel_launch(void* const* d_in, const int* in_sizes, int n_in,
                              void* d_out, int out_size) {
    const float* x    = (const float*)d_in[0];
    const float* mask = (const float*)d_in[1];
    const float* Wq   = (const float*)d_in[2];
    const float* Wk   = (const float*)d_in[3];
    const float* Wv   = (const float*)d_in[4];
    float* out = (float*)d_out;

    __nv_bfloat16 *xh, *xl, *wh, *wl, *qh, *ql, *kh, *kl, *vh, *vl;
    cudaGetSymbolAddress((void**)&xh, g_Xh);
    cudaGetSymbolAddress((void**)&xl, g_Xl);
    cudaGetSymbolAddress((void**)&wh, g_Wh);
    cudaGetSymbolAddress((void**)&wl, g_Wl);
    cudaGetSymbolAddress((void**)&qh, g_Qh);
    cudaGetSymbolAddress((void**)&ql, g_Ql);
    cudaGetSymbolAddress((void**)&kh, g_Kh);
    cudaGetSymbolAddress((void**)&kl, g_Kl);
    cudaGetSymbolAddress((void**)&vh, g_Vh);
    cudaGetSymbolAddress((void**)&vl, g_Vl);

    cudaFuncSetAttribute(gemm_qkv_fused, cudaFuncAttributeMaxDynamicSharedMemorySize,
                         GEMM_SMEM);
    cudaFuncSetAttribute(attn_tc, cudaFuncAttributeMaxDynamicSharedMemorySize,
                         ATTN_SMEM);

    const int xn4 = BATCH * TSEQ * DMOD / 4;
    const int wn4 = DMOD * DMOD / 4;
    split_bf16<<<xn4 / 256, 256>>>((const float4*)x, (uint2*)xh, (uint2*)xl);
    split_bf16<<<wn4 / 256, 256>>>((const float4*)Wq, (uint2*)wh, (uint2*)wl);
    split_bf16<<<wn4 / 256, 256>>>((const float4*)Wk,
                                   (uint2*)(wh + DMOD * DMOD),
                                   (uint2*)(wl + DMOD * DMOD));
    split_bf16<<<wn4 / 256, 256>>>((const float4*)Wv,
                                   (uint2*)(wh + 2 * DMOD * DMOD),
                                   (uint2*)(wl + 2 * DMOD * DMOD));

    dim3 ggrid(3 * DMOD / 128, (BATCH * TSEQ) / 128);
    gemm_qkv_fused<<<ggrid, 256, GEMM_SMEM>>>(xh, xl, wh, wl,
                                              qh, ql, kh, kl, vh, vl);

    dim3 agrid(TSEQ / 64, NH, BATCH);
    attn_tc<<<agrid, 256, ATTN_SMEM>>>(mask, out);
}

// round 6
// speedup vs baseline: 2.8079x; 1.2017x over previous
#include <cuda_runtime.h>
#include <cuda_bf16.h>
#include <cuda_fp16.h>
#include <cstdint>

#define BATCH 8
#define TSEQ 1024
#define DMOD 1024
#define NH 8
#define DH 128
#define SCALE 0.08838834764831845f

// Scratch (device globals: allocation-free).
__device__ __half g_Xh[BATCH * TSEQ * DMOD];
__device__ __half g_Wh[3 * DMOD * DMOD];
__device__ __half g_Wl[3 * DMOD * DMOD];
__device__ __nv_bfloat16 g_Qh[BATCH * TSEQ * DMOD];
__device__ __nv_bfloat16 g_Ql[BATCH * TSEQ * DMOD];
__device__ __nv_bfloat16 g_Kh[BATCH * TSEQ * DMOD];
__device__ __nv_bfloat16 g_Kl[BATCH * TSEQ * DMOD];
__device__ __nv_bfloat16 g_Vh[BATCH * TSEQ * DMOD];
__device__ __nv_bfloat16 g_Vl[BATCH * TSEQ * DMOD];

__device__ __forceinline__ uint32_t smem_u32(const void* p) {
    uint32_t a;
    asm("{ .reg .u64 t; cvta.to.shared.u64 t, %1; cvt.u32.u64 %0, t; }"
        : "=r"(a) : "l"(p));
    return a;
}
__device__ __forceinline__ void cp16(uint32_t dst, const void* src) {
    asm volatile("cp.async.cg.shared.global [%0], [%1], 16;"
                 :: "r"(dst), "l"(src) : "memory");
}
#define CP_COMMIT() asm volatile("cp.async.commit_group;" ::: "memory")
#define CP_WAIT(n)  asm volatile("cp.async.wait_group %0;" :: "n"(n) : "memory")

// bf16 mma (attention)
#define MMA_B2(c, a, b0_, b1_) \
    asm volatile("mma.sync.aligned.m16n8k16.row.col.f32.bf16.bf16.f32 " \
                 "{%0,%1,%2,%3}, {%4,%5,%6,%7}, {%8,%9}, {%0,%1,%2,%3};" \
                 : "+f"((c)[0]), "+f"((c)[1]), "+f"((c)[2]), "+f"((c)[3]) \
                 : "r"((a)[0]), "r"((a)[1]), "r"((a)[2]), "r"((a)[3]), \
                   "r"(b0_), "r"(b1_))
// fp16 mma (GEMM)
#define MMA_F16(c, a, b0_, b1_) \
    asm volatile("mma.sync.aligned.m16n8k16.row.col.f32.f16.f16.f32 " \
                 "{%0,%1,%2,%3}, {%4,%5,%6,%7}, {%8,%9}, {%0,%1,%2,%3};" \
                 : "+f"((c)[0]), "+f"((c)[1]), "+f"((c)[2]), "+f"((c)[3]) \
                 : "r"((a)[0]), "r"((a)[1]), "r"((a)[2]), "r"((a)[3]), \
                   "r"(b0_), "r"(b1_))

#define LDMX4(r, addr) \
    asm volatile("ldmatrix.sync.aligned.m8n8.x4.shared.b16 {%0,%1,%2,%3}, [%4];" \
                 : "=r"((r)[0]), "=r"((r)[1]), "=r"((r)[2]), "=r"((r)[3]) : "r"(addr))
#define LDMX4T(r, addr) \
    asm volatile("ldmatrix.sync.aligned.m8n8.x4.trans.shared.b16 {%0,%1,%2,%3}, [%4];" \
                 : "=r"((r)[0]), "=r"((r)[1]), "=r"((r)[2]), "=r"((r)[3]) : "r"(addr))

__device__ __forceinline__ uint32_t hmul2u(uint32_t a, uint32_t b) {
    uint32_t d;
    asm("mul.rn.f16x2 %0, %1, %2;" : "=r"(d) : "r"(a), "r"(b));
    return d;
}

__device__ __forceinline__ uint32_t packbf(float x, float y) {
    __nv_bfloat16 hx = __float2bfloat16(x), hy = __float2bfloat16(y);
    return (uint32_t)__bfloat16_as_ushort(hx) |
           ((uint32_t)__bfloat16_as_ushort(hy) << 16);
}

// ===========================================================================
// Split kernels
// ===========================================================================
__global__ __launch_bounds__(256) void split_x_h(const float4* __restrict__ src,
                                                 uint2* __restrict__ xh) {
    int i = blockIdx.x * 256 + threadIdx.x;
    float4 v = src[i];
    __half2 p01 = __floats2half2_rn(v.x, v.y);
    __half2 p23 = __floats2half2_rn(v.z, v.w);
    uint2 H;
    H.x = *(uint32_t*)&p01;
    H.y = *(uint32_t*)&p23;
    xh[i] = H;
}

__global__ __launch_bounds__(256) void split_w_h(const float4* __restrict__ src,
                                                 uint2* __restrict__ wh,
                                                 uint2* __restrict__ wl) {
    int i = blockIdx.x * 256 + threadIdx.x;
    float4 v = src[i];
    __half h0 = __float2half_rn(v.x), h1 = __float2half_rn(v.y);
    __half h2 = __float2half_rn(v.z), h3 = __float2half_rn(v.w);
    __half2 hp01 = __halves2half2(h0, h1), hp23 = __halves2half2(h2, h3);
    float r0 = (v.x - __half2float(h0)) * 2048.f;
    float r1 = (v.y - __half2float(h1)) * 2048.f;
    float r2 = (v.z - __half2float(h2)) * 2048.f;
    float r3 = (v.w - __half2float(h3)) * 2048.f;
    __half2 lp01 = __floats2half2_rn(r0, r1), lp23 = __floats2half2_rn(r2, r3);
    uint2 H, L;
    H.x = *(uint32_t*)&hp01; H.y = *(uint32_t*)&hp23;
    L.x = *(uint32_t*)&lp01; L.y = *(uint32_t*)&lp23;
    wh[i] = H;
    wl[i] = L;
}

// ===========================================================================
// Fused QKV GEMM: [8192,3072] = X[8192,1024] @ Wqkv[3072,1024]^T
// fp16 2-product scaled-residual: C = Xh*Wh + (Xh*2^-11)*Wl.
// 128x128 block, BK=32, 8 warps, 2-stage cp.async, ldmatrix fragments.
// ===========================================================================
#define GTILE 10240
#define GSTAGE (3 * GTILE)
#define GEMM_SMEM (2 * GSTAGE)   // 61440 bytes

__global__ __launch_bounds__(256, 1) void gemm_qkv_f16(
    const __half* __restrict__ Xh,
    const __half* __restrict__ Wh, const __half* __restrict__ Wl,
    __nv_bfloat16* __restrict__ qh, __nv_bfloat16* __restrict__ ql,
    __nv_bfloat16* __restrict__ kh, __nv_bfloat16* __restrict__ kl,
    __nv_bfloat16* __restrict__ vh, __nv_bfloat16* __restrict__ vl) {
    extern __shared__ char smc[];
    const uint32_t sb = smem_u32(smc);

    const int tid = threadIdx.x;
    const int lane = tid & 31, wid = tid >> 5;
    const int bm = blockIdx.y << 7;
    const int bnG = blockIdx.x << 7;
    const int wm = (wid & 1) * 64, wn = (wid >> 1) * 32;
    const int fm = lane >> 2;
    const int fkb = (lane & 3) * 4;
    const int grp = lane >> 3, li = lane & 7;
    const uint32_t SC11 = 0x10001000u;   // fp16x2 {2^-11, 2^-11}

    float acc[4][4][4];
#pragma unroll
    for (int i = 0; i < 4; i++)
#pragma unroll
        for (int j = 0; j < 4; j++)
#pragma unroll
            for (int q = 0; q < 4; q++) acc[i][j][q] = 0.f;

    const int c0row = tid >> 2;
    const int c1row = c0row + 64;
    const int ce = (tid & 3) * 8;                 // element offset in row
    const uint32_t d0 = (uint32_t)(c0row * 80 + (tid & 3) * 16);
    const uint32_t d1 = (uint32_t)(c1row * 80 + (tid & 3) * 16);

#define ISSUE_STAGE(kt, p) do {                                        \
    uint32_t s0 = sb + (p) * GSTAGE;                                   \
    size_t a0 = (size_t)(bm + c0row) * 1024 + (size_t)(kt) * 32 + ce;  \
    size_t a1 = (size_t)(bm + c1row) * 1024 + (size_t)(kt) * 32 + ce;  \
    size_t b0 = (size_t)(bnG + c0row) * 1024 + (size_t)(kt) * 32 + ce; \
    size_t b1 = (size_t)(bnG + c1row) * 1024 + (size_t)(kt) * 32 + ce; \
    cp16(s0 + d0,             Xh + a0);  cp16(s0 + d1,             Xh + a1); \
    cp16(s0 + GTILE + d0,     Wh + b0);  cp16(s0 + GTILE + d1,     Wh + b1); \
    cp16(s0 + 2 * GTILE + d0, Wl + b0);  cp16(s0 + 2 * GTILE + d1, Wl + b1); \
    CP_COMMIT();                                                       \
} while (0)

    ISSUE_STAGE(0, 0);

    for (int kt = 0; kt < 32; kt++) {
        const int p = kt & 1;
        if (kt < 31) {
            ISSUE_STAGE(kt + 1, p ^ 1);
            CP_WAIT(1);
        } else {
            CP_WAIT(0);
        }
        __syncthreads();

        const uint32_t st = sb + p * GSTAGE;
#pragma unroll
        for (int k16o = 0; k16o < 64; k16o += 32) {
            uint32_t ah[4][4], as[4][4], bh[2][4], bl[2][4];
            const uint32_t akb = (uint32_t)(k16o + ((grp >> 1) << 4));
            const uint32_t bkb = (uint32_t)(k16o + ((grp & 1) << 4));
#pragma unroll
            for (int np = 0; np < 2; np++) {
                uint32_t nrow = (uint32_t)(wn + np * 16 + ((grp >> 1) << 3) + li);
                LDMX4(bh[np], st + GTILE + nrow * 80 + bkb);
                LDMX4(bl[np], st + 2 * GTILE + nrow * 80 + bkb);
            }
#pragma unroll
            for (int mt = 0; mt < 4; mt++) {
                uint32_t arow = (uint32_t)(wm + mt * 16 + ((grp & 1) << 3) + li);
                LDMX4(ah[mt], st + arow * 80 + akb);
            }
            // hi*hi
#pragma unroll
            for (int mt = 0; mt < 4; mt++)
#pragma unroll
                for (int nt = 0; nt < 4; nt++)
                    MMA_F16(acc[mt][nt], ah[mt], bh[nt >> 1][(nt & 1) * 2],
                            bh[nt >> 1][(nt & 1) * 2 + 1]);
            // scaled-hi * residual
#pragma unroll
            for (int mt = 0; mt < 4; mt++)
#pragma unroll
                for (int r = 0; r < 4; r++) as[mt][r] = hmul2u(ah[mt][r], SC11);
#pragma unroll
            for (int mt = 0; mt < 4; mt++)
#pragma unroll
                for (int nt = 0; nt < 4; nt++)
                    MMA_F16(acc[mt][nt], as[mt], bl[nt >> 1][(nt & 1) * 2],
                            bl[nt >> 1][(nt & 1) * 2 + 1]);
        }
        __syncthreads();
    }

    const int which = bnG >> 10;
    const int nloc = bnG & 1023;
    __nv_bfloat16* Ch = (which == 0) ? qh : (which == 1) ? kh : vh;
    __nv_bfloat16* Cl = (which == 0) ? ql : (which == 1) ? kl : vl;

#pragma unroll
    for (int mt = 0; mt < 4; mt++) {
        size_t m0 = (size_t)(bm + wm + mt * 16 + fm);
#pragma unroll
        for (int nt = 0; nt < 4; nt++) {
            size_t n0 = (size_t)(nloc + wn + nt * 8 + (fkb >> 1));
            float c0 = acc[mt][nt][0], c1 = acc[mt][nt][1];
            float c2 = acc[mt][nt][2], c3 = acc[mt][nt][3];
            __nv_bfloat16 h0 = __float2bfloat16(c0), h1 = __float2bfloat16(c1);
            __nv_bfloat16 h2 = __float2bfloat16(c2), h3 = __float2bfloat16(c3);
            uint32_t ph01 = (uint32_t)__bfloat16_as_ushort(h0) |
                            ((uint32_t)__bfloat16_as_ushort(h1) << 16);
            uint32_t ph23 = (uint32_t)__bfloat16_as_ushort(h2) |
                            ((uint32_t)__bfloat16_as_ushort(h3) << 16);
            uint32_t pl01 = packbf(c0 - __bfloat162float(h0), c1 - __bfloat162float(h1));
            uint32_t pl23 = packbf(c2 - __bfloat162float(h2), c3 - __bfloat162float(h3));
            *(uint32_t*)((char*)Ch + (m0 * 1024 + n0) * 2) = ph01;
            *(uint32_t*)((char*)Cl + (m0 * 1024 + n0) * 2) = pl01;
            *(uint32_t*)((char*)Ch + ((m0 + 8) * 1024 + n0) * 2) = ph23;
            *(uint32_t*)((char*)Cl + ((m0 + 8) * 1024 + n0) * 2) = pl23;
        }
    }
}

// ===========================================================================
// Tensor-core flash attention (unchanged — verified).
// ===========================================================================
#define A_QH 0
#define A_QL 17408
#define A_KB 34816
#define A_VB 104448
#define A_SS 174080
#define A_PH 191488
#define A_PL 200704
#define A_RM 209920
#define A_RL 210176
#define A_RA 210432
#define ATTN_SMEM 210688
#define KV_STRIDE 34816

__global__ __launch_bounds__(256, 1) void attn_tc(const float* __restrict__ mask,
                                                  float* __restrict__ out) {
    extern __shared__ char smc[];
    const uint32_t sb = smem_u32(smc);

    const int tid = threadIdx.x;
    const int lane = tid & 31, wid = tid >> 5;
    const int qt = blockIdx.x, h = blockIdx.y, b = blockIdx.z;
    const int wm = (wid & 3) * 16;
    const int wnS = (wid >> 2) * 32;
    const int wnV = (wid >> 2) * 64;
    const int fm = lane >> 2;

    const size_t bh_off = (size_t)b * TSEQ * DMOD + (size_t)h * DH;
    const __nv_bfloat16* Qh = g_Qh + bh_off;
    const __nv_bfloat16* Ql = g_Ql + bh_off;
    const __nv_bfloat16* Kh = g_Kh + bh_off;
    const __nv_bfloat16* Kl = g_Kl + bh_off;
    const __nv_bfloat16* Vh = g_Vh + bh_off;
    const __nv_bfloat16* Vl = g_Vl + bh_off;

    const int kt0 = (qt == 15) ? 0 : qt;

    for (int c = tid; c < 1024; c += 256) {
        int r = c >> 4, o = c & 15;
        uint32_t d = (uint32_t)(r * 272 + o * 16);
        size_t g = (size_t)(qt * 64 + r) * DMOD + o * 8;
        cp16(sb + A_QH + d, Qh + g);
        cp16(sb + A_QL + d, Ql + g);
    }

#define ISSUE_KV(kt_, s_) do {                                           \
    uint32_t kst = sb + A_KB + (uint32_t)(s_) * KV_STRIDE;               \
    uint32_t vst = sb + A_VB + (uint32_t)(s_) * KV_STRIDE;               \
    size_t roff = (size_t)(kt_) * 64 * DMOD;                             \
    for (int c = tid; c < 1024; c += 256) {                              \
        int r = c >> 4, o = c & 15;                                      \
        uint32_t d = (uint32_t)(r * 272 + o * 16);                       \
        size_t g = roff + (size_t)r * DMOD + o * 8;                      \
        cp16(kst + d,         Kh + g);                                   \
        cp16(kst + 17408 + d, Kl + g);                                   \
        cp16(vst + d,         Vh + g);                                   \
        cp16(vst + 17408 + d, Vl + g);                                   \
    }                                                                    \
} while (0)

    ISSUE_KV(kt0, 0);
    CP_COMMIT();
    ISSUE_KV(kt0 + 1, 1);
    CP_COMMIT();

    float* rowm = (float*)(smc + A_RM);
    float* rowl = (float*)(smc + A_RL);
    float* rowa = (float*)(smc + A_RA);
    if (tid < 64) { rowm[tid] = -1e30f; rowl[tid] = 0.f; }

    float acc_o[8][4];
#pragma unroll
    for (int j = 0; j < 8; j++)
#pragma unroll
        for (int q = 0; q < 4; q++) acc_o[j][q] = 0.f;

    const int grp = lane >> 3, li = lane & 7;

    for (int kt = kt0; kt < 16; kt++) {
        const int p = (kt - kt0) & 1;
        if (kt == 15) { CP_WAIT(0); } else { CP_WAIT(1); }
        __syncthreads();

        const uint32_t kst = sb + A_KB + (uint32_t)p * KV_STRIDE;
        const uint32_t vst = sb + A_VB + (uint32_t)p * KV_STRIDE;

        float sacc[4][4];
#pragma unroll
        for (int j = 0; j < 4; j++)
#pragma unroll
            for (int q = 0; q < 4; q++) sacc[j][q] = 0.f;

#pragma unroll
        for (int ks = 0; ks < 8; ks++) {
            uint32_t ah[4], al[4];
            {
                uint32_t arow = (uint32_t)(wm + ((grp & 1) << 3) + li);
                uint32_t akb = (uint32_t)(ks * 32 + ((grp >> 1) << 4));
                LDMX4(ah, sb + A_QH + arow * 272 + akb);
                LDMX4(al, sb + A_QL + arow * 272 + akb);
            }
            uint32_t bh[2][4], bl[2][4];
#pragma unroll
            for (int j2 = 0; j2 < 2; j2++) {
                uint32_t nrow = (uint32_t)(wnS + j2 * 16 + ((grp >> 1) << 3) + li);
                uint32_t kb = (uint32_t)(ks * 32 + ((grp & 1) << 4));
                LDMX4(bh[j2], kst + nrow * 272 + kb);
                LDMX4(bl[j2], kst + 17408 + nrow * 272 + kb);
            }
#pragma unroll
            for (int j = 0; j < 4; j++)
                MMA_B2(sacc[j], ah, bh[j >> 1][(j & 1) * 2], bh[j >> 1][(j & 1) * 2 + 1]);
#pragma unroll
            for (int j = 0; j < 4; j++)
                MMA_B2(sacc[j], ah, bl[j >> 1][(j & 1) * 2], bl[j >> 1][(j & 1) * 2 + 1]);
#pragma unroll
            for (int j = 0; j < 4; j++)
                MMA_B2(sacc[j], al, bh[j >> 1][(j & 1) * 2], bh[j >> 1][(j & 1) * 2 + 1]);
        }

        {
            const int r0 = wm + fm;
            const int qg0 = qt * 64 + r0, qg1 = qg0 + 8;
#pragma unroll
            for (int j = 0; j < 4; j++) {
                int col = wnS + 8 * j + 2 * (lane & 3);
                int kg = kt * 64 + col;
                float2 v01, v23;
                v01.x = sacc[j][0] * SCALE + ((kg     <= qg0) ? -10000.f : 0.f);
                v01.y = sacc[j][1] * SCALE + ((kg + 1 <= qg0) ? -10000.f : 0.f);
                v23.x = sacc[j][2] * SCALE + ((kg     <= qg1) ? -10000.f : 0.f);
                v23.y = sacc[j][3] * SCALE + ((kg + 1 <= qg1) ? -10000.f : 0.f);
                *(float2*)(smc + A_SS + (size_t)r0 * 272 + col * 4) = v01;
                *(float2*)(smc + A_SS + (size_t)(r0 + 8) * 272 + col * 4) = v23;
            }
        }
        __syncthreads();

        {
            const int row = tid >> 2, q = tid & 3;
            float* srow = (float*)(smc + A_SS + (size_t)row * 272) + (q << 4);
            float4 v0 = *(float4*)&srow[0];
            float4 v1 = *(float4*)&srow[4];
            float4 v2 = *(float4*)&srow[8];
            float4 v3 = *(float4*)&srow[12];
            float mloc = fmaxf(
                fmaxf(fmaxf(fmaxf(v0.x, v0.y), fmaxf(v0.z, v0.w)),
                      fmaxf(fmaxf(v1.x, v1.y), fmaxf(v1.z, v1.w))),
                fmaxf(fmaxf(fmaxf(v2.x, v2.y), fmaxf(v2.z, v2.w)),
                      fmaxf(fmaxf(v3.x, v3.y), fmaxf(v3.z, v3.w))));
            mloc = fmaxf(mloc, __shfl_xor_sync(0xffffffffu, mloc, 1));
            mloc = fmaxf(mloc, __shfl_xor_sync(0xffffffffu, mloc, 2));
            float mold = rowm[row];
            float mnew = fmaxf(mold, mloc);
            float alpha = __expf(mold - mnew);
            v0.x = __expf(v0.x - mnew); v0.y = __expf(v0.y - mnew);
            v0.z = __expf(v0.z - mnew); v0.w = __expf(v0.w - mnew);
            v1.x = __expf(v1.x - mnew); v1.y = __expf(v1.y - mnew);
            v1.z = __expf(v1.z - mnew); v1.w = __expf(v1.w - mnew);
            v2.x = __expf(v2.x - mnew); v2.y = __expf(v2.y - mnew);
            v2.z = __expf(v2.z - mnew); v2.w = __expf(v2.w - mnew);
            v3.x = __expf(v3.x - mnew); v3.y = __expf(v3.y - mnew);
            v3.z = __expf(v3.z - mnew); v3.w = __expf(v3.w - mnew);

            uint32_t* phr = (uint32_t*)(smc + A_PH + (size_t)row * 144) + (q << 3);
            uint32_t* plr = (uint32_t*)(smc + A_PL + (size_t)row * 144) + (q << 3);
            const float4 vv[4] = {v0, v1, v2, v3};
#pragma unroll
            for (int u = 0; u < 4; u++) {
                float a0 = vv[u].x, a1 = vv[u].y, a2 = vv[u].z, a3 = vv[u].w;
                __nv_bfloat16 h0 = __float2bfloat16(a0), h1 = __float2bfloat16(a1);
                __nv_bfloat16 h2 = __float2bfloat16(a2), h3 = __float2bfloat16(a3);
                phr[2 * u]     = (uint32_t)__bfloat16_as_ushort(h0) |
                                 ((uint32_t)__bfloat16_as_ushort(h1) << 16);
                phr[2 * u + 1] = (uint32_t)__bfloat16_as_ushort(h2) |
                                 ((uint32_t)__bfloat16_as_ushort(h3) << 16);
                plr[2 * u]     = packbf(a0 - __bfloat162float(h0), a1 - __bfloat162float(h1));
                plr[2 * u + 1] = packbf(a2 - __bfloat162float(h2), a3 - __bfloat162float(h3));
            }

            float ssum = (v0.x + v0.y + v0.z + v0.w) + (v1.x + v1.y + v1.z + v1.w) +
                         (v2.x + v2.y + v2.z + v2.w) + (v3.x + v3.y + v3.z + v3.w);
            ssum += __shfl_xor_sync(0xffffffffu, ssum, 1);
            ssum += __shfl_xor_sync(0xffffffffu, ssum, 2);
            if (q == 0) {
                rowl[row] = rowl[row] * alpha + ssum;
                rowm[row] = mnew;
                rowa[row] = alpha;
            }
        }
        __syncthreads();

        {
            float al0 = rowa[wm + fm], al1 = rowa[wm + fm + 8];
#pragma unroll
            for (int j = 0; j < 8; j++) {
                acc_o[j][0] *= al0; acc_o[j][1] *= al0;
                acc_o[j][2] *= al1; acc_o[j][3] *= al1;
            }
#pragma unroll
            for (int ks = 0; ks < 4; ks++) {
                uint32_t ph[4], pl[4];
                {
                    uint32_t arow = (uint32_t)(wm + ((grp & 1) << 3) + li);
                    uint32_t akb = (uint32_t)(ks * 32 + ((grp >> 1) << 4));
                    LDMX4(ph, sb + A_PH + arow * 144 + akb);
                    LDMX4(pl, sb + A_PL + arow * 144 + akb);
                }
#pragma unroll
                for (int j2 = 0; j2 < 4; j2++) {
                    uint32_t bvh[4], bvl[4];
                    uint32_t krow = (uint32_t)(ks * 16 + ((grp & 1) << 3) + li);
                    uint32_t nb = (uint32_t)((wnV + 16 * j2 + ((grp >> 1) << 3)) * 2);
                    LDMX4T(bvh, vst + krow * 272 + nb);
                    LDMX4T(bvl, vst + 17408 + krow * 272 + nb);
#pragma unroll
                    for (int jj = 0; jj < 2; jj++) {
                        int j = 2 * j2 + jj;
                        MMA_B2(acc_o[j], ph, bvh[jj * 2], bvh[jj * 2 + 1]);
                        MMA_B2(acc_o[j], ph, bvl[jj * 2], bvl[jj * 2 + 1]);
                        MMA_B2(acc_o[j], pl, bvh[jj * 2], bvh[jj * 2 + 1]);
                    }
                }
            }
        }
        __syncthreads();

        if (kt + 2 <= 15) {
            ISSUE_KV(kt + 2, p);
            CP_COMMIT();
        }
    }

    {
        const int r0 = wm + fm;
        const int grow0 = b * TSEQ + qt * 64 + r0;
        float scl0 = (1.f / rowl[r0]) * mask[(size_t)b * TSEQ + qt * 64 + r0];
        float scl1 = (1.f / rowl[r0 + 8]) * mask[(size_t)b * TSEQ + qt * 64 + r0 + 8];
#pragma unroll
        for (int j = 0; j < 8; j++) {
            int col = h * DH + wnV + j * 8 + 2 * (lane & 3);
            float2 w0 = {acc_o[j][0] * scl0, acc_o[j][1] * scl0};
            float2 w1 = {acc_o[j][2] * scl1, acc_o[j][3] * scl1};
            *(float2*)&out[(size_t)grow0 * DMOD + col] = w0;
            *(float2*)&out[(size_t)(grow0 + 8) * DMOD + col] = w1;
        }
    }
}

extern "C" void kernel_launch(void* const* d_in, const int* in_sizes, int n_in,
                              void* d_out, int out_size) {
    const float* x    = (const float*)d_in[0];
    const float* mask = (const float*)d_in[1];
    const float* Wq   = (const float*)d_in[2];
    const float* Wk   = (const float*)d_in[3];
    const float* Wv   = (const float*)d_in[4];
    float* out = (float*)d_out;

    __half *xh, *wh, *wl;
    __nv_bfloat16 *qh, *ql, *kh, *kl, *vh, *vl;
    cudaGetSymbolAddress((void**)&xh, g_Xh);
    cudaGetSymbolAddress((void**)&wh, g_Wh);
    cudaGetSymbolAddress((void**)&wl, g_Wl);
    cudaGetSymbolAddress((void**)&qh, g_Qh);
    cudaGetSymbolAddress((void**)&ql, g_Ql);
    cudaGetSymbolAddress((void**)&kh, g_Kh);
    cudaGetSymbolAddress((void**)&kl, g_Kl);
    cudaGetSymbolAddress((void**)&vh, g_Vh);
    cudaGetSymbolAddress((void**)&vl, g_Vl);

    cudaFuncSetAttribute(gemm_qkv_f16, cudaFuncAttributeMaxDynamicSharedMemorySize,
                         GEMM_SMEM);
    cudaFuncSetAttribute(attn_tc, cudaFuncAttributeMaxDynamicSharedMemorySize,
                         ATTN_SMEM);

    const int xn4 = BATCH * TSEQ * DMOD / 4;
    const int wn4 = DMOD * DMOD / 4;
    split_x_h<<<xn4 / 256, 256>>>((const float4*)x, (uint2*)xh);
    split_w_h<<<wn4 / 256, 256>>>((const float4*)Wq, (uint2*)wh, (uint2*)wl);
    split_w_h<<<wn4 / 256, 256>>>((const float4*)Wk,
                                  (uint2*)(wh + DMOD * DMOD),
                                  (uint2*)(wl + DMOD * DMOD));
    split_w_h<<<wn4 / 256, 256>>>((const float4*)Wv,
                                  (uint2*)(wh + 2 * DMOD * DMOD),
                                  (uint2*)(wl + 2 * DMOD * DMOD));

    dim3 ggrid(3 * DMOD / 128, (BATCH * TSEQ) / 128);
    gemm_qkv_f16<<<ggrid, 256, GEMM_SMEM>>>(xh, wh, wl, qh, ql, kh, kl, vh, vl);

    dim3 agrid(TSEQ / 64, NH, BATCH);
    attn_tc<<<agrid, 256, ATTN_SMEM>>>(mask, out);
}

// round 7
// speedup vs baseline: 3.1711x; 1.1293x over previous
#include <cuda_runtime.h>
#include <cuda_bf16.h>
#include <cuda_fp16.h>
#include <cstdint>

#define BATCH 8
#define TSEQ 1024
#define DMOD 1024
#define NH 8
#define DH 128
#define SCALE 0.08838834764831845f

// Scratch (device globals: allocation-free).
__device__ __half g_Xh[BATCH * TSEQ * DMOD];
__device__ __half g_Wh[3 * DMOD * DMOD];
__device__ __half g_Wl[3 * DMOD * DMOD];
__device__ __half g_Qh[BATCH * TSEQ * DMOD];
__device__ __half g_Kh[BATCH * TSEQ * DMOD];
__device__ __half g_Kl[BATCH * TSEQ * DMOD];
__device__ __half g_Vh[BATCH * TSEQ * DMOD];

__device__ __forceinline__ uint32_t smem_u32(const void* p) {
    uint32_t a;
    asm("{ .reg .u64 t; cvta.to.shared.u64 t, %1; cvt.u32.u64 %0, t; }"
        : "=r"(a) : "l"(p));
    return a;
}
__device__ __forceinline__ void cp16(uint32_t dst, const void* src) {
    asm volatile("cp.async.cg.shared.global [%0], [%1], 16;"
                 :: "r"(dst), "l"(src) : "memory");
}
#define CP_COMMIT() asm volatile("cp.async.commit_group;" ::: "memory")
#define CP_WAIT(n)  asm volatile("cp.async.wait_group %0;" :: "n"(n) : "memory")

#define MMA_F16(c, a, b0_, b1_) \
    asm volatile("mma.sync.aligned.m16n8k16.row.col.f32.f16.f16.f32 " \
                 "{%0,%1,%2,%3}, {%4,%5,%6,%7}, {%8,%9}, {%0,%1,%2,%3};" \
                 : "+f"((c)[0]), "+f"((c)[1]), "+f"((c)[2]), "+f"((c)[3]) \
                 : "r"((a)[0]), "r"((a)[1]), "r"((a)[2]), "r"((a)[3]), \
                   "r"(b0_), "r"(b1_))

#define LDMX4(r, addr) \
    asm volatile("ldmatrix.sync.aligned.m8n8.x4.shared.b16 {%0,%1,%2,%3}, [%4];" \
                 : "=r"((r)[0]), "=r"((r)[1]), "=r"((r)[2]), "=r"((r)[3]) : "r"(addr))
#define LDMX4T(r, addr) \
    asm volatile("ldmatrix.sync.aligned.m8n8.x4.trans.shared.b16 {%0,%1,%2,%3}, [%4];" \
                 : "=r"((r)[0]), "=r"((r)[1]), "=r"((r)[2]), "=r"((r)[3]) : "r"(addr))

__device__ __forceinline__ uint32_t hmul2u(uint32_t a, uint32_t b) {
    uint32_t d;
    asm("mul.rn.f16x2 %0, %1, %2;" : "=r"(d) : "r"(a), "r"(b));
    return d;
}
__device__ __forceinline__ uint32_t packh2(__half x, __half y) {
    __half2 h = __halves2half2(x, y);
    return *(uint32_t*)&h;
}

// ===========================================================================
// Split kernels
// ===========================================================================
__global__ __launch_bounds__(256) void split_x_h(const float4* __restrict__ src,
                                                 uint2* __restrict__ xh) {
    int i = blockIdx.x * 256 + threadIdx.x;
    float4 v = src[i];
    __half2 p01 = __floats2half2_rn(v.x, v.y);
    __half2 p23 = __floats2half2_rn(v.z, v.w);
    uint2 H;
    H.x = *(uint32_t*)&p01;
    H.y = *(uint32_t*)&p23;
    xh[i] = H;
}

__global__ __launch_bounds__(256) void split_w_h(const float4* __restrict__ src,
                                                 uint2* __restrict__ wh,
                                                 uint2* __restrict__ wl) {
    int i = blockIdx.x * 256 + threadIdx.x;
    float4 v = src[i];
    __half h0 = __float2half_rn(v.x), h1 = __float2half_rn(v.y);
    __half h2 = __float2half_rn(v.z), h3 = __float2half_rn(v.w);
    float r0 = (v.x - __half2float(h0)) * 2048.f;
    float r1 = (v.y - __half2float(h1)) * 2048.f;
    float r2 = (v.z - __half2float(h2)) * 2048.f;
    float r3 = (v.w - __half2float(h3)) * 2048.f;
    __half2 lp01 = __floats2half2_rn(r0, r1), lp23 = __floats2half2_rn(r2, r3);
    uint2 H, L;
    H.x = packh2(h0, h1); H.y = packh2(h2, h3);
    L.x = *(uint32_t*)&lp01; L.y = *(uint32_t*)&lp23;
    wh[i] = H;
    wl[i] = L;
}

// ===========================================================================
// Fused QKV GEMM: [8192,3072] = X @ Wqkv^T, fp16 2-product scaled residual.
// Epilogue: Q -> fp16 hi; K -> fp16 hi + 2^11-scaled lo; V -> fp16 hi.
// ===========================================================================
#define GTILE 10240
#define GSTAGE (3 * GTILE)
#define GEMM_SMEM (2 * GSTAGE)

__global__ __launch_bounds__(256, 1) void gemm_qkv_f16(
    const __half* __restrict__ Xh,
    const __half* __restrict__ Wh, const __half* __restrict__ Wl,
    __half* __restrict__ qh,
    __half* __restrict__ kh, __half* __restrict__ kl,
    __half* __restrict__ vh) {
    extern __shared__ char smc[];
    const uint32_t sb = smem_u32(smc);

    const int tid = threadIdx.x;
    const int lane = tid & 31, wid = tid >> 5;
    const int bm = blockIdx.y << 7;
    const int bnG = blockIdx.x << 7;
    const int wm = (wid & 1) * 64, wn = (wid >> 1) * 32;
    const int fm = lane >> 2;
    const int fkb = (lane & 3) * 4;
    const int grp = lane >> 3, li = lane & 7;
    const uint32_t SC11 = 0x10001000u;   // fp16x2 {2^-11, 2^-11}

    float acc[4][4][4];
#pragma unroll
    for (int i = 0; i < 4; i++)
#pragma unroll
        for (int j = 0; j < 4; j++)
#pragma unroll
            for (int q = 0; q < 4; q++) acc[i][j][q] = 0.f;

    const int c0row = tid >> 2;
    const int c1row = c0row + 64;
    const int ce = (tid & 3) * 8;
    const uint32_t d0 = (uint32_t)(c0row * 80 + (tid & 3) * 16);
    const uint32_t d1 = (uint32_t)(c1row * 80 + (tid & 3) * 16);

#define ISSUE_STAGE(kt, p) do {                                        \
    uint32_t s0 = sb + (p) * GSTAGE;                                   \
    size_t a0 = (size_t)(bm + c0row) * 1024 + (size_t)(kt) * 32 + ce;  \
    size_t a1 = (size_t)(bm + c1row) * 1024 + (size_t)(kt) * 32 + ce;  \
    size_t b0 = (size_t)(bnG + c0row) * 1024 + (size_t)(kt) * 32 + ce; \
    size_t b1 = (size_t)(bnG + c1row) * 1024 + (size_t)(kt) * 32 + ce; \
    cp16(s0 + d0,             Xh + a0);  cp16(s0 + d1,             Xh + a1); \
    cp16(s0 + GTILE + d0,     Wh + b0);  cp16(s0 + GTILE + d1,     Wh + b1); \
    cp16(s0 + 2 * GTILE + d0, Wl + b0);  cp16(s0 + 2 * GTILE + d1, Wl + b1); \
    CP_COMMIT();                                                       \
} while (0)

    ISSUE_STAGE(0, 0);

    for (int kt = 0; kt < 32; kt++) {
        const int p = kt & 1;
        if (kt < 31) {
            ISSUE_STAGE(kt + 1, p ^ 1);
            CP_WAIT(1);
        } else {
            CP_WAIT(0);
        }
        __syncthreads();

        const uint32_t st = sb + p * GSTAGE;
#pragma unroll
        for (int k16o = 0; k16o < 64; k16o += 32) {
            uint32_t ah[4][4], as[4][4], bh[2][4], bl[2][4];
            const uint32_t akb = (uint32_t)(k16o + ((grp >> 1) << 4));
            const uint32_t bkb = (uint32_t)(k16o + ((grp & 1) << 4));
#pragma unroll
            for (int np = 0; np < 2; np++) {
                uint32_t nrow = (uint32_t)(wn + np * 16 + ((grp >> 1) << 3) + li);
                LDMX4(bh[np], st + GTILE + nrow * 80 + bkb);
                LDMX4(bl[np], st + 2 * GTILE + nrow * 80 + bkb);
            }
#pragma unroll
            for (int mt = 0; mt < 4; mt++) {
                uint32_t arow = (uint32_t)(wm + mt * 16 + ((grp & 1) << 3) + li);
                LDMX4(ah[mt], st + arow * 80 + akb);
            }
#pragma unroll
            for (int mt = 0; mt < 4; mt++)
#pragma unroll
                for (int nt = 0; nt < 4; nt++)
                    MMA_F16(acc[mt][nt], ah[mt], bh[nt >> 1][(nt & 1) * 2],
                            bh[nt >> 1][(nt & 1) * 2 + 1]);
#pragma unroll
            for (int mt = 0; mt < 4; mt++)
#pragma unroll
                for (int r = 0; r < 4; r++) as[mt][r] = hmul2u(ah[mt][r], SC11);
#pragma unroll
            for (int mt = 0; mt < 4; mt++)
#pragma unroll
                for (int nt = 0; nt < 4; nt++)
                    MMA_F16(acc[mt][nt], as[mt], bl[nt >> 1][(nt & 1) * 2],
                            bl[nt >> 1][(nt & 1) * 2 + 1]);
        }
        __syncthreads();
    }

    const int which = bnG >> 10;
    const int nloc = bnG & 1023;

    if (which == 1) {
        // K: hi + scaled lo
#pragma unroll
        for (int mt = 0; mt < 4; mt++) {
            size_t m0 = (size_t)(bm + wm + mt * 16 + fm);
#pragma unroll
            for (int nt = 0; nt < 4; nt++) {
                size_t n0 = (size_t)(nloc + wn + nt * 8 + (fkb >> 1));
                float c0 = acc[mt][nt][0], c1 = acc[mt][nt][1];
                float c2 = acc[mt][nt][2], c3 = acc[mt][nt][3];
                __half h0 = __float2half_rn(c0), h1 = __float2half_rn(c1);
                __half h2 = __float2half_rn(c2), h3 = __float2half_rn(c3);
                __half2 l01 = __floats2half2_rn((c0 - __half2float(h0)) * 2048.f,
                                                (c1 - __half2float(h1)) * 2048.f);
                __half2 l23 = __floats2half2_rn((c2 - __half2float(h2)) * 2048.f,
                                                (c3 - __half2float(h3)) * 2048.f);
                *(uint32_t*)((char*)kh + (m0 * 1024 + n0) * 2) = packh2(h0, h1);
                *(uint32_t*)((char*)kl + (m0 * 1024 + n0) * 2) = *(uint32_t*)&l01;
                *(uint32_t*)((char*)kh + ((m0 + 8) * 1024 + n0) * 2) = packh2(h2, h3);
                *(uint32_t*)((char*)kl + ((m0 + 8) * 1024 + n0) * 2) = *(uint32_t*)&l23;
            }
        }
    } else {
        __half* C = (which == 0) ? qh : vh;
#pragma unroll
        for (int mt = 0; mt < 4; mt++) {
            size_t m0 = (size_t)(bm + wm + mt * 16 + fm);
#pragma unroll
            for (int nt = 0; nt < 4; nt++) {
                size_t n0 = (size_t)(nloc + wn + nt * 8 + (fkb >> 1));
                __half2 p01 = __floats2half2_rn(acc[mt][nt][0], acc[mt][nt][1]);
                __half2 p23 = __floats2half2_rn(acc[mt][nt][2], acc[mt][nt][3]);
                *(uint32_t*)((char*)C + (m0 * 1024 + n0) * 2) = *(uint32_t*)&p01;
                *(uint32_t*)((char*)C + ((m0 + 8) * 1024 + n0) * 2) = *(uint32_t*)&p23;
            }
        }
    }
}

// ===========================================================================
// Flash attention, fp16 2-product scheme.
// S = Qh*(Kh + 2^-11 Kl); O = (Ph + 2^-11 Pl)*Vh.
// ===========================================================================
#define A_QH 0
#define A_KB 17408
#define KV_K_STRIDE 34816
#define A_VB 87040
#define KV_V_STRIDE 17408
#define A_SS 121856
#define A_PH 139264
#define A_PL 148480
#define A_RM 157696
#define A_RL 157952
#define A_RA 158208
#define ATTN_SMEM 158464

__global__ __launch_bounds__(256, 1) void attn_tc(const float* __restrict__ mask,
                                                  float* __restrict__ out) {
    extern __shared__ char smc[];
    const uint32_t sb = smem_u32(smc);

    const int tid = threadIdx.x;
    const int lane = tid & 31, wid = tid >> 5;
    const int qt = blockIdx.x, h = blockIdx.y, b = blockIdx.z;
    const int wm = (wid & 3) * 16;
    const int wnS = (wid >> 2) * 32;
    const int wnV = (wid >> 2) * 64;
    const int fm = lane >> 2;
    const uint32_t SC11 = 0x10001000u;

    const size_t bh_off = (size_t)b * TSEQ * DMOD + (size_t)h * DH;
    const __half* Qh = g_Qh + bh_off;
    const __half* Kh = g_Kh + bh_off;
    const __half* Kl = g_Kl + bh_off;
    const __half* Vh = g_Vh + bh_off;

    const int kt0 = (qt == 15) ? 0 : qt;

    for (int c = tid; c < 1024; c += 256) {
        int r = c >> 4, o = c & 15;
        uint32_t d = (uint32_t)(r * 272 + o * 16);
        size_t g = (size_t)(qt * 64 + r) * DMOD + o * 8;
        cp16(sb + A_QH + d, Qh + g);
    }

#define ISSUE_KV(kt_, s_) do {                                           \
    uint32_t kst = sb + A_KB + (uint32_t)(s_) * KV_K_STRIDE;             \
    uint32_t vst = sb + A_VB + (uint32_t)(s_) * KV_V_STRIDE;             \
    size_t roff = (size_t)(kt_) * 64 * DMOD;                             \
    for (int c = tid; c < 1024; c += 256) {                              \
        int r = c >> 4, o = c & 15;                                      \
        uint32_t d = (uint32_t)(r * 272 + o * 16);                       \
        size_t g = roff + (size_t)r * DMOD + o * 8;                      \
        cp16(kst + d,         Kh + g);                                   \
        cp16(kst + 17408 + d, Kl + g);                                   \
        cp16(vst + d,         Vh + g);                                   \
    }                                                                    \
} while (0)

    ISSUE_KV(kt0, 0);
    CP_COMMIT();
    ISSUE_KV(kt0 + 1, 1);
    CP_COMMIT();

    float* rowm = (float*)(smc + A_RM);
    float* rowl = (float*)(smc + A_RL);
    float* rowa = (float*)(smc + A_RA);
    if (tid < 64) { rowm[tid] = -1e30f; rowl[tid] = 0.f; }

    float acc_o[8][4];
#pragma unroll
    for (int j = 0; j < 8; j++)
#pragma unroll
        for (int q = 0; q < 4; q++) acc_o[j][q] = 0.f;

    const int grp = lane >> 3, li = lane & 7;

    for (int kt = kt0; kt < 16; kt++) {
        const int p = (kt - kt0) & 1;
        if (kt == 15) { CP_WAIT(0); } else { CP_WAIT(1); }
        __syncthreads();

        const uint32_t kst = sb + A_KB + (uint32_t)p * KV_K_STRIDE;
        const uint32_t vst = sb + A_VB + (uint32_t)p * KV_V_STRIDE;

        float sacc[4][4];
#pragma unroll
        for (int j = 0; j < 4; j++)
#pragma unroll
            for (int q = 0; q < 4; q++) sacc[j][q] = 0.f;

#pragma unroll
        for (int ks = 0; ks < 8; ks++) {
            uint32_t ah[4], as[4];
            {
                uint32_t arow = (uint32_t)(wm + ((grp & 1) << 3) + li);
                uint32_t akb = (uint32_t)(ks * 32 + ((grp >> 1) << 4));
                LDMX4(ah, sb + A_QH + arow * 272 + akb);
            }
#pragma unroll
            for (int r = 0; r < 4; r++) as[r] = hmul2u(ah[r], SC11);
            uint32_t bh[2][4], bl[2][4];
#pragma unroll
            for (int j2 = 0; j2 < 2; j2++) {
                uint32_t nrow = (uint32_t)(wnS + j2 * 16 + ((grp >> 1) << 3) + li);
                uint32_t kb = (uint32_t)(ks * 32 + ((grp & 1) << 4));
                LDMX4(bh[j2], kst + nrow * 272 + kb);
                LDMX4(bl[j2], kst + 17408 + nrow * 272 + kb);
            }
#pragma unroll
            for (int j = 0; j < 4; j++)
                MMA_F16(sacc[j], ah, bh[j >> 1][(j & 1) * 2], bh[j >> 1][(j & 1) * 2 + 1]);
#pragma unroll
            for (int j = 0; j < 4; j++)
                MMA_F16(sacc[j], as, bl[j >> 1][(j & 1) * 2], bl[j >> 1][(j & 1) * 2 + 1]);
        }

        {
            const int r0 = wm + fm;
            const int qg0 = qt * 64 + r0, qg1 = qg0 + 8;
#pragma unroll
            for (int j = 0; j < 4; j++) {
                int col = wnS + 8 * j + 2 * (lane & 3);
                int kg = kt * 64 + col;
                float2 v01, v23;
                v01.x = sacc[j][0] * SCALE + ((kg     <= qg0) ? -10000.f : 0.f);
                v01.y = sacc[j][1] * SCALE + ((kg + 1 <= qg0) ? -10000.f : 0.f);
                v23.x = sacc[j][2] * SCALE + ((kg     <= qg1) ? -10000.f : 0.f);
                v23.y = sacc[j][3] * SCALE + ((kg + 1 <= qg1) ? -10000.f : 0.f);
                *(float2*)(smc + A_SS + (size_t)r0 * 272 + col * 4) = v01;
                *(float2*)(smc + A_SS + (size_t)(r0 + 8) * 272 + col * 4) = v23;
            }
        }
        __syncthreads();

        {
            const int row = tid >> 2, q = tid & 3;
            float* srow = (float*)(smc + A_SS + (size_t)row * 272) + (q << 4);
            float4 v0 = *(float4*)&srow[0];
            float4 v1 = *(float4*)&srow[4];
            float4 v2 = *(float4*)&srow[8];
            float4 v3 = *(float4*)&srow[12];
            float mloc = fmaxf(
                fmaxf(fmaxf(fmaxf(v0.x, v0.y), fmaxf(v0.z, v0.w)),
                      fmaxf(fmaxf(v1.x, v1.y), fmaxf(v1.z, v1.w))),
                fmaxf(fmaxf(fmaxf(v2.x, v2.y), fmaxf(v2.z, v2.w)),
                      fmaxf(fmaxf(v3.x, v3.y), fmaxf(v3.z, v3.w))));
            mloc = fmaxf(mloc, __shfl_xor_sync(0xffffffffu, mloc, 1));
            mloc = fmaxf(mloc, __shfl_xor_sync(0xffffffffu, mloc, 2));
            float mold = rowm[row];
            float mnew = fmaxf(mold, mloc);
            float alpha = __expf(mold - mnew);
            v0.x = __expf(v0.x - mnew); v0.y = __expf(v0.y - mnew);
            v0.z = __expf(v0.z - mnew); v0.w = __expf(v0.w - mnew);
            v1.x = __expf(v1.x - mnew); v1.y = __expf(v1.y - mnew);
            v1.z = __expf(v1.z - mnew); v1.w = __expf(v1.w - mnew);
            v2.x = __expf(v2.x - mnew); v2.y = __expf(v2.y - mnew);
            v2.z = __expf(v2.z - mnew); v2.w = __expf(v2.w - mnew);
            v3.x = __expf(v3.x - mnew); v3.y = __expf(v3.y - mnew);
            v3.z = __expf(v3.z - mnew); v3.w = __expf(v3.w - mnew);

            uint32_t* phr = (uint32_t*)(smc + A_PH + (size_t)row * 144) + (q << 3);
            uint32_t* plr = (uint32_t*)(smc + A_PL + (size_t)row * 144) + (q << 3);
            const float4 vv[4] = {v0, v1, v2, v3};
#pragma unroll
            for (int u = 0; u < 4; u++) {
                float a0 = vv[u].x, a1 = vv[u].y, a2 = vv[u].z, a3 = vv[u].w;
                __half h0 = __float2half_rn(a0), h1 = __float2half_rn(a1);
                __half h2 = __float2half_rn(a2), h3 = __float2half_rn(a3);
                __half2 l01 = __floats2half2_rn((a0 - __half2float(h0)) * 2048.f,
                                                (a1 - __half2float(h1)) * 2048.f);
                __half2 l23 = __floats2half2_rn((a2 - __half2float(h2)) * 2048.f,
                                                (a3 - __half2float(h3)) * 2048.f);
                phr[2 * u]     = packh2(h0, h1);
                phr[2 * u + 1] = packh2(h2, h3);
                plr[2 * u]     = *(uint32_t*)&l01;
                plr[2 * u + 1] = *(uint32_t*)&l23;
            }

            float ssum = (v0.x + v0.y + v0.z + v0.w) + (v1.x + v1.y + v1.z + v1.w) +
                         (v2.x + v2.y + v2.z + v2.w) + (v3.x + v3.y + v3.z + v3.w);
            ssum += __shfl_xor_sync(0xffffffffu, ssum, 1);
            ssum += __shfl_xor_sync(0xffffffffu, ssum, 2);
            if (q == 0) {
                rowl[row] = rowl[row] * alpha + ssum;
                rowm[row] = mnew;
                rowa[row] = alpha;
            }
        }
        __syncthreads();

        {
            float al0 = rowa[wm + fm], al1 = rowa[wm + fm + 8];
#pragma unroll
            for (int j = 0; j < 8; j++) {
                acc_o[j][0] *= al0; acc_o[j][1] *= al0;
                acc_o[j][2] *= al1; acc_o[j][3] *= al1;
            }
#pragma unroll
            for (int ks = 0; ks < 4; ks++) {
                uint32_t ph[4], pls[4];
                {
                    uint32_t arow = (uint32_t)(wm + ((grp & 1) << 3) + li);
                    uint32_t akb = (uint32_t)(ks * 32 + ((grp >> 1) << 4));
                    LDMX4(ph, sb + A_PH + arow * 144 + akb);
                    LDMX4(pls, sb + A_PL + arow * 144 + akb);
                }
#pragma unroll
                for (int r = 0; r < 4; r++) pls[r] = hmul2u(pls[r], SC11);
#pragma unroll
                for (int j2 = 0; j2 < 4; j2++) {
                    uint32_t bvh[4];
                    uint32_t krow = (uint32_t)(ks * 16 + ((grp & 1) << 3) + li);
                    uint32_t nb = (uint32_t)((wnV + 16 * j2 + ((grp >> 1) << 3)) * 2);
                    LDMX4T(bvh, vst + krow * 272 + nb);
#pragma unroll
                    for (int jj = 0; jj < 2; jj++) {
                        int j = 2 * j2 + jj;
                        MMA_F16(acc_o[j], ph, bvh[jj * 2], bvh[jj * 2 + 1]);
                        MMA_F16(acc_o[j], pls, bvh[jj * 2], bvh[jj * 2 + 1]);
                    }
                }
            }
        }
        __syncthreads();

        if (kt + 2 <= 15) {
            ISSUE_KV(kt + 2, p);
            CP_COMMIT();
        }
    }

    {
        const int r0 = wm + fm;
        const int grow0 = b * TSEQ + qt * 64 + r0;
        float scl0 = (1.f / rowl[r0]) * mask[(size_t)b * TSEQ + qt * 64 + r0];
        float scl1 = (1.f / rowl[r0 + 8]) * mask[(size_t)b * TSEQ + qt * 64 + r0 + 8];
#pragma unroll
        for (int j = 0; j < 8; j++) {
            int col = h * DH + wnV + j * 8 + 2 * (lane & 3);
            float2 w0 = {acc_o[j][0] * scl0, acc_o[j][1] * scl0};
            float2 w1 = {acc_o[j][2] * scl1, acc_o[j][3] * scl1};
            *(float2*)&out[(size_t)grow0 * DMOD + col] = w0;
            *(float2*)&out[(size_t)(grow0 + 8) * DMOD + col] = w1;
        }
    }
}

extern "C" void kernel_launch(void* const* d_in, const int* in_sizes, int n_in,
                              void* d_out, int out_size) {
    const float* x    = (const float*)d_in[0];
    const float* mask = (const float*)d_in[1];
    const float* Wq   = (const float*)d_in[2];
    const float* Wk   = (const float*)d_in[3];
    const float* Wv   = (const float*)d_in[4];
    float* out = (float*)d_out;

    __half *xh, *wh, *wl, *qh, *kh, *kl, *vh;
    cudaGetSymbolAddress((void**)&xh, g_Xh);
    cudaGetSymbolAddress((void**)&wh, g_Wh);
    cudaGetSymbolAddress((void**)&wl, g_Wl);
    cudaGetSymbolAddress((void**)&qh, g_Qh);
    cudaGetSymbolAddress((void**)&kh, g_Kh);
    cudaGetSymbolAddress((void**)&kl, g_Kl);
    cudaGetSymbolAddress((void**)&vh, g_Vh);

    cudaFuncSetAttribute(gemm_qkv_f16, cudaFuncAttributeMaxDynamicSharedMemorySize,
                         GEMM_SMEM);
    cudaFuncSetAttribute(attn_tc, cudaFuncAttributeMaxDynamicSharedMemorySize,
                         ATTN_SMEM);

    const int xn4 = BATCH * TSEQ * DMOD / 4;
    const int wn4 = DMOD * DMOD / 4;
    split_x_h<<<xn4 / 256, 256>>>((const float4*)x, (uint2*)xh);
    split_w_h<<<wn4 / 256, 256>>>((const float4*)Wq, (uint2*)wh, (uint2*)wl);
    split_w_h<<<wn4 / 256, 256>>>((const float4*)Wk,
                                  (uint2*)(wh + DMOD * DMOD),
                                  (uint2*)(wl + DMOD * DMOD));
    split_w_h<<<wn4 / 256, 256>>>((const float4*)Wv,
                                  (uint2*)(wh + 2 * DMOD * DMOD),
                                  (uint2*)(wl + 2 * DMOD * DMOD));

    dim3 ggrid(3 * DMOD / 128, (BATCH * TSEQ) / 128);
    gemm_qkv_f16<<<ggrid, 256, GEMM_SMEM>>>(xh, wh, wl, qh, kh, kl, vh);

    dim3 agrid(TSEQ / 64, NH, BATCH);
    attn_tc<<<agrid, 256, ATTN_SMEM>>>(mask, out);
}

// round 8
// speedup vs baseline: 4.1025x; 1.2937x over previous
#include <cuda_runtime.h>
#include <cuda_bf16.h>
#include <cuda_fp16.h>
#include <cstdint>

#define BATCH 8
#define TSEQ 1024
#define DMOD 1024
#define NH 8
#define DH 128
#define SCALE 0.08838834764831845f

// Scratch (device globals: allocation-free).
__device__ __half g_Xh[BATCH * TSEQ * DMOD];
__device__ __half g_Wh[3 * DMOD * DMOD];
__device__ __half g_Qh[BATCH * TSEQ * DMOD];
__device__ __half g_Kh[BATCH * TSEQ * DMOD];
__device__ __half g_Kl[BATCH * TSEQ * DMOD];
__device__ __half g_Vh[BATCH * TSEQ * DMOD];

__device__ __forceinline__ uint32_t smem_u32(const void* p) {
    uint32_t a;
    asm("{ .reg .u64 t; cvta.to.shared.u64 t, %1; cvt.u32.u64 %0, t; }"
        : "=r"(a) : "l"(p));
    return a;
}
__device__ __forceinline__ void cp16(uint32_t dst, const void* src) {
    asm volatile("cp.async.cg.shared.global [%0], [%1], 16;"
                 :: "r"(dst), "l"(src) : "memory");
}
#define CP_COMMIT() asm volatile("cp.async.commit_group;" ::: "memory")
#define CP_WAIT(n)  asm volatile("cp.async.wait_group %0;" :: "n"(n) : "memory")

#define MMA_F16(c, a, b0_, b1_) \
    asm volatile("mma.sync.aligned.m16n8k16.row.col.f32.f16.f16.f32 " \
                 "{%0,%1,%2,%3}, {%4,%5,%6,%7}, {%8,%9}, {%0,%1,%2,%3};" \
                 : "+f"((c)[0]), "+f"((c)[1]), "+f"((c)[2]), "+f"((c)[3]) \
                 : "r"((a)[0]), "r"((a)[1]), "r"((a)[2]), "r"((a)[3]), \
                   "r"(b0_), "r"(b1_))

#define LDMX4(r, addr) \
    asm volatile("ldmatrix.sync.aligned.m8n8.x4.shared.b16 {%0,%1,%2,%3}, [%4];" \
                 : "=r"((r)[0]), "=r"((r)[1]), "=r"((r)[2]), "=r"((r)[3]) : "r"(addr))
#define LDMX4T(r, addr) \
    asm volatile("ldmatrix.sync.aligned.m8n8.x4.trans.shared.b16 {%0,%1,%2,%3}, [%4];" \
                 : "=r"((r)[0]), "=r"((r)[1]), "=r"((r)[2]), "=r"((r)[3]) : "r"(addr))

__device__ __forceinline__ uint32_t hmul2u(uint32_t a, uint32_t b) {
    uint32_t d;
    asm("mul.rn.f16x2 %0, %1, %2;" : "=r"(d) : "r"(a), "r"(b));
    return d;
}
__device__ __forceinline__ uint32_t packh2(__half x, __half y) {
    __half2 h = __halves2half2(x, y);
    return *(uint32_t*)&h;
}

// ===========================================================================
// fp32 -> fp16 conversion (used for X and all three W's)
// ===========================================================================
__global__ __launch_bounds__(256) void cvt_f16(const float4* __restrict__ src,
                                               uint2* __restrict__ dst) {
    int i = blockIdx.x * 256 + threadIdx.x;
    float4 v = src[i];
    __half2 p01 = __floats2half2_rn(v.x, v.y);
    __half2 p23 = __floats2half2_rn(v.z, v.w);
    uint2 H;
    H.x = *(uint32_t*)&p01;
    H.y = *(uint32_t*)&p23;
    dst[i] = H;
}

// ===========================================================================
// Fused QKV GEMM: [8192,3072] = X @ Wqkv^T, single-product fp16 (C = Xh*Wh).
// 128x128 block, BK=32, 8 warps, 2-stage cp.async, ldmatrix fragments.
// Epilogue: Q -> fp16 hi; K -> fp16 hi + 2^11-scaled lo; V -> fp16 hi.
// ===========================================================================
#define GTILE 10240
#define GSTAGE (2 * GTILE)
#define GEMM_SMEM (2 * GSTAGE)   // 40960 bytes

__global__ __launch_bounds__(256, 1) void gemm_qkv_f16(
    const __half* __restrict__ Xh, const __half* __restrict__ Wh,
    __half* __restrict__ qh,
    __half* __restrict__ kh, __half* __restrict__ kl,
    __half* __restrict__ vh) {
    extern __shared__ char smc[];
    const uint32_t sb = smem_u32(smc);

    const int tid = threadIdx.x;
    const int lane = tid & 31, wid = tid >> 5;
    const int bm = blockIdx.y << 7;
    const int bnG = blockIdx.x << 7;
    const int wm = (wid & 1) * 64, wn = (wid >> 1) * 32;
    const int fm = lane >> 2;
    const int fkb = (lane & 3) * 4;
    const int grp = lane >> 3, li = lane & 7;

    float acc[4][4][4];
#pragma unroll
    for (int i = 0; i < 4; i++)
#pragma unroll
        for (int j = 0; j < 4; j++)
#pragma unroll
            for (int q = 0; q < 4; q++) acc[i][j][q] = 0.f;

    const int c0row = tid >> 2;
    const int c1row = c0row + 64;
    const int ce = (tid & 3) * 8;
    const uint32_t d0 = (uint32_t)(c0row * 80 + (tid & 3) * 16);
    const uint32_t d1 = (uint32_t)(c1row * 80 + (tid & 3) * 16);

#define ISSUE_STAGE(kt, p) do {                                        \
    uint32_t s0 = sb + (p) * GSTAGE;                                   \
    size_t a0 = (size_t)(bm + c0row) * 1024 + (size_t)(kt) * 32 + ce;  \
    size_t a1 = (size_t)(bm + c1row) * 1024 + (size_t)(kt) * 32 + ce;  \
    size_t b0 = (size_t)(bnG + c0row) * 1024 + (size_t)(kt) * 32 + ce; \
    size_t b1 = (size_t)(bnG + c1row) * 1024 + (size_t)(kt) * 32 + ce; \
    cp16(s0 + d0,         Xh + a0);  cp16(s0 + d1,         Xh + a1);   \
    cp16(s0 + GTILE + d0, Wh + b0);  cp16(s0 + GTILE + d1, Wh + b1);   \
    CP_COMMIT();                                                       \
} while (0)

    ISSUE_STAGE(0, 0);

    for (int kt = 0; kt < 32; kt++) {
        const int p = kt & 1;
        if (kt < 31) {
            ISSUE_STAGE(kt + 1, p ^ 1);
            CP_WAIT(1);
        } else {
            CP_WAIT(0);
        }
        __syncthreads();

        const uint32_t st = sb + p * GSTAGE;
#pragma unroll
        for (int k16o = 0; k16o < 64; k16o += 32) {
            uint32_t ah[4][4], bh[2][4];
            const uint32_t akb = (uint32_t)(k16o + ((grp >> 1) << 4));
            const uint32_t bkb = (uint32_t)(k16o + ((grp & 1) << 4));
#pragma unroll
            for (int np = 0; np < 2; np++) {
                uint32_t nrow = (uint32_t)(wn + np * 16 + ((grp >> 1) << 3) + li);
                LDMX4(bh[np], st + GTILE + nrow * 80 + bkb);
            }
#pragma unroll
            for (int mt = 0; mt < 4; mt++) {
                uint32_t arow = (uint32_t)(wm + mt * 16 + ((grp & 1) << 3) + li);
                LDMX4(ah[mt], st + arow * 80 + akb);
            }
#pragma unroll
            for (int mt = 0; mt < 4; mt++)
#pragma unroll
                for (int nt = 0; nt < 4; nt++)
                    MMA_F16(acc[mt][nt], ah[mt], bh[nt >> 1][(nt & 1) * 2],
                            bh[nt >> 1][(nt & 1) * 2 + 1]);
        }
        __syncthreads();
    }

    const int which = bnG >> 10;
    const int nloc = bnG & 1023;

    if (which == 1) {
        // K: hi + scaled lo (consumed by attention's 2-product S-GEMM)
#pragma unroll
        for (int mt = 0; mt < 4; mt++) {
            size_t m0 = (size_t)(bm + wm + mt * 16 + fm);
#pragma unroll
            for (int nt = 0; nt < 4; nt++) {
                size_t n0 = (size_t)(nloc + wn + nt * 8 + (fkb >> 1));
                float c0 = acc[mt][nt][0], c1 = acc[mt][nt][1];
                float c2 = acc[mt][nt][2], c3 = acc[mt][nt][3];
                __half h0 = __float2half_rn(c0), h1 = __float2half_rn(c1);
                __half h2 = __float2half_rn(c2), h3 = __float2half_rn(c3);
                __half2 l01 = __floats2half2_rn((c0 - __half2float(h0)) * 2048.f,
                                                (c1 - __half2float(h1)) * 2048.f);
                __half2 l23 = __floats2half2_rn((c2 - __half2float(h2)) * 2048.f,
                                                (c3 - __half2float(h3)) * 2048.f);
                *(uint32_t*)((char*)kh + (m0 * 1024 + n0) * 2) = packh2(h0, h1);
                *(uint32_t*)((char*)kl + (m0 * 1024 + n0) * 2) = *(uint32_t*)&l01;
                *(uint32_t*)((char*)kh + ((m0 + 8) * 1024 + n0) * 2) = packh2(h2, h3);
                *(uint32_t*)((char*)kl + ((m0 + 8) * 1024 + n0) * 2) = *(uint32_t*)&l23;
            }
        }
    } else {
        __half* C = (which == 0) ? qh : vh;
#pragma unroll
        for (int mt = 0; mt < 4; mt++) {
            size_t m0 = (size_t)(bm + wm + mt * 16 + fm);
#pragma unroll
            for (int nt = 0; nt < 4; nt++) {
                size_t n0 = (size_t)(nloc + wn + nt * 8 + (fkb >> 1));
                __half2 p01 = __floats2half2_rn(acc[mt][nt][0], acc[mt][nt][1]);
                __half2 p23 = __floats2half2_rn(acc[mt][nt][2], acc[mt][nt][3]);
                *(uint32_t*)((char*)C + (m0 * 1024 + n0) * 2) = *(uint32_t*)&p01;
                *(uint32_t*)((char*)C + ((m0 + 8) * 1024 + n0) * 2) = *(uint32_t*)&p23;
            }
        }
    }
}

// ===========================================================================
// Flash attention, fp16 2-product scheme (unchanged — verified).
// S = Qh*(Kh + 2^-11 Kl); O = (Ph + 2^-11 Pl)*Vh.
// ===========================================================================
#define A_QH 0
#define A_KB 17408
#define KV_K_STRIDE 34816
#define A_VB 87040
#define KV_V_STRIDE 17408
#define A_SS 121856
#define A_PH 139264
#define A_PL 148480
#define A_RM 157696
#define A_RL 157952
#define A_RA 158208
#define ATTN_SMEM 158464

__global__ __launch_bounds__(256, 1) void attn_tc(const float* __restrict__ mask,
                                                  float* __restrict__ out) {
    extern __shared__ char smc[];
    const uint32_t sb = smem_u32(smc);

    const int tid = threadIdx.x;
    const int lane = tid & 31, wid = tid >> 5;
    const int qt = blockIdx.x, h = blockIdx.y, b = blockIdx.z;
    const int wm = (wid & 3) * 16;
    const int wnS = (wid >> 2) * 32;
    const int wnV = (wid >> 2) * 64;
    const int fm = lane >> 2;
    const uint32_t SC11 = 0x10001000u;

    const size_t bh_off = (size_t)b * TSEQ * DMOD + (size_t)h * DH;
    const __half* Qh = g_Qh + bh_off;
    const __half* Kh = g_Kh + bh_off;
    const __half* Kl = g_Kl + bh_off;
    const __half* Vh = g_Vh + bh_off;

    const int kt0 = (qt == 15) ? 0 : qt;

    for (int c = tid; c < 1024; c += 256) {
        int r = c >> 4, o = c & 15;
        uint32_t d = (uint32_t)(r * 272 + o * 16);
        size_t g = (size_t)(qt * 64 + r) * DMOD + o * 8;
        cp16(sb + A_QH + d, Qh + g);
    }

#define ISSUE_KV(kt_, s_) do {                                           \
    uint32_t kst = sb + A_KB + (uint32_t)(s_) * KV_K_STRIDE;             \
    uint32_t vst = sb + A_VB + (uint32_t)(s_) * KV_V_STRIDE;             \
    size_t roff = (size_t)(kt_) * 64 * DMOD;                             \
    for (int c = tid; c < 1024; c += 256) {                              \
        int r = c >> 4, o = c & 15;                                      \
        uint32_t d = (uint32_t)(r * 272 + o * 16);                       \
        size_t g = roff + (size_t)r * DMOD + o * 8;                      \
        cp16(kst + d,         Kh + g);                                   \
        cp16(kst + 17408 + d, Kl + g);                                   \
        cp16(vst + d,         Vh + g);                                   \
    }                                                                    \
} while (0)

    ISSUE_KV(kt0, 0);
    CP_COMMIT();
    ISSUE_KV(kt0 + 1, 1);
    CP_COMMIT();

    float* rowm = (float*)(smc + A_RM);
    float* rowl = (float*)(smc + A_RL);
    float* rowa = (float*)(smc + A_RA);
    if (tid < 64) { rowm[tid] = -1e30f; rowl[tid] = 0.f; }

    float acc_o[8][4];
#pragma unroll
    for (int j = 0; j < 8; j++)
#pragma unroll
        for (int q = 0; q < 4; q++) acc_o[j][q] = 0.f;

    const int grp = lane >> 3, li = lane & 7;

    for (int kt = kt0; kt < 16; kt++) {
        const int p = (kt - kt0) & 1;
        if (kt == 15) { CP_WAIT(0); } else { CP_WAIT(1); }
        __syncthreads();

        const uint32_t kst = sb + A_KB + (uint32_t)p * KV_K_STRIDE;
        const uint32_t vst = sb + A_VB + (uint32_t)p * KV_V_STRIDE;

        float sacc[4][4];
#pragma unroll
        for (int j = 0; j < 4; j++)
#pragma unroll
            for (int q = 0; q < 4; q++) sacc[j][q] = 0.f;

#pragma unroll
        for (int ks = 0; ks < 8; ks++) {
            uint32_t ah[4], as[4];
            {
                uint32_t arow = (uint32_t)(wm + ((grp & 1) << 3) + li);
                uint32_t akb = (uint32_t)(ks * 32 + ((grp >> 1) << 4));
                LDMX4(ah, sb + A_QH + arow * 272 + akb);
            }
#pragma unroll
            for (int r = 0; r < 4; r++) as[r] = hmul2u(ah[r], SC11);
            uint32_t bh[2][4], bl[2][4];
#pragma unroll
            for (int j2 = 0; j2 < 2; j2++) {
                uint32_t nrow = (uint32_t)(wnS + j2 * 16 + ((grp >> 1) << 3) + li);
                uint32_t kb = (uint32_t)(ks * 32 + ((grp & 1) << 4));
                LDMX4(bh[j2], kst + nrow * 272 + kb);
                LDMX4(bl[j2], kst + 17408 + nrow * 272 + kb);
            }
#pragma unroll
            for (int j = 0; j < 4; j++)
                MMA_F16(sacc[j], ah, bh[j >> 1][(j & 1) * 2], bh[j >> 1][(j & 1) * 2 + 1]);
#pragma unroll
            for (int j = 0; j < 4; j++)
                MMA_F16(sacc[j], as, bl[j >> 1][(j & 1) * 2], bl[j >> 1][(j & 1) * 2 + 1]);
        }

        {
            const int r0 = wm + fm;
            const int qg0 = qt * 64 + r0, qg1 = qg0 + 8;
#pragma unroll
            for (int j = 0; j < 4; j++) {
                int col = wnS + 8 * j + 2 * (lane & 3);
                int kg = kt * 64 + col;
                float2 v01, v23;
                v01.x = sacc[j][0] * SCALE + ((kg     <= qg0) ? -10000.f : 0.f);
                v01.y = sacc[j][1] * SCALE + ((kg + 1 <= qg0) ? -10000.f : 0.f);
                v23.x = sacc[j][2] * SCALE + ((kg     <= qg1) ? -10000.f : 0.f);
                v23.y = sacc[j][3] * SCALE + ((kg + 1 <= qg1) ? -10000.f : 0.f);
                *(float2*)(smc + A_SS + (size_t)r0 * 272 + col * 4) = v01;
                *(float2*)(smc + A_SS + (size_t)(r0 + 8) * 272 + col * 4) = v23;
            }
        }
        __syncthreads();

        {
            const int row = tid >> 2, q = tid & 3;
            float* srow = (float*)(smc + A_SS + (size_t)row * 272) + (q << 4);
            float4 v0 = *(float4*)&srow[0];
            float4 v1 = *(float4*)&srow[4];
            float4 v2 = *(float4*)&srow[8];
            float4 v3 = *(float4*)&srow[12];
            float mloc = fmaxf(
                fmaxf(fmaxf(fmaxf(v0.x, v0.y), fmaxf(v0.z, v0.w)),
                      fmaxf(fmaxf(v1.x, v1.y), fmaxf(v1.z, v1.w))),
                fmaxf(fmaxf(fmaxf(v2.x, v2.y), fmaxf(v2.z, v2.w)),
                      fmaxf(fmaxf(v3.x, v3.y), fmaxf(v3.z, v3.w))));
            mloc = fmaxf(mloc, __shfl_xor_sync(0xffffffffu, mloc, 1));
            mloc = fmaxf(mloc, __shfl_xor_sync(0xffffffffu, mloc, 2));
            float mold = rowm[row];
            float mnew = fmaxf(mold, mloc);
            float alpha = __expf(mold - mnew);
            v0.x = __expf(v0.x - mnew); v0.y = __expf(v0.y - mnew);
            v0.z = __expf(v0.z - mnew); v0.w = __expf(v0.w - mnew);
            v1.x = __expf(v1.x - mnew); v1.y = __expf(v1.y - mnew);
            v1.z = __expf(v1.z - mnew); v1.w = __expf(v1.w - mnew);
            v2.x = __expf(v2.x - mnew); v2.y = __expf(v2.y - mnew);
            v2.z = __expf(v2.z - mnew); v2.w = __expf(v2.w - mnew);
            v3.x = __expf(v3.x - mnew); v3.y = __expf(v3.y - mnew);
            v3.z = __expf(v3.z - mnew); v3.w = __expf(v3.w - mnew);

            uint32_t* phr = (uint32_t*)(smc + A_PH + (size_t)row * 144) + (q << 3);
            uint32_t* plr = (uint32_t*)(smc + A_PL + (size_t)row * 144) + (q << 3);
            const float4 vv[4] = {v0, v1, v2, v3};
#pragma unroll
            for (int u = 0; u < 4; u++) {
                float a0 = vv[u].x, a1 = vv[u].y, a2 = vv[u].z, a3 = vv[u].w;
                __half h0 = __float2half_rn(a0), h1 = __float2half_rn(a1);
                __half h2 = __float2half_rn(a2), h3 = __float2half_rn(a3);
                __half2 l01 = __floats2half2_rn((a0 - __half2float(h0)) * 2048.f,
                                                (a1 - __half2float(h1)) * 2048.f);
                __half2 l23 = __floats2half2_rn((a2 - __half2float(h2)) * 2048.f,
                                                (a3 - __half2float(h3)) * 2048.f);
                phr[2 * u]     = packh2(h0, h1);
                phr[2 * u + 1] = packh2(h2, h3);
                plr[2 * u]     = *(uint32_t*)&l01;
                plr[2 * u + 1] = *(uint32_t*)&l23;
            }

            float ssum = (v0.x + v0.y + v0.z + v0.w) + (v1.x + v1.y + v1.z + v1.w) +
                         (v2.x + v2.y + v2.z + v2.w) + (v3.x + v3.y + v3.z + v3.w);
            ssum += __shfl_xor_sync(0xffffffffu, ssum, 1);
            ssum += __shfl_xor_sync(0xffffffffu, ssum, 2);
            if (q == 0) {
                rowl[row] = rowl[row] * alpha + ssum;
                rowm[row] = mnew;
                rowa[row] = alpha;
            }
        }
        __syncthreads();

        {
            float al0 = rowa[wm + fm], al1 = rowa[wm + fm + 8];
#pragma unroll
            for (int j = 0; j < 8; j++) {
                acc_o[j][0] *= al0; acc_o[j][1] *= al0;
                acc_o[j][2] *= al1; acc_o[j][3] *= al1;
            }
#pragma unroll
            for (int ks = 0; ks < 4; ks++) {
                uint32_t ph[4], pls[4];
                {
                    uint32_t arow = (uint32_t)(wm + ((grp & 1) << 3) + li);
                    uint32_t akb = (uint32_t)(ks * 32 + ((grp >> 1) << 4));
                    LDMX4(ph, sb + A_PH + arow * 144 + akb);
                    LDMX4(pls, sb + A_PL + arow * 144 + akb);
                }
#pragma unroll
                for (int r = 0; r < 4; r++) pls[r] = hmul2u(pls[r], SC11);
#pragma unroll
                for (int j2 = 0; j2 < 4; j2++) {
                    uint32_t bvh[4];
                    uint32_t krow = (uint32_t)(ks * 16 + ((grp & 1) << 3) + li);
                    uint32_t nb = (uint32_t)((wnV + 16 * j2 + ((grp >> 1) << 3)) * 2);
                    LDMX4T(bvh, vst + krow * 272 + nb);
#pragma unroll
                    for (int jj = 0; jj < 2; jj++) {
                        int j = 2 * j2 + jj;
                        MMA_F16(acc_o[j], ph, bvh[jj * 2], bvh[jj * 2 + 1]);
                        MMA_F16(acc_o[j], pls, bvh[jj * 2], bvh[jj * 2 + 1]);
                    }
                }
            }
        }
        __syncthreads();

        if (kt + 2 <= 15) {
            ISSUE_KV(kt + 2, p);
            CP_COMMIT();
        }
    }

    {
        const int r0 = wm + fm;
        const int grow0 = b * TSEQ + qt * 64 + r0;
        float scl0 = (1.f / rowl[r0]) * mask[(size_t)b * TSEQ + qt * 64 + r0];
        float scl1 = (1.f / rowl[r0 + 8]) * mask[(size_t)b * TSEQ + qt * 64 + r0 + 8];
#pragma unroll
        for (int j = 0; j < 8; j++) {
            int col = h * DH + wnV + j * 8 + 2 * (lane & 3);
            float2 w0 = {acc_o[j][0] * scl0, acc_o[j][1] * scl0};
            float2 w1 = {acc_o[j][2] * scl1, acc_o[j][3] * scl1};
            *(float2*)&out[(size_t)grow0 * DMOD + col] = w0;
            *(float2*)&out[(size_t)(grow0 + 8) * DMOD + col] = w1;
        }
    }
}

extern "C" void kernel_launch(void* const* d_in, const int* in_sizes, int n_in,
                              void* d_out, int out_size) {
    const float* x    = (const float*)d_in[0];
    const float* mask = (const float*)d_in[1];
    const float* Wq   = (const float*)d_in[2];
    const float* Wk   = (const float*)d_in[3];
    const float* Wv   = (const float*)d_in[4];
    float* out = (float*)d_out;

    __half *xh, *wh, *qh, *kh, *kl, *vh;
    cudaGetSymbolAddress((void**)&xh, g_Xh);
    cudaGetSymbolAddress((void**)&wh, g_Wh);
    cudaGetSymbolAddress((void**)&qh, g_Qh);
    cudaGetSymbolAddress((void**)&kh, g_Kh);
    cudaGetSymbolAddress((void**)&kl, g_Kl);
    cudaGetSymbolAddress((void**)&vh, g_Vh);

    cudaFuncSetAttribute(gemm_qkv_f16, cudaFuncAttributeMaxDynamicSharedMemorySize,
                         GEMM_SMEM);
    cudaFuncSetAttribute(attn_tc, cudaFuncAttributeMaxDynamicSharedMemorySize,
                         ATTN_SMEM);

    const int xn4 = BATCH * TSEQ * DMOD / 4;
    const int wn4 = DMOD * DMOD / 4;
    cvt_f16<<<xn4 / 256, 256>>>((const float4*)x, (uint2*)xh);
    cvt_f16<<<wn4 / 256, 256>>>((const float4*)Wq, (uint2*)wh);
    cvt_f16<<<wn4 / 256, 256>>>((const float4*)Wk, (uint2*)(wh + DMOD * DMOD));
    cvt_f16<<<wn4 / 256, 256>>>((const float4*)Wv, (uint2*)(wh + 2 * DMOD * DMOD));

    dim3 ggrid(3 * DMOD / 128, (BATCH * TSEQ) / 128);
    gemm_qkv_f16<<<ggrid, 256, GEMM_SMEM>>>(xh, wh, qh, kh, kl, vh);

    dim3 agrid(TSEQ / 64, NH, BATCH);
    attn_tc<<<agrid, 256, ATTN_SMEM>>>(mask, out);
}

// round 9
// speedup vs baseline: 5.7824x; 1.4095x over previous
#include <cuda_runtime.h>
#include <cuda_bf16.h>
#include <cuda_fp16.h>
#include <cstdint>

#define BATCH 8
#define TSEQ 1024
#define DMOD 1024
#define NH 8
#define DH 128
#define SCALE 0.08838834764831845f

// Scratch (device globals: allocation-free).
__device__ __half g_Xh[BATCH * TSEQ * DMOD];
__device__ __half g_Wh[3 * DMOD * DMOD];
__device__ __half g_Qh[BATCH * TSEQ * DMOD];
__device__ __half g_Kh[BATCH * TSEQ * DMOD];
__device__ __half g_Vh[BATCH * TSEQ * DMOD];

__device__ __forceinline__ uint32_t smem_u32(const void* p) {
    uint32_t a;
    asm("{ .reg .u64 t; cvta.to.shared.u64 t, %1; cvt.u32.u64 %0, t; }"
        : "=r"(a) : "l"(p));
    return a;
}
__device__ __forceinline__ void cp16(uint32_t dst, const void* src) {
    asm volatile("cp.async.cg.shared.global [%0], [%1], 16;"
                 :: "r"(dst), "l"(src) : "memory");
}
#define CP_COMMIT() asm volatile("cp.async.commit_group;" ::: "memory")
#define CP_WAIT(n)  asm volatile("cp.async.wait_group %0;" :: "n"(n) : "memory")

#define MMA_F16(c, a, b0_, b1_) \
    asm volatile("mma.sync.aligned.m16n8k16.row.col.f32.f16.f16.f32 " \
                 "{%0,%1,%2,%3}, {%4,%5,%6,%7}, {%8,%9}, {%0,%1,%2,%3};" \
                 : "+f"((c)[0]), "+f"((c)[1]), "+f"((c)[2]), "+f"((c)[3]) \
                 : "r"((a)[0]), "r"((a)[1]), "r"((a)[2]), "r"((a)[3]), \
                   "r"(b0_), "r"(b1_))

#define LDMX4(r, addr) \
    asm volatile("ldmatrix.sync.aligned.m8n8.x4.shared.b16 {%0,%1,%2,%3}, [%4];" \
                 : "=r"((r)[0]), "=r"((r)[1]), "=r"((r)[2]), "=r"((r)[3]) : "r"(addr))
#define LDMX4T(r, addr) \
    asm volatile("ldmatrix.sync.aligned.m8n8.x4.trans.shared.b16 {%0,%1,%2,%3}, [%4];" \
                 : "=r"((r)[0]), "=r"((r)[1]), "=r"((r)[2]), "=r"((r)[3]) : "r"(addr))

__device__ __forceinline__ uint32_t packh2(__half x, __half y) {
    __half2 h = __halves2half2(x, y);
    return *(uint32_t*)&h;
}

// ===========================================================================
// fp32 -> fp16 conversion (X and all three W's)
// ===========================================================================
__global__ __launch_bounds__(256) void cvt_f16(const float4* __restrict__ src,
                                               uint2* __restrict__ dst) {
    int i = blockIdx.x * 256 + threadIdx.x;
    float4 v = src[i];
    __half2 p01 = __floats2half2_rn(v.x, v.y);
    __half2 p23 = __floats2half2_rn(v.z, v.w);
    uint2 H;
    H.x = *(uint32_t*)&p01;
    H.y = *(uint32_t*)&p23;
    dst[i] = H;
}

// ===========================================================================
// Fused QKV GEMM: [8192,3072] = X @ Wqkv^T, single-product fp16.
// 128x128 block, BK=32, 8 warps, 2-stage cp.async, 2 CTAs/SM.
// ===========================================================================
#define GTILE 10240
#define GSTAGE (2 * GTILE)
#define GEMM_SMEM (2 * GSTAGE)   // 40960 bytes

__global__ __launch_bounds__(256, 2) void gemm_qkv_f16(
    const __half* __restrict__ Xh, const __half* __restrict__ Wh,
    __half* __restrict__ qh, __half* __restrict__ kh, __half* __restrict__ vh) {
    extern __shared__ char smc[];
    const uint32_t sb = smem_u32(smc);

    const int tid = threadIdx.x;
    const int lane = tid & 31, wid = tid >> 5;
    const int bm = blockIdx.y << 7;
    const int bnG = blockIdx.x << 7;
    const int wm = (wid & 1) * 64, wn = (wid >> 1) * 32;
    const int fm = lane >> 2;
    const int fkb = (lane & 3) * 4;
    const int grp = lane >> 3, li = lane & 7;

    float acc[4][4][4];
#pragma unroll
    for (int i = 0; i < 4; i++)
#pragma unroll
        for (int j = 0; j < 4; j++)
#pragma unroll
            for (int q = 0; q < 4; q++) acc[i][j][q] = 0.f;

    const int c0row = tid >> 2;
    const int c1row = c0row + 64;
    const int ce = (tid & 3) * 8;
    const uint32_t d0 = (uint32_t)(c0row * 80 + (tid & 3) * 16);
    const uint32_t d1 = (uint32_t)(c1row * 80 + (tid & 3) * 16);

#define ISSUE_STAGE(kt, p) do {                                        \
    uint32_t s0 = sb + (p) * GSTAGE;                                   \
    size_t a0 = (size_t)(bm + c0row) * 1024 + (size_t)(kt) * 32 + ce;  \
    size_t a1 = (size_t)(bm + c1row) * 1024 + (size_t)(kt) * 32 + ce;  \
    size_t b0 = (size_t)(bnG + c0row) * 1024 + (size_t)(kt) * 32 + ce; \
    size_t b1 = (size_t)(bnG + c1row) * 1024 + (size_t)(kt) * 32 + ce; \
    cp16(s0 + d0,         Xh + a0);  cp16(s0 + d1,         Xh + a1);   \
    cp16(s0 + GTILE + d0, Wh + b0);  cp16(s0 + GTILE + d1, Wh + b1);   \
    CP_COMMIT();                                                       \
} while (0)

    ISSUE_STAGE(0, 0);

    for (int kt = 0; kt < 32; kt++) {
        const int p = kt & 1;
        if (kt < 31) {
            ISSUE_STAGE(kt + 1, p ^ 1);
            CP_WAIT(1);
        } else {
            CP_WAIT(0);
        }
        __syncthreads();

        const uint32_t st = sb + p * GSTAGE;
#pragma unroll
        for (int k16o = 0; k16o < 64; k16o += 32) {
            uint32_t ah[4][4], bh[2][4];
            const uint32_t akb = (uint32_t)(k16o + ((grp >> 1) << 4));
            const uint32_t bkb = (uint32_t)(k16o + ((grp & 1) << 4));
#pragma unroll
            for (int np = 0; np < 2; np++) {
                uint32_t nrow = (uint32_t)(wn + np * 16 + ((grp >> 1) << 3) + li);
                LDMX4(bh[np], st + GTILE + nrow * 80 + bkb);
            }
#pragma unroll
            for (int mt = 0; mt < 4; mt++) {
                uint32_t arow = (uint32_t)(wm + mt * 16 + ((grp & 1) << 3) + li);
                LDMX4(ah[mt], st + arow * 80 + akb);
            }
#pragma unroll
            for (int mt = 0; mt < 4; mt++)
#pragma unroll
                for (int nt = 0; nt < 4; nt++)
                    MMA_F16(acc[mt][nt], ah[mt], bh[nt >> 1][(nt & 1) * 2],
                            bh[nt >> 1][(nt & 1) * 2 + 1]);
        }
        __syncthreads();
    }

    const int which = bnG >> 10;
    const int nloc = bnG & 1023;
    __half* C = (which == 0) ? qh : (which == 1) ? kh : vh;

#pragma unroll
    for (int mt = 0; mt < 4; mt++) {
        size_t m0 = (size_t)(bm + wm + mt * 16 + fm);
#pragma unroll
        for (int nt = 0; nt < 4; nt++) {
            size_t n0 = (size_t)(nloc + wn + nt * 8 + (fkb >> 1));
            __half2 p01 = __floats2half2_rn(acc[mt][nt][0], acc[mt][nt][1]);
            __half2 p23 = __floats2half2_rn(acc[mt][nt][2], acc[mt][nt][3]);
            *(uint32_t*)((char*)C + (m0 * 1024 + n0) * 2) = *(uint32_t*)&p01;
            *(uint32_t*)((char*)C + ((m0 + 8) * 1024 + n0) * 2) = *(uint32_t*)&p23;
        }
    }
}

// ===========================================================================
// Flash attention, single-product fp16: S = Qh*Kh; O = Ph*Vh.
// ===========================================================================
#define A_QH 0
#define A_KB 17408
#define KV_STRIDE 17408
#define A_VB 52224
#define A_SS 87040
#define A_PH 104448
#define A_RM 113664
#define A_RL 113920
#define A_RA 114176
#define ATTN_SMEM 114432

__global__ __launch_bounds__(256, 1) void attn_tc(const float* __restrict__ mask,
                                                  float* __restrict__ out) {
    extern __shared__ char smc[];
    const uint32_t sb = smem_u32(smc);

    const int tid = threadIdx.x;
    const int lane = tid & 31, wid = tid >> 5;
    const int qt = blockIdx.x, h = blockIdx.y, b = blockIdx.z;
    const int wm = (wid & 3) * 16;
    const int wnS = (wid >> 2) * 32;
    const int wnV = (wid >> 2) * 64;
    const int fm = lane >> 2;

    const size_t bh_off = (size_t)b * TSEQ * DMOD + (size_t)h * DH;
    const __half* Qh = g_Qh + bh_off;
    const __half* Kh = g_Kh + bh_off;
    const __half* Vh = g_Vh + bh_off;

    const int kt0 = (qt == 15) ? 0 : qt;

    for (int c = tid; c < 1024; c += 256) {
        int r = c >> 4, o = c & 15;
        uint32_t d = (uint32_t)(r * 272 + o * 16);
        size_t g = (size_t)(qt * 64 + r) * DMOD + o * 8;
        cp16(sb + A_QH + d, Qh + g);
    }

#define ISSUE_KV(kt_, s_) do {                                           \
    uint32_t kst = sb + A_KB + (uint32_t)(s_) * KV_STRIDE;               \
    uint32_t vst = sb + A_VB + (uint32_t)(s_) * KV_STRIDE;               \
    size_t roff = (size_t)(kt_) * 64 * DMOD;                             \
    for (int c = tid; c < 1024; c += 256) {                              \
        int r = c >> 4, o = c & 15;                                      \
        uint32_t d = (uint32_t)(r * 272 + o * 16);                       \
        size_t g = roff + (size_t)r * DMOD + o * 8;                      \
        cp16(kst + d, Kh + g);                                           \
        cp16(vst + d, Vh + g);                                           \
    }                                                                    \
} while (0)

    ISSUE_KV(kt0, 0);
    CP_COMMIT();
    ISSUE_KV(kt0 + 1, 1);
    CP_COMMIT();

    float* rowm = (float*)(smc + A_RM);
    float* rowl = (float*)(smc + A_RL);
    float* rowa = (float*)(smc + A_RA);
    if (tid < 64) { rowm[tid] = -1e30f; rowl[tid] = 0.f; }

    float acc_o[8][4];
#pragma unroll
    for (int j = 0; j < 8; j++)
#pragma unroll
        for (int q = 0; q < 4; q++) acc_o[j][q] = 0.f;

    const int grp = lane >> 3, li = lane & 7;

    for (int kt = kt0; kt < 16; kt++) {
        const int p = (kt - kt0) & 1;
        if (kt == 15) { CP_WAIT(0); } else { CP_WAIT(1); }
        __syncthreads();

        const uint32_t kst = sb + A_KB + (uint32_t)p * KV_STRIDE;
        const uint32_t vst = sb + A_VB + (uint32_t)p * KV_STRIDE;

        float sacc[4][4];
#pragma unroll
        for (int j = 0; j < 4; j++)
#pragma unroll
            for (int q = 0; q < 4; q++) sacc[j][q] = 0.f;

#pragma unroll
        for (int ks = 0; ks < 8; ks++) {
            uint32_t ah[4];
            {
                uint32_t arow = (uint32_t)(wm + ((grp & 1) << 3) + li);
                uint32_t akb = (uint32_t)(ks * 32 + ((grp >> 1) << 4));
                LDMX4(ah, sb + A_QH + arow * 272 + akb);
            }
            uint32_t bh[2][4];
#pragma unroll
            for (int j2 = 0; j2 < 2; j2++) {
                uint32_t nrow = (uint32_t)(wnS + j2 * 16 + ((grp >> 1) << 3) + li);
                uint32_t kb = (uint32_t)(ks * 32 + ((grp & 1) << 4));
                LDMX4(bh[j2], kst + nrow * 272 + kb);
            }
#pragma unroll
            for (int j = 0; j < 4; j++)
                MMA_F16(sacc[j], ah, bh[j >> 1][(j & 1) * 2], bh[j >> 1][(j & 1) * 2 + 1]);
        }

        {
            const int r0 = wm + fm;
            const int qg0 = qt * 64 + r0, qg1 = qg0 + 8;
#pragma unroll
            for (int j = 0; j < 4; j++) {
                int col = wnS + 8 * j + 2 * (lane & 3);
                int kg = kt * 64 + col;
                float2 v01, v23;
                v01.x = sacc[j][0] * SCALE + ((kg     <= qg0) ? -10000.f : 0.f);
                v01.y = sacc[j][1] * SCALE + ((kg + 1 <= qg0) ? -10000.f : 0.f);
                v23.x = sacc[j][2] * SCALE + ((kg     <= qg1) ? -10000.f : 0.f);
                v23.y = sacc[j][3] * SCALE + ((kg + 1 <= qg1) ? -10000.f : 0.f);
                *(float2*)(smc + A_SS + (size_t)r0 * 272 + col * 4) = v01;
                *(float2*)(smc + A_SS + (size_t)(r0 + 8) * 272 + col * 4) = v23;
            }
        }
        __syncthreads();

        {
            const int row = tid >> 2, q = tid & 3;
            float* srow = (float*)(smc + A_SS + (size_t)row * 272) + (q << 4);
            float4 v0 = *(float4*)&srow[0];
            float4 v1 = *(float4*)&srow[4];
            float4 v2 = *(float4*)&srow[8];
            float4 v3 = *(float4*)&srow[12];
            float mloc = fmaxf(
                fmaxf(fmaxf(fmaxf(v0.x, v0.y), fmaxf(v0.z, v0.w)),
                      fmaxf(fmaxf(v1.x, v1.y), fmaxf(v1.z, v1.w))),
                fmaxf(fmaxf(fmaxf(v2.x, v2.y), fmaxf(v2.z, v2.w)),
                      fmaxf(fmaxf(v3.x, v3.y), fmaxf(v3.z, v3.w))));
            mloc = fmaxf(mloc, __shfl_xor_sync(0xffffffffu, mloc, 1));
            mloc = fmaxf(mloc, __shfl_xor_sync(0xffffffffu, mloc, 2));
            float mold = rowm[row];
            float mnew = fmaxf(mold, mloc);
            float alpha = __expf(mold - mnew);
            v0.x = __expf(v0.x - mnew); v0.y = __expf(v0.y - mnew);
            v0.z = __expf(v0.z - mnew); v0.w = __expf(v0.w - mnew);
            v1.x = __expf(v1.x - mnew); v1.y = __expf(v1.y - mnew);
            v1.z = __expf(v1.z - mnew); v1.w = __expf(v1.w - mnew);
            v2.x = __expf(v2.x - mnew); v2.y = __expf(v2.y - mnew);
            v2.z = __expf(v2.z - mnew); v2.w = __expf(v2.w - mnew);
            v3.x = __expf(v3.x - mnew); v3.y = __expf(v3.y - mnew);
            v3.z = __expf(v3.z - mnew); v3.w = __expf(v3.w - mnew);

            uint32_t* phr = (uint32_t*)(smc + A_PH + (size_t)row * 144) + (q << 3);
            const float4 vv[4] = {v0, v1, v2, v3};
#pragma unroll
            for (int u = 0; u < 4; u++) {
                __half2 hp01 = __floats2half2_rn(vv[u].x, vv[u].y);
                __half2 hp23 = __floats2half2_rn(vv[u].z, vv[u].w);
                phr[2 * u]     = *(uint32_t*)&hp01;
                phr[2 * u + 1] = *(uint32_t*)&hp23;
            }

            float ssum = (v0.x + v0.y + v0.z + v0.w) + (v1.x + v1.y + v1.z + v1.w) +
                         (v2.x + v2.y + v2.z + v2.w) + (v3.x + v3.y + v3.z + v3.w);
            ssum += __shfl_xor_sync(0xffffffffu, ssum, 1);
            ssum += __shfl_xor_sync(0xffffffffu, ssum, 2);
            if (q == 0) {
                rowl[row] = rowl[row] * alpha + ssum;
                rowm[row] = mnew;
                rowa[row] = alpha;
            }
        }
        __syncthreads();

        {
            float al0 = rowa[wm + fm], al1 = rowa[wm + fm + 8];
#pragma unroll
            for (int j = 0; j < 8; j++) {
                acc_o[j][0] *= al0; acc_o[j][1] *= al0;
                acc_o[j][2] *= al1; acc_o[j][3] *= al1;
            }
#pragma unroll
            for (int ks = 0; ks < 4; ks++) {
                uint32_t ph[4];
                {
                    uint32_t arow = (uint32_t)(wm + ((grp & 1) << 3) + li);
                    uint32_t akb = (uint32_t)(ks * 32 + ((grp >> 1) << 4));
                    LDMX4(ph, sb + A_PH + arow * 144 + akb);
                }
#pragma unroll
                for (int j2 = 0; j2 < 4; j2++) {
                    uint32_t bvh[4];
                    uint32_t krow = (uint32_t)(ks * 16 + ((grp & 1) << 3) + li);
                    uint32_t nb = (uint32_t)((wnV + 16 * j2 + ((grp >> 1) << 3)) * 2);
                    LDMX4T(bvh, vst + krow * 272 + nb);
#pragma unroll
                    for (int jj = 0; jj < 2; jj++) {
                        int j = 2 * j2 + jj;
                        MMA_F16(acc_o[j], ph, bvh[jj * 2], bvh[jj * 2 + 1]);
                    }
                }
            }
        }
        __syncthreads();

        if (kt + 2 <= 15) {
            ISSUE_KV(kt + 2, p);
            CP_COMMIT();
        }
    }

    {
        const int r0 = wm + fm;
        const int grow0 = b * TSEQ + qt * 64 + r0;
        float scl0 = (1.f / rowl[r0]) * mask[(size_t)b * TSEQ + qt * 64 + r0];
        float scl1 = (1.f / rowl[r0 + 8]) * mask[(size_t)b * TSEQ + qt * 64 + r0 + 8];
#pragma unroll
        for (int j = 0; j < 8; j++) {
            int col = h * DH + wnV + j * 8 + 2 * (lane & 3);
            float2 w0 = {acc_o[j][0] * scl0, acc_o[j][1] * scl0};
            float2 w1 = {acc_o[j][2] * scl1, acc_o[j][3] * scl1};
            *(float2*)&out[(size_t)grow0 * DMOD + col] = w0;
            *(float2*)&out[(size_t)(grow0 + 8) * DMOD + col] = w1;
        }
    }
}

extern "C" void kernel_launch(void* const* d_in, const int* in_sizes, int n_in,
                              void* d_out, int out_size) {
    const float* x    = (const float*)d_in[0];
    const float* mask = (const float*)d_in[1];
    const float* Wq   = (const float*)d_in[2];
    const float* Wk   = (const float*)d_in[3];
    const float* Wv   = (const float*)d_in[4];
    float* out = (float*)d_out;

    __half *xh, *wh, *qh, *kh, *vh;
    cudaGetSymbolAddress((void**)&xh, g_Xh);
    cudaGetSymbolAddress((void**)&wh, g_Wh);
    cudaGetSymbolAddress((void**)&qh, g_Qh);
    cudaGetSymbolAddress((void**)&kh, g_Kh);
    cudaGetSymbolAddress((void**)&vh, g_Vh);

    cudaFuncSetAttribute(gemm_qkv_f16, cudaFuncAttributeMaxDynamicSharedMemorySize,
                         GEMM_SMEM);
    cudaFuncSetAttribute(attn_tc, cudaFuncAttributeMaxDynamicSharedMemorySize,
                         ATTN_SMEM);

    const int xn4 = BATCH * TSEQ * DMOD / 4;
    const int wn4 = DMOD * DMOD / 4;
    cvt_f16<<<xn4 / 256, 256>>>((const float4*)x, (uint2*)xh);
    cvt_f16<<<wn4 / 256, 256>>>((const float4*)Wq, (uint2*)wh);
    cvt_f16<<<wn4 / 256, 256>>>((const float4*)Wk, (uint2*)(wh + DMOD * DMOD));
    cvt_f16<<<wn4 / 256, 256>>>((const float4*)Wv, (uint2*)(wh + 2 * DMOD * DMOD));

    dim3 ggrid(3 * DMOD / 128, (BATCH * TSEQ) / 128);
    gemm_qkv_f16<<<ggrid, 256, GEMM_SMEM>>>(xh, wh, qh, kh, vh);

    dim3 agrid(TSEQ / 64, NH, BATCH);
    attn_tc<<<agrid, 256, ATTN_SMEM>>>(mask, out);
}

// round 10
// speedup vs baseline: 5.9051x; 1.0212x over previous
#include <cuda_runtime.h>
#include <cuda_bf16.h>
#include <cuda_fp16.h>
#include <cstdint>

#define BATCH 8
#define TSEQ 1024
#define DMOD 1024
#define NH 8
#define DH 128
#define SCALE 0.08838834764831845f

// Scratch (device globals: allocation-free).
__device__ __half g_Xh[BATCH * TSEQ * DMOD];
__device__ __half g_Wh[3 * DMOD * DMOD];
__device__ __half g_Qh[BATCH * TSEQ * DMOD];
__device__ __half g_Kh[BATCH * TSEQ * DMOD];
__device__ __half g_Vh[BATCH * TSEQ * DMOD];

__device__ __forceinline__ uint32_t smem_u32(const void* p) {
    uint32_t a;
    asm("{ .reg .u64 t; cvta.to.shared.u64 t, %1; cvt.u32.u64 %0, t; }"
        : "=r"(a) : "l"(p));
    return a;
}
__device__ __forceinline__ void cp16(uint32_t dst, const void* src) {
    asm volatile("cp.async.cg.shared.global [%0], [%1], 16;"
                 :: "r"(dst), "l"(src) : "memory");
}
#define CP_COMMIT() asm volatile("cp.async.commit_group;" ::: "memory")
#define CP_WAIT(n)  asm volatile("cp.async.wait_group %0;" :: "n"(n) : "memory")

#define MMA_F16(c, a, b0_, b1_) \
    asm volatile("mma.sync.aligned.m16n8k16.row.col.f32.f16.f16.f32 " \
                 "{%0,%1,%2,%3}, {%4,%5,%6,%7}, {%8,%9}, {%0,%1,%2,%3};" \
                 : "+f"((c)[0]), "+f"((c)[1]), "+f"((c)[2]), "+f"((c)[3]) \
                 : "r"((a)[0]), "r"((a)[1]), "r"((a)[2]), "r"((a)[3]), \
                   "r"(b0_), "r"(b1_))

#define LDMX4(r, addr) \
    asm volatile("ldmatrix.sync.aligned.m8n8.x4.shared.b16 {%0,%1,%2,%3}, [%4];" \
                 : "=r"((r)[0]), "=r"((r)[1]), "=r"((r)[2]), "=r"((r)[3]) : "r"(addr))
#define LDMX4T(r, addr) \
    asm volatile("ldmatrix.sync.aligned.m8n8.x4.trans.shared.b16 {%0,%1,%2,%3}, [%4];" \
                 : "=r"((r)[0]), "=r"((r)[1]), "=r"((r)[2]), "=r"((r)[3]) : "r"(addr))

// ===========================================================================
// fp32 -> fp16 conversion kernels
// ===========================================================================
__global__ __launch_bounds__(256) void cvt_f16(const float4* __restrict__ src,
                                               uint2* __restrict__ dst) {
    int i = blockIdx.x * 256 + threadIdx.x;
    float4 v = src[i];
    __half2 p01 = __floats2half2_rn(v.x, v.y);
    __half2 p23 = __floats2half2_rn(v.z, v.w);
    uint2 H;
    H.x = *(uint32_t*)&p01;
    H.y = *(uint32_t*)&p23;
    dst[i] = H;
}

// All three weight matrices in one launch; blockIdx.y selects the source.
__global__ __launch_bounds__(256) void cvt_w3(const float4* __restrict__ w0,
                                              const float4* __restrict__ w1,
                                              const float4* __restrict__ w2,
                                              uint2* __restrict__ dst) {
    const float4* src = (blockIdx.y == 0) ? w0 : (blockIdx.y == 1) ? w1 : w2;
    int i = blockIdx.x * 256 + threadIdx.x;
    float4 v = src[i];
    __half2 p01 = __floats2half2_rn(v.x, v.y);
    __half2 p23 = __floats2half2_rn(v.z, v.w);
    uint2 H;
    H.x = *(uint32_t*)&p01;
    H.y = *(uint32_t*)&p23;
    dst[(size_t)blockIdx.y * (DMOD * DMOD / 4) + i] = H;
}

// ===========================================================================
// Fused QKV GEMM: [8192,3072] = X @ Wqkv^T, single-product fp16.
// 128x128 block, BK=32, 8 warps, 2-stage cp.async, 2 CTAs/SM.
// ===========================================================================
#define GTILE 10240
#define GSTAGE (2 * GTILE)
#define GEMM_SMEM (2 * GSTAGE)   // 40960 bytes

__global__ __launch_bounds__(256, 2) void gemm_qkv_f16(
    const __half* __restrict__ Xh, const __half* __restrict__ Wh,
    __half* __restrict__ qh, __half* __restrict__ kh, __half* __restrict__ vh) {
    extern __shared__ char smc[];
    const uint32_t sb = smem_u32(smc);

    const int tid = threadIdx.x;
    const int lane = tid & 31, wid = tid >> 5;
    const int bm = blockIdx.y << 7;
    const int bnG = blockIdx.x << 7;
    const int wm = (wid & 1) * 64, wn = (wid >> 1) * 32;
    const int fm = lane >> 2;
    const int fkb = (lane & 3) * 4;
    const int grp = lane >> 3, li = lane & 7;

    float acc[4][4][4];
#pragma unroll
    for (int i = 0; i < 4; i++)
#pragma unroll
        for (int j = 0; j < 4; j++)
#pragma unroll
            for (int q = 0; q < 4; q++) acc[i][j][q] = 0.f;

    const int c0row = tid >> 2;
    const int c1row = c0row + 64;
    const int ce = (tid & 3) * 8;
    const uint32_t d0 = (uint32_t)(c0row * 80 + (tid & 3) * 16);
    const uint32_t d1 = (uint32_t)(c1row * 80 + (tid & 3) * 16);

#define ISSUE_STAGE(kt, p) do {                                        \
    uint32_t s0 = sb + (p) * GSTAGE;                                   \
    size_t a0 = (size_t)(bm + c0row) * 1024 + (size_t)(kt) * 32 + ce;  \
    size_t a1 = (size_t)(bm + c1row) * 1024 + (size_t)(kt) * 32 + ce;  \
    size_t b0 = (size_t)(bnG + c0row) * 1024 + (size_t)(kt) * 32 + ce; \
    size_t b1 = (size_t)(bnG + c1row) * 1024 + (size_t)(kt) * 32 + ce; \
    cp16(s0 + d0,         Xh + a0);  cp16(s0 + d1,         Xh + a1);   \
    cp16(s0 + GTILE + d0, Wh + b0);  cp16(s0 + GTILE + d1, Wh + b1);   \
    CP_COMMIT();                                                       \
} while (0)

    ISSUE_STAGE(0, 0);

    for (int kt = 0; kt < 32; kt++) {
        const int p = kt & 1;
        if (kt < 31) {
            ISSUE_STAGE(kt + 1, p ^ 1);
            CP_WAIT(1);
        } else {
            CP_WAIT(0);
        }
        __syncthreads();

        const uint32_t st = sb + p * GSTAGE;
#pragma unroll
        for (int k16o = 0; k16o < 64; k16o += 32) {
            uint32_t ah[4][4], bh[2][4];
            const uint32_t akb = (uint32_t)(k16o + ((grp >> 1) << 4));
            const uint32_t bkb = (uint32_t)(k16o + ((grp & 1) << 4));
#pragma unroll
            for (int np = 0; np < 2; np++) {
                uint32_t nrow = (uint32_t)(wn + np * 16 + ((grp >> 1) << 3) + li);
                LDMX4(bh[np], st + GTILE + nrow * 80 + bkb);
            }
#pragma unroll
            for (int mt = 0; mt < 4; mt++) {
                uint32_t arow = (uint32_t)(wm + mt * 16 + ((grp & 1) << 3) + li);
                LDMX4(ah[mt], st + arow * 80 + akb);
            }
#pragma unroll
            for (int mt = 0; mt < 4; mt++)
#pragma unroll
                for (int nt = 0; nt < 4; nt++)
                    MMA_F16(acc[mt][nt], ah[mt], bh[nt >> 1][(nt & 1) * 2],
                            bh[nt >> 1][(nt & 1) * 2 + 1]);
        }
        __syncthreads();
    }

    const int which = bnG >> 10;
    const int nloc = bnG & 1023;
    __half* C = (which == 0) ? qh : (which == 1) ? kh : vh;

#pragma unroll
    for (int mt = 0; mt < 4; mt++) {
        size_t m0 = (size_t)(bm + wm + mt * 16 + fm);
#pragma unroll
        for (int nt = 0; nt < 4; nt++) {
            size_t n0 = (size_t)(nloc + wn + nt * 8 + (fkb >> 1));
            __half2 p01 = __floats2half2_rn(acc[mt][nt][0], acc[mt][nt][1]);
            __half2 p23 = __floats2half2_rn(acc[mt][nt][2], acc[mt][nt][3]);
            *(uint32_t*)((char*)C + (m0 * 1024 + n0) * 2) = *(uint32_t*)&p01;
            *(uint32_t*)((char*)C + ((m0 + 8) * 1024 + n0) * 2) = *(uint32_t*)&p23;
        }
    }
}

// ===========================================================================
// Flash attention, single-product fp16: S = Qh*Kh; O = Ph*Vh.
// 2 CTAs/SM target; heavy q-tiles (qt=15, qt=0) scheduled first.
// ===========================================================================
#define A_QH 0
#define A_KB 17408
#define KV_STRIDE 17408
#define A_VB 52224
#define A_SS 87040
#define A_PH 104448
#define A_RM 113664
#define A_RL 113920
#define A_RA 114176
#define ATTN_SMEM 114432

__global__ __launch_bounds__(256, 2) void attn_tc(const float* __restrict__ mask,
                                                  float* __restrict__ out) {
    extern __shared__ char smc[];
    const uint32_t sb = smem_u32(smc);

    const int tid = threadIdx.x;
    const int lane = tid & 31, wid = tid >> 5;
    // Heaviest blocks first: qt=15 (full causal wrap) launches at bx=0.
    const int qt = (blockIdx.x == 0) ? 15 : (int)blockIdx.x - 1;
    const int h = blockIdx.y, b = blockIdx.z;
    const int wm = (wid & 3) * 16;
    const int wnS = (wid >> 2) * 32;
    const int wnV = (wid >> 2) * 64;
    const int fm = lane >> 2;

    const size_t bh_off = (size_t)b * TSEQ * DMOD + (size_t)h * DH;
    const __half* Qh = g_Qh + bh_off;
    const __half* Kh = g_Kh + bh_off;
    const __half* Vh = g_Vh + bh_off;

    const int kt0 = (qt == 15) ? 0 : qt;

    for (int c = tid; c < 1024; c += 256) {
        int r = c >> 4, o = c & 15;
        uint32_t d = (uint32_t)(r * 272 + o * 16);
        size_t g = (size_t)(qt * 64 + r) * DMOD + o * 8;
        cp16(sb + A_QH + d, Qh + g);
    }

#define ISSUE_KV(kt_, s_) do {                                           \
    uint32_t kst = sb + A_KB + (uint32_t)(s_) * KV_STRIDE;               \
    uint32_t vst = sb + A_VB + (uint32_t)(s_) * KV_STRIDE;               \
    size_t roff = (size_t)(kt_) * 64 * DMOD;                             \
    for (int c = tid; c < 1024; c += 256) {                              \
        int r = c >> 4, o = c & 15;                                      \
        uint32_t d = (uint32_t)(r * 272 + o * 16);                       \
        size_t g = roff + (size_t)r * DMOD + o * 8;                      \
        cp16(kst + d, Kh + g);                                           \
        cp16(vst + d, Vh + g);                                           \
    }                                                                    \
} while (0)

    ISSUE_KV(kt0, 0);
    CP_COMMIT();
    ISSUE_KV(kt0 + 1, 1);
    CP_COMMIT();

    float* rowm = (float*)(smc + A_RM);
    float* rowl = (float*)(smc + A_RL);
    float* rowa = (float*)(smc + A_RA);
    if (tid < 64) { rowm[tid] = -1e30f; rowl[tid] = 0.f; }

    float acc_o[8][4];
#pragma unroll
    for (int j = 0; j < 8; j++)
#pragma unroll
        for (int q = 0; q < 4; q++) acc_o[j][q] = 0.f;

    const int grp = lane >> 3, li = lane & 7;

    for (int kt = kt0; kt < 16; kt++) {
        const int p = (kt - kt0) & 1;
        if (kt == 15) { CP_WAIT(0); } else { CP_WAIT(1); }
        __syncthreads();

        const uint32_t kst = sb + A_KB + (uint32_t)p * KV_STRIDE;
        const uint32_t vst = sb + A_VB + (uint32_t)p * KV_STRIDE;

        float sacc[4][4];
#pragma unroll
        for (int j = 0; j < 4; j++)
#pragma unroll
            for (int q = 0; q < 4; q++) sacc[j][q] = 0.f;

#pragma unroll
        for (int ks = 0; ks < 8; ks++) {
            uint32_t ah[4];
            {
                uint32_t arow = (uint32_t)(wm + ((grp & 1) << 3) + li);
                uint32_t akb = (uint32_t)(ks * 32 + ((grp >> 1) << 4));
                LDMX4(ah, sb + A_QH + arow * 272 + akb);
            }
            uint32_t bh[2][4];
#pragma unroll
            for (int j2 = 0; j2 < 2; j2++) {
                uint32_t nrow = (uint32_t)(wnS + j2 * 16 + ((grp >> 1) << 3) + li);
                uint32_t kb = (uint32_t)(ks * 32 + ((grp & 1) << 4));
                LDMX4(bh[j2], kst + nrow * 272 + kb);
            }
#pragma unroll
            for (int j = 0; j < 4; j++)
                MMA_F16(sacc[j], ah, bh[j >> 1][(j & 1) * 2], bh[j >> 1][(j & 1) * 2 + 1]);
        }

        {
            const int r0 = wm + fm;
            const int qg0 = qt * 64 + r0, qg1 = qg0 + 8;
#pragma unroll
            for (int j = 0; j < 4; j++) {
                int col = wnS + 8 * j + 2 * (lane & 3);
                int kg = kt * 64 + col;
                float2 v01, v23;
                v01.x = sacc[j][0] * SCALE + ((kg     <= qg0) ? -10000.f : 0.f);
                v01.y = sacc[j][1] * SCALE + ((kg + 1 <= qg0) ? -10000.f : 0.f);
                v23.x = sacc[j][2] * SCALE + ((kg     <= qg1) ? -10000.f : 0.f);
                v23.y = sacc[j][3] * SCALE + ((kg + 1 <= qg1) ? -10000.f : 0.f);
                *(float2*)(smc + A_SS + (size_t)r0 * 272 + col * 4) = v01;
                *(float2*)(smc + A_SS + (size_t)(r0 + 8) * 272 + col * 4) = v23;
            }
        }
        __syncthreads();

        {
            const int row = tid >> 2, q = tid & 3;
            float* srow = (float*)(smc + A_SS + (size_t)row * 272) + (q << 4);
            float4 v0 = *(float4*)&srow[0];
            float4 v1 = *(float4*)&srow[4];
            float4 v2 = *(float4*)&srow[8];
            float4 v3 = *(float4*)&srow[12];
            float mloc = fmaxf(
                fmaxf(fmaxf(fmaxf(v0.x, v0.y), fmaxf(v0.z, v0.w)),
                      fmaxf(fmaxf(v1.x, v1.y), fmaxf(v1.z, v1.w))),
                fmaxf(fmaxf(fmaxf(v2.x, v2.y), fmaxf(v2.z, v2.w)),
                      fmaxf(fmaxf(v3.x, v3.y), fmaxf(v3.z, v3.w))));
            mloc = fmaxf(mloc, __shfl_xor_sync(0xffffffffu, mloc, 1));
            mloc = fmaxf(mloc, __shfl_xor_sync(0xffffffffu, mloc, 2));
            float mold = rowm[row];
            float mnew = fmaxf(mold, mloc);
            float alpha = __expf(mold - mnew);
            v0.x = __expf(v0.x - mnew); v0.y = __expf(v0.y - mnew);
            v0.z = __expf(v0.z - mnew); v0.w = __expf(v0.w - mnew);
            v1.x = __expf(v1.x - mnew); v1.y = __expf(v1.y - mnew);
            v1.z = __expf(v1.z - mnew); v1.w = __expf(v1.w - mnew);
            v2.x = __expf(v2.x - mnew); v2.y = __expf(v2.y - mnew);
            v2.z = __expf(v2.z - mnew); v2.w = __expf(v2.w - mnew);
            v3.x = __expf(v3.x - mnew); v3.y = __expf(v3.y - mnew);
            v3.z = __expf(v3.z - mnew); v3.w = __expf(v3.w - mnew);

            uint32_t* phr = (uint32_t*)(smc + A_PH + (size_t)row * 144) + (q << 3);
            const float4 vv[4] = {v0, v1, v2, v3};
#pragma unroll
            for (int u = 0; u < 4; u++) {
                __half2 hp01 = __floats2half2_rn(vv[u].x, vv[u].y);
                __half2 hp23 = __floats2half2_rn(vv[u].z, vv[u].w);
                phr[2 * u]     = *(uint32_t*)&hp01;
                phr[2 * u + 1] = *(uint32_t*)&hp23;
            }

            float ssum = (v0.x + v0.y + v0.z + v0.w) + (v1.x + v1.y + v1.z + v1.w) +
                         (v2.x + v2.y + v2.z + v2.w) + (v3.x + v3.y + v3.z + v3.w);
            ssum += __shfl_xor_sync(0xffffffffu, ssum, 1);
            ssum += __shfl_xor_sync(0xffffffffu, ssum, 2);
            if (q == 0) {
                rowl[row] = rowl[row] * alpha + ssum;
                rowm[row] = mnew;
                rowa[row] = alpha;
            }
        }
        __syncthreads();

        {
            float al0 = rowa[wm + fm], al1 = rowa[wm + fm + 8];
#pragma unroll
            for (int j = 0; j < 8; j++) {
                acc_o[j][0] *= al0; acc_o[j][1] *= al0;
                acc_o[j][2] *= al1; acc_o[j][3] *= al1;
            }
#pragma unroll
            for (int ks = 0; ks < 4; ks++) {
                uint32_t ph[4];
                {
                    uint32_t arow = (uint32_t)(wm + ((grp & 1) << 3) + li);
                    uint32_t akb = (uint32_t)(ks * 32 + ((grp >> 1) << 4));
                    LDMX4(ph, sb + A_PH + arow * 144 + akb);
                }
#pragma unroll
                for (int j2 = 0; j2 < 4; j2++) {
                    uint32_t bvh[4];
                    uint32_t krow = (uint32_t)(ks * 16 + ((grp & 1) << 3) + li);
                    uint32_t nb = (uint32_t)((wnV + 16 * j2 + ((grp >> 1) << 3)) * 2);
                    LDMX4T(bvh, vst + krow * 272 + nb);
#pragma unroll
                    for (int jj = 0; jj < 2; jj++) {
                        int j = 2 * j2 + jj;
                        MMA_F16(acc_o[j], ph, bvh[jj * 2], bvh[jj * 2 + 1]);
                    }
                }
            }
        }
        __syncthreads();

        if (kt + 2 <= 15) {
            ISSUE_KV(kt + 2, p);
            CP_COMMIT();
        }
    }

    {
        const int r0 = wm + fm;
        const int grow0 = b * TSEQ + qt * 64 + r0;
        float scl0 = (1.f / rowl[r0]) * mask[(size_t)b * TSEQ + qt * 64 + r0];
        float scl1 = (1.f / rowl[r0 + 8]) * mask[(size_t)b * TSEQ + qt * 64 + r0 + 8];
#pragma unroll
        for (int j = 0; j < 8; j++) {
            int col = h * DH + wnV + j * 8 + 2 * (lane & 3);
            float2 w0 = {acc_o[j][0] * scl0, acc_o[j][1] * scl0};
            float2 w1 = {acc_o[j][2] * scl1, acc_o[j][3] * scl1};
            *(float2*)&out[(size_t)grow0 * DMOD + col] = w0;
            *(float2*)&out[(size_t)(grow0 + 8) * DMOD + col] = w1;
        }
    }
}

extern "C" void kernel_launch(void* const* d_in, const int* in_sizes, int n_in,
                              void* d_out, int out_size) {
    const float* x    = (const float*)d_in[0];
    const float* mask = (const float*)d_in[1];
    const float* Wq   = (const float*)d_in[2];
    const float* Wk   = (const float*)d_in[3];
    const float* Wv   = (const float*)d_in[4];
    float* out = (float*)d_out;

    __half *xh, *wh, *qh, *kh, *vh;
    cudaGetSymbolAddress((void**)&xh, g_Xh);
    cudaGetSymbolAddress((void**)&wh, g_Wh);
    cudaGetSymbolAddress((void**)&qh, g_Qh);
    cudaGetSymbolAddress((void**)&kh, g_Kh);
    cudaGetSymbolAddress((void**)&vh, g_Vh);

    cudaFuncSetAttribute(gemm_qkv_f16, cudaFuncAttributeMaxDynamicSharedMemorySize,
                         GEMM_SMEM);
    cudaFuncSetAttribute(attn_tc, cudaFuncAttributeMaxDynamicSharedMemorySize,
                         ATTN_SMEM);

    const int xn4 = BATCH * TSEQ * DMOD / 4;
    const int wn4 = DMOD * DMOD / 4;
    cvt_f16<<<xn4 / 256, 256>>>((const float4*)x, (uint2*)xh);
    dim3 wgrid(wn4 / 256, 3);
    cvt_w3<<<wgrid, 256>>>((const float4*)Wq, (const float4*)Wk,
                           (const float4*)Wv, (uint2*)wh);

    dim3 ggrid(3 * DMOD / 128, (BATCH * TSEQ) / 128);
    gemm_qkv_f16<<<ggrid, 256, GEMM_SMEM>>>(xh, wh, qh, kh, vh);

    dim3 agrid(TSEQ / 64, NH, BATCH);
    attn_tc<<<agrid, 256, ATTN_SMEM>>>(mask, out);
}

// round 11
// speedup vs baseline: 6.1930x; 1.0488x over previous
#include <cuda_runtime.h>
#include <cuda_bf16.h>
#include <cuda_fp16.h>
#include <cstdint>

#define BATCH 8
#define TSEQ 1024
#define DMOD 1024
#define NH 8
#define DH 128
#define SCALE 0.08838834764831845f

// Scratch (device globals: allocation-free).
__device__ __half g_Xh[BATCH * TSEQ * DMOD];
__device__ __half g_Wh[3 * DMOD * DMOD];
__device__ __half g_Qh[BATCH * TSEQ * DMOD];
__device__ __half g_Kh[BATCH * TSEQ * DMOD];
__device__ __half g_Vh[BATCH * TSEQ * DMOD];

__device__ __forceinline__ uint32_t smem_u32(const void* p) {
    uint32_t a;
    asm("{ .reg .u64 t; cvta.to.shared.u64 t, %1; cvt.u32.u64 %0, t; }"
        : "=r"(a) : "l"(p));
    return a;
}
__device__ __forceinline__ void cp16(uint32_t dst, const void* src) {
    asm volatile("cp.async.cg.shared.global [%0], [%1], 16;"
                 :: "r"(dst), "l"(src) : "memory");
}
#define CP_COMMIT() asm volatile("cp.async.commit_group;" ::: "memory")
#define CP_WAIT(n)  asm volatile("cp.async.wait_group %0;" :: "n"(n) : "memory")

#define MMA_F16(c, a, b0_, b1_) \
    asm volatile("mma.sync.aligned.m16n8k16.row.col.f32.f16.f16.f32 " \
                 "{%0,%1,%2,%3}, {%4,%5,%6,%7}, {%8,%9}, {%0,%1,%2,%3};" \
                 : "+f"((c)[0]), "+f"((c)[1]), "+f"((c)[2]), "+f"((c)[3]) \
                 : "r"((a)[0]), "r"((a)[1]), "r"((a)[2]), "r"((a)[3]), \
                   "r"(b0_), "r"(b1_))

#define LDMX4(r, addr) \
    asm volatile("ldmatrix.sync.aligned.m8n8.x4.shared.b16 {%0,%1,%2,%3}, [%4];" \
                 : "=r"((r)[0]), "=r"((r)[1]), "=r"((r)[2]), "=r"((r)[3]) : "r"(addr))
#define LDMX4T(r, addr) \
    asm volatile("ldmatrix.sync.aligned.m8n8.x4.trans.shared.b16 {%0,%1,%2,%3}, [%4];" \
                 : "=r"((r)[0]), "=r"((r)[1]), "=r"((r)[2]), "=r"((r)[3]) : "r"(addr))

// ===========================================================================
// fp32 -> fp16 conversion kernels
// ===========================================================================
__global__ __launch_bounds__(256) void cvt_f16(const float4* __restrict__ src,
                                               uint2* __restrict__ dst) {
    int i = blockIdx.x * 256 + threadIdx.x;
    float4 v = src[i];
    __half2 p01 = __floats2half2_rn(v.x, v.y);
    __half2 p23 = __floats2half2_rn(v.z, v.w);
    uint2 H;
    H.x = *(uint32_t*)&p01;
    H.y = *(uint32_t*)&p23;
    dst[i] = H;
}

__global__ __launch_bounds__(256) void cvt_w3(const float4* __restrict__ w0,
                                              const float4* __restrict__ w1,
                                              const float4* __restrict__ w2,
                                              uint2* __restrict__ dst) {
    const float4* src = (blockIdx.y == 0) ? w0 : (blockIdx.y == 1) ? w1 : w2;
    int i = blockIdx.x * 256 + threadIdx.x;
    float4 v = src[i];
    __half2 p01 = __floats2half2_rn(v.x, v.y);
    __half2 p23 = __floats2half2_rn(v.z, v.w);
    uint2 H;
    H.x = *(uint32_t*)&p01;
    H.y = *(uint32_t*)&p23;
    dst[(size_t)blockIdx.y * (DMOD * DMOD / 4) + i] = H;
}

// ===========================================================================
// Fused QKV GEMM (unchanged — at mma.sync floor)
// ===========================================================================
#define GTILE 10240
#define GSTAGE (2 * GTILE)
#define GEMM_SMEM (2 * GSTAGE)

__global__ __launch_bounds__(256, 2) void gemm_qkv_f16(
    const __half* __restrict__ Xh, const __half* __restrict__ Wh,
    __half* __restrict__ qh, __half* __restrict__ kh, __half* __restrict__ vh) {
    extern __shared__ char smc[];
    const uint32_t sb = smem_u32(smc);

    const int tid = threadIdx.x;
    const int lane = tid & 31, wid = tid >> 5;
    const int bm = blockIdx.y << 7;
    const int bnG = blockIdx.x << 7;
    const int wm = (wid & 1) * 64, wn = (wid >> 1) * 32;
    const int fm = lane >> 2;
    const int fkb = (lane & 3) * 4;
    const int grp = lane >> 3, li = lane & 7;

    float acc[4][4][4];
#pragma unroll
    for (int i = 0; i < 4; i++)
#pragma unroll
        for (int j = 0; j < 4; j++)
#pragma unroll
            for (int q = 0; q < 4; q++) acc[i][j][q] = 0.f;

    const int c0row = tid >> 2;
    const int c1row = c0row + 64;
    const int ce = (tid & 3) * 8;
    const uint32_t d0 = (uint32_t)(c0row * 80 + (tid & 3) * 16);
    const uint32_t d1 = (uint32_t)(c1row * 80 + (tid & 3) * 16);

#define ISSUE_STAGE(kt, p) do {                                        \
    uint32_t s0 = sb + (p) * GSTAGE;                                   \
    size_t a0 = (size_t)(bm + c0row) * 1024 + (size_t)(kt) * 32 + ce;  \
    size_t a1 = (size_t)(bm + c1row) * 1024 + (size_t)(kt) * 32 + ce;  \
    size_t b0 = (size_t)(bnG + c0row) * 1024 + (size_t)(kt) * 32 + ce; \
    size_t b1 = (size_t)(bnG + c1row) * 1024 + (size_t)(kt) * 32 + ce; \
    cp16(s0 + d0,         Xh + a0);  cp16(s0 + d1,         Xh + a1);   \
    cp16(s0 + GTILE + d0, Wh + b0);  cp16(s0 + GTILE + d1, Wh + b1);   \
    CP_COMMIT();                                                       \
} while (0)

    ISSUE_STAGE(0, 0);

    for (int kt = 0; kt < 32; kt++) {
        const int p = kt & 1;
        if (kt < 31) {
            ISSUE_STAGE(kt + 1, p ^ 1);
            CP_WAIT(1);
        } else {
            CP_WAIT(0);
        }
        __syncthreads();

        const uint32_t st = sb + p * GSTAGE;
#pragma unroll
        for (int k16o = 0; k16o < 64; k16o += 32) {
            uint32_t ah[4][4], bh[2][4];
            const uint32_t akb = (uint32_t)(k16o + ((grp >> 1) << 4));
            const uint32_t bkb = (uint32_t)(k16o + ((grp & 1) << 4));
#pragma unroll
            for (int np = 0; np < 2; np++) {
                uint32_t nrow = (uint32_t)(wn + np * 16 + ((grp >> 1) << 3) + li);
                LDMX4(bh[np], st + GTILE + nrow * 80 + bkb);
            }
#pragma unroll
            for (int mt = 0; mt < 4; mt++) {
                uint32_t arow = (uint32_t)(wm + mt * 16 + ((grp & 1) << 3) + li);
                LDMX4(ah[mt], st + arow * 80 + akb);
            }
#pragma unroll
            for (int mt = 0; mt < 4; mt++)
#pragma unroll
                for (int nt = 0; nt < 4; nt++)
                    MMA_F16(acc[mt][nt], ah[mt], bh[nt >> 1][(nt & 1) * 2],
                            bh[nt >> 1][(nt & 1) * 2 + 1]);
        }
        __syncthreads();
    }

    const int which = bnG >> 10;
    const int nloc = bnG & 1023;
    __half* C = (which == 0) ? qh : (which == 1) ? kh : vh;

#pragma unroll
    for (int mt = 0; mt < 4; mt++) {
        size_t m0 = (size_t)(bm + wm + mt * 16 + fm);
#pragma unroll
        for (int nt = 0; nt < 4; nt++) {
            size_t n0 = (size_t)(nloc + wn + nt * 8 + (fkb >> 1));
            __half2 p01 = __floats2half2_rn(acc[mt][nt][0], acc[mt][nt][1]);
            __half2 p23 = __floats2half2_rn(acc[mt][nt][2], acc[mt][nt][3]);
            *(uint32_t*)((char*)C + (m0 * 1024 + n0) * 2) = *(uint32_t*)&p01;
            *(uint32_t*)((char*)C + ((m0 + 8) * 1024 + n0) * 2) = *(uint32_t*)&p23;
        }
    }
}

// ===========================================================================
// Flash attention, register-resident softmax.
// S kept in MMA fragments; row stats via tiny smem arrays; own P half
// repacked in-register as PV A-fragments; partner half via smem + ldmatrix.
// ===========================================================================
#define A_QH 0
#define A_KB 17408
#define KV_STRIDE 17408
#define A_VB 52224
#define A_PH 87040          // P fp16 [64][72] (144B rows)
#define A_MX 96256          // float [2][64] per-warpgroup row max
#define A_SU 96768          // float [2][64] per-warpgroup row sum
#define A_RM 97280          // float [64] running max
#define A_RL 97536          // float [64] running denom
#define ATTN_SMEM 97792

__global__ __launch_bounds__(256, 2) void attn_tc(const float* __restrict__ mask,
                                                  float* __restrict__ out) {
    extern __shared__ char smc[];
    const uint32_t sb = smem_u32(smc);

    const int tid = threadIdx.x;
    const int lane = tid & 31, wid = tid >> 5;
    const int qt = (blockIdx.x == 0) ? 15 : (int)blockIdx.x - 1;
    const int h = blockIdx.y, b = blockIdx.z;
    const int wm = (wid & 3) * 16;
    const int cg = wid >> 2;           // col-group: S cols / P k-half
    const int wnS = cg * 32;
    const int wnV = cg * 64;
    const int fm = lane >> 2, q = lane & 3;
    const int grp = lane >> 3, li = lane & 7;

    const size_t bh_off = (size_t)b * TSEQ * DMOD + (size_t)h * DH;
    const __half* Qh = g_Qh + bh_off;
    const __half* Kh = g_Kh + bh_off;
    const __half* Vh = g_Vh + bh_off;

    const int kt0 = (qt == 15) ? 0 : qt;

    for (int c = tid; c < 1024; c += 256) {
        int r = c >> 4, o = c & 15;
        uint32_t d = (uint32_t)(r * 272 + o * 16);
        size_t g = (size_t)(qt * 64 + r) * DMOD + o * 8;
        cp16(sb + A_QH + d, Qh + g);
    }

#define ISSUE_KV(kt_, s_) do {                                           \
    uint32_t kst = sb + A_KB + (uint32_t)(s_) * KV_STRIDE;               \
    uint32_t vst = sb + A_VB + (uint32_t)(s_) * KV_STRIDE;               \
    size_t roff = (size_t)(kt_) * 64 * DMOD;                             \
    for (int c = tid; c < 1024; c += 256) {                              \
        int r = c >> 4, o = c & 15;                                      \
        uint32_t d = (uint32_t)(r * 272 + o * 16);                       \
        size_t g = roff + (size_t)r * DMOD + o * 8;                      \
        cp16(kst + d, Kh + g);                                           \
        cp16(vst + d, Vh + g);                                           \
    }                                                                    \
} while (0)

    ISSUE_KV(kt0, 0);
    CP_COMMIT();
    ISSUE_KV(kt0 + 1, 1);
    CP_COMMIT();

    float* MX   = (float*)(smc + A_MX);   // MX[cg*64 + row]
    float* SU   = (float*)(smc + A_SU);
    float* rowm = (float*)(smc + A_RM);
    float* rowl = (float*)(smc + A_RL);
    if (tid < 64) { rowm[tid] = -1e30f; rowl[tid] = 0.f; }

    float acc_o[8][4];
#pragma unroll
    for (int j = 0; j < 8; j++)
#pragma unroll
        for (int qq = 0; qq < 4; qq++) acc_o[j][qq] = 0.f;

    const int r0 = wm + fm, r1 = r0 + 8;

    for (int kt = kt0; kt < 16; kt++) {
        const int p = (kt - kt0) & 1;
        if (kt == 15) { CP_WAIT(0); } else { CP_WAIT(1); }
        __syncthreads();                               // sync0: K/V stage ready

        const uint32_t kst = sb + A_KB + (uint32_t)p * KV_STRIDE;
        const uint32_t vst = sb + A_VB + (uint32_t)p * KV_STRIDE;

        // ---- S = Qh * Kh^T (registers) ----
        float sacc[4][4];
#pragma unroll
        for (int j = 0; j < 4; j++)
#pragma unroll
            for (int qq = 0; qq < 4; qq++) sacc[j][qq] = 0.f;

#pragma unroll
        for (int ks = 0; ks < 8; ks++) {
            uint32_t ah[4];
            {
                uint32_t arow = (uint32_t)(wm + ((grp & 1) << 3) + li);
                uint32_t akb = (uint32_t)(ks * 32 + ((grp >> 1) << 4));
                LDMX4(ah, sb + A_QH + arow * 272 + akb);
            }
            uint32_t bh[2][4];
#pragma unroll
            for (int j2 = 0; j2 < 2; j2++) {
                uint32_t nrow = (uint32_t)(wnS + j2 * 16 + ((grp >> 1) << 3) + li);
                uint32_t kb = (uint32_t)(ks * 32 + ((grp & 1) << 4));
                LDMX4(bh[j2], kst + nrow * 272 + kb);
            }
#pragma unroll
            for (int j = 0; j < 4; j++)
                MMA_F16(sacc[j], ah, bh[j >> 1][(j & 1) * 2], bh[j >> 1][(j & 1) * 2 + 1]);
        }

        // ---- scale + causal mask, in fragments ----
        {
            const int qg0 = qt * 64 + r0, qg1 = qg0 + 8;
#pragma unroll
            for (int j = 0; j < 4; j++) {
                int kg = kt * 64 + wnS + 8 * j + 2 * q;
                sacc[j][0] = sacc[j][0] * SCALE + ((kg     <= qg0) ? -10000.f : 0.f);
                sacc[j][1] = sacc[j][1] * SCALE + ((kg + 1 <= qg0) ? -10000.f : 0.f);
                sacc[j][2] = sacc[j][2] * SCALE + ((kg     <= qg1) ? -10000.f : 0.f);
                sacc[j][3] = sacc[j][3] * SCALE + ((kg + 1 <= qg1) ? -10000.f : 0.f);
            }
        }

        // ---- local row max over this warp's 32 cols ----
        float m0 = fmaxf(fmaxf(sacc[0][0], sacc[0][1]), fmaxf(sacc[1][0], sacc[1][1]));
        m0 = fmaxf(m0, fmaxf(fmaxf(sacc[2][0], sacc[2][1]), fmaxf(sacc[3][0], sacc[3][1])));
        float m1 = fmaxf(fmaxf(sacc[0][2], sacc[0][3]), fmaxf(sacc[1][2], sacc[1][3]));
        m1 = fmaxf(m1, fmaxf(fmaxf(sacc[2][2], sacc[2][3]), fmaxf(sacc[3][2], sacc[3][3])));
        m0 = fmaxf(m0, __shfl_xor_sync(0xffffffffu, m0, 1));
        m0 = fmaxf(m0, __shfl_xor_sync(0xffffffffu, m0, 2));
        m1 = fmaxf(m1, __shfl_xor_sync(0xffffffffu, m1, 1));
        m1 = fmaxf(m1, __shfl_xor_sync(0xffffffffu, m1, 2));
        if (q == 0) { MX[cg * 64 + r0] = m0; MX[cg * 64 + r1] = m1; }
        __syncthreads();                               // sync1: maxes visible

        const float mold0 = rowm[r0], mold1 = rowm[r1];
        const float mn0 = fmaxf(mold0, fmaxf(MX[r0], MX[64 + r0]));
        const float mn1 = fmaxf(mold1, fmaxf(MX[r1], MX[64 + r1]));
        const float alpha0 = __expf(mold0 - mn0);
        const float alpha1 = __expf(mold1 - mn1);

        // ---- exp in fragments; pack own P half as PV A-frags; write to smem ----
        uint32_t pf[2][4];
        float s0 = 0.f, s1 = 0.f;
#pragma unroll
        for (int j = 0; j < 4; j++) {
            float p0 = __expf(sacc[j][0] - mn0);
            float p1 = __expf(sacc[j][1] - mn0);
            float p2 = __expf(sacc[j][2] - mn1);
            float p3 = __expf(sacc[j][3] - mn1);
            s0 += p0 + p1;
            s1 += p2 + p3;
            __half2 h01 = __floats2half2_rn(p0, p1);
            __half2 h23 = __floats2half2_rn(p2, p3);
            pf[j >> 1][((j & 1) << 1) + 0] = *(uint32_t*)&h01;
            pf[j >> 1][((j & 1) << 1) + 1] = *(uint32_t*)&h23;
            uint32_t cb = (uint32_t)((wnS + 8 * j + 2 * q) * 2);
            *(uint32_t*)(smc + A_PH + (size_t)r0 * 144 + cb) = *(uint32_t*)&h01;
            *(uint32_t*)(smc + A_PH + (size_t)r1 * 144 + cb) = *(uint32_t*)&h23;
        }
        s0 += __shfl_xor_sync(0xffffffffu, s0, 1);
        s0 += __shfl_xor_sync(0xffffffffu, s0, 2);
        s1 += __shfl_xor_sync(0xffffffffu, s1, 1);
        s1 += __shfl_xor_sync(0xffffffffu, s1, 2);
        if (q == 0) { SU[cg * 64 + r0] = s0; SU[cg * 64 + r1] = s1; }
        __syncthreads();                               // sync2: P + sums ready

        if (cg == 0 && q == 0) {
            rowl[r0] = rowl[r0] * alpha0 + SU[r0] + SU[64 + r0];
            rowl[r1] = rowl[r1] * alpha1 + SU[r1] + SU[64 + r1];
            rowm[r0] = mn0;
            rowm[r1] = mn1;
        }

        // ---- O = O*alpha + P * Vh ----
#pragma unroll
        for (int j = 0; j < 8; j++) {
            acc_o[j][0] *= alpha0; acc_o[j][1] *= alpha0;
            acc_o[j][2] *= alpha1; acc_o[j][3] *= alpha1;
        }
#pragma unroll
        for (int kc = 0; kc < 4; kc++) {
            uint32_t ph[4];
            if ((kc >> 1) == cg) {
                ph[0] = pf[kc & 1][0]; ph[1] = pf[kc & 1][1];
                ph[2] = pf[kc & 1][2]; ph[3] = pf[kc & 1][3];
            } else {
                uint32_t arow = (uint32_t)(wm + ((grp & 1) << 3) + li);
                uint32_t akb = (uint32_t)(kc * 32 + ((grp >> 1) << 4));
                LDMX4(ph, sb + A_PH + arow * 144 + akb);
            }
#pragma unroll
            for (int j2 = 0; j2 < 4; j2++) {
                uint32_t bvh[4];
                uint32_t krow = (uint32_t)(kc * 16 + ((grp & 1) << 3) + li);
                uint32_t nb = (uint32_t)((wnV + 16 * j2 + ((grp >> 1) << 3)) * 2);
                LDMX4T(bvh, vst + krow * 272 + nb);
#pragma unroll
                for (int jj = 0; jj < 2; jj++) {
                    int j = 2 * j2 + jj;
                    MMA_F16(acc_o[j], ph, bvh[jj * 2], bvh[jj * 2 + 1]);
                }
            }
        }
        __syncthreads();                               // sync3: stage consumed

        if (kt + 2 <= 15) {
            ISSUE_KV(kt + 2, p);
            CP_COMMIT();
        }
    }

    {
        const int grow0 = b * TSEQ + qt * 64 + r0;
        float scl0 = (1.f / rowl[r0]) * mask[(size_t)b * TSEQ + qt * 64 + r0];
        float scl1 = (1.f / rowl[r1]) * mask[(size_t)b * TSEQ + qt * 64 + r1];
#pragma unroll
        for (int j = 0; j < 8; j++) {
            int col = h * DH + wnV + j * 8 + 2 * q;
            float2 w0 = {acc_o[j][0] * scl0, acc_o[j][1] * scl0};
            float2 w1 = {acc_o[j][2] * scl1, acc_o[j][3] * scl1};
            *(float2*)&out[(size_t)grow0 * DMOD + col] = w0;
            *(float2*)&out[(size_t)(grow0 + 8) * DMOD + col] = w1;
        }
    }
}

extern "C" void kernel_launch(void* const* d_in, const int* in_sizes, int n_in,
                              void* d_out, int out_size) {
    const float* x    = (const float*)d_in[0];
    const float* mask = (const float*)d_in[1];
    const float* Wq   = (const float*)d_in[2];
    const float* Wk   = (const float*)d_in[3];
    const float* Wv   = (const float*)d_in[4];
    float* out = (float*)d_out;

    __half *xh, *wh, *qh, *kh, *vh;
    cudaGetSymbolAddress((void**)&xh, g_Xh);
    cudaGetSymbolAddress((void**)&wh, g_Wh);
    cudaGetSymbolAddress((void**)&qh, g_Qh);
    cudaGetSymbolAddress((void**)&kh, g_Kh);
    cudaGetSymbolAddress((void**)&vh, g_Vh);

    cudaFuncSetAttribute(gemm_qkv_f16, cudaFuncAttributeMaxDynamicSharedMemorySize,
                         GEMM_SMEM);
    cudaFuncSetAttribute(attn_tc, cudaFuncAttributeMaxDynamicSharedMemorySize,
                         ATTN_SMEM);

    const int xn4 = BATCH * TSEQ * DMOD / 4;
    const int wn4 = DMOD * DMOD / 4;
    cvt_f16<<<xn4 / 256, 256>>>((const float4*)x, (uint2*)xh);
    dim3 wgrid(wn4 / 256, 3);
    cvt_w3<<<wgrid, 256>>>((const float4*)Wq, (const float4*)Wk,
                           (const float4*)Wv, (uint2*)wh);

    dim3 ggrid(3 * DMOD / 128, (BATCH * TSEQ) / 128);
    gemm_qkv_f16<<<ggrid, 256, GEMM_SMEM>>>(xh, wh, qh, kh, vh);

    dim3 agrid(TSEQ / 64, NH, BATCH);
    attn_tc<<<agrid, 256, ATTN_SMEM>>>(mask, out);
}